// round 10
// baseline (speedup 1.0000x reference)
#include <cuda_runtime.h>
#include <cuda_fp16.h>
#include <math.h>

#define NN 50000
#define EE 800000
#define NG4 (4 * NN)
#define EG4 (4 * EE)

// ---------------- scratch (static device globals; no runtime alloc) ----------------
__device__ int    g_CNT[NG4];
__device__ int    g_ROWPTR[NG4 + 1];
__device__ int    g_CUR[NG4];
__device__ int    g_ESRC[EG4];
__device__ int    g_EDST[EG4];
__device__ float  g_EVAL[EG4];
__device__ int    g_EPD[EE];                      // perm[dst] for adj edges (sorted order)
__device__ __half g_Xh[(size_t)NN * 64];          // feat@W_enc + b_enc (fp16 gather table)
__device__ __half g_Hh0[(size_t)NN * 64];         // relu(h)   fp16
__device__ __half g_Hh1[(size_t)NN * 64];         // relu(h_g) fp16
__device__ float  g_S[(size_t)NN * 64];           // spmm(adj, relu_h)
__device__ float  g_MLPIN[(size_t)5 * NN * 64];   // h, h_g, shuf_h, sig_neigh, sig_diff
__device__ float  g_MLPOUT[(size_t)5 * NN * 64];  // z, z_g, shuf_z, g, g_g
__device__ float  g_DEG[3 * NN];                  // [adj | neigh | diff]
__device__ __half g_W1T[512 * 64];                // W1 transposed [n][k] fp16
__device__ __half g_W3T[64 * 512];                // W3 transposed [n][k] fp16

// ---------------- mma helpers ----------------
__device__ __forceinline__ unsigned cvt_tf32(float x) {
    unsigned u;
    asm("cvt.rna.tf32.f32 %0, %1;" : "=r"(u) : "f"(x));
    return u;
}
__device__ __forceinline__ void mma8(float* c, const unsigned* a, const unsigned* b) {
    asm("mma.sync.aligned.m16n8k8.row.col.f32.tf32.tf32.f32 "
        "{%0,%1,%2,%3},{%4,%5,%6,%7},{%8,%9},{%0,%1,%2,%3};"
        : "+f"(c[0]), "+f"(c[1]), "+f"(c[2]), "+f"(c[3])
        : "r"(a[0]), "r"(a[1]), "r"(a[2]), "r"(a[3]), "r"(b[0]), "r"(b[1]));
}
__device__ __forceinline__ void mma16(float* c, const unsigned* a, const unsigned* b) {
    asm("mma.sync.aligned.m16n8k16.row.col.f32.f16.f16.f32 "
        "{%0,%1,%2,%3},{%4,%5,%6,%7},{%8,%9},{%0,%1,%2,%3};"
        : "+f"(c[0]), "+f"(c[1]), "+f"(c[2]), "+f"(c[3])
        : "r"(a[0]), "r"(a[1]), "r"(a[2]), "r"(a[3]), "r"(b[0]), "r"(b[1]));
}

#define CP16(sdst, gsrc) \
    asm volatile("cp.async.ca.shared.global [%0], [%1], 16;" ::"r"(sdst), "l"(gsrc))
#define CP_COMMIT() asm volatile("cp.async.commit_group;")
#define CP_WAIT0() asm volatile("cp.async.wait_group 0;" ::: "memory")

// =============================== CSR construction ====================================
__global__ void hist4(const int* __restrict__ sA, const int* __restrict__ sG,
                      const int* __restrict__ sN, const int* __restrict__ sD,
                      int* __restrict__ cnt) {
    int e = blockIdx.x * blockDim.x + threadIdx.x;
    if (e < EE) {
        atomicAdd(&cnt[sA[e]], 1);
        atomicAdd(&cnt[NN + sG[e]], 1);
        atomicAdd(&cnt[2 * NN + sN[e]], 1);
        atomicAdd(&cnt[3 * NN + sD[e]], 1);
    }
}

__global__ void scan_kernel(const int* __restrict__ cnt, int* __restrict__ rowptr,
                            int* __restrict__ cur) {
    __shared__ int part[1024];
    const int T = NG4, C = (T + 1023) / 1024;
    int t = threadIdx.x;
    int lo = t * C, hi = min(T, lo + C);
    int s = 0;
    for (int j = lo; j < hi; j++) s += cnt[j];
    part[t] = s;
    __syncthreads();
    for (int off = 1; off < 1024; off <<= 1) {
        int v = (t >= off) ? part[t - off] : 0;
        __syncthreads();
        part[t] += v;
        __syncthreads();
    }
    int run = part[t] - s;
    for (int j = lo; j < hi; j++) {
        rowptr[j] = run;
        cur[j] = run;
        run += cnt[j];
    }
    if (t == 0) rowptr[T] = EG4;
}

__global__ void scatter4(const int* __restrict__ sA, const int* __restrict__ dA,
                         const float* __restrict__ vA, const int* __restrict__ sG,
                         const int* __restrict__ dG, const float* __restrict__ vG,
                         const int* __restrict__ sN, const int* __restrict__ dN,
                         const float* __restrict__ vN, const int* __restrict__ sD,
                         const int* __restrict__ dD, const float* __restrict__ vD,
                         const int* __restrict__ perm, int* __restrict__ cur,
                         int* __restrict__ esrc, int* __restrict__ edst,
                         float* __restrict__ eval, int* __restrict__ epd) {
    int e = blockIdx.x * blockDim.x + threadIdx.x;
    if (e >= EE) return;
    {
        int ss = sA[e], d = dA[e];
        int p = atomicAdd(&cur[ss], 1);  // p < EE (adj occupies [0,EE))
        esrc[p] = ss;
        edst[p] = d;
        eval[p] = vA[e];
        epd[p] = perm[d];
    }
    {
        int ss = sG[e];
        int p = atomicAdd(&cur[NN + ss], 1);
        esrc[p] = ss;
        edst[p] = dG[e];
        eval[p] = vG[e];
    }
    {
        int ss = sN[e];
        int p = atomicAdd(&cur[2 * NN + ss], 1);
        esrc[p] = ss;
        edst[p] = dN[e];
        eval[p] = vN[e];
    }
    {
        int ss = sD[e];
        int p = atomicAdd(&cur[3 * NN + ss], 1);
        esrc[p] = ss;
        edst[p] = dD[e];
        eval[p] = vD[e];
    }
}

// ================= merged-atomic SpMM over sorted edges ==============================
// Each thread: 4 consecutive edges (same-src runs merged in registers), 16 cols.
__device__ __forceinline__ void red4(float* p, float a, float b, float c, float d) {
    asm volatile("red.global.add.v4.f32 [%0], {%1,%2,%3,%4};" ::"l"(p), "f"(a), "f"(b), "f"(c),
                 "f"(d)
                 : "memory");
}
__device__ __forceinline__ void acc16(const uint4& a, const uint4& b, float v, float* f) {
    const __half2* ha = reinterpret_cast<const __half2*>(&a);
    const __half2* hb = reinterpret_cast<const __half2*>(&b);
#pragma unroll
    for (int i = 0; i < 4; i++) {
        float2 x = __half22float2(ha[i]);
        f[2 * i] += v * x.x;
        f[2 * i + 1] += v * x.y;
        float2 y = __half22float2(hb[i]);
        f[8 + 2 * i] += v * y.x;
        f[8 + 2 * i + 1] += v * y.y;
    }
}

__global__ __launch_bounds__(256) void spmm_merge(const int* __restrict__ esrc,
                                                  const int* __restrict__ edst,
                                                  const float* __restrict__ eval,
                                                  const __half* __restrict__ X,
                                                  float* __restrict__ out,
                                                  float* __restrict__ deg, int E) {
    unsigned gid = blockIdx.x * blockDim.x + threadIdx.x;
    unsigned q = gid >> 2;
    if (q * 4 >= (unsigned)E) return;
    unsigned c = gid & 3;
    int base = q * 4;

    int4 s4 = *reinterpret_cast<const int4*>(esrc + base);
    int4 d4 = *reinterpret_cast<const int4*>(edst + base);
    float4 v4 = *reinterpret_cast<const float4*>(eval + base);
    int ss[4] = {s4.x, s4.y, s4.z, s4.w};
    int dd[4] = {d4.x, d4.y, d4.z, d4.w};
    float vv[4] = {v4.x, v4.y, v4.z, v4.w};

    // prefetch all gathers (branch-free -> all 8 loads in flight)
    uint4 ra[4], rb[4];
#pragma unroll
    for (int j = 0; j < 4; j++) {
        unsigned off = (unsigned)dd[j] * 64 + c * 16;
        ra[j] = *reinterpret_cast<const uint4*>(X + off);
        rb[j] = *reinterpret_cast<const uint4*>(X + off + 8);
    }

    float f[16];
#pragma unroll
    for (int i = 0; i < 16; i++) f[i] = 0.f;
    int cur = ss[0];
    float ds = 0.f;
#pragma unroll
    for (int j = 0; j < 4; j++) {
        if (ss[j] != cur) {
            float* p = out + (size_t)cur * 64 + c * 16;
#pragma unroll
            for (int i = 0; i < 4; i++)
                red4(p + 4 * i, f[4 * i], f[4 * i + 1], f[4 * i + 2], f[4 * i + 3]);
            if (deg != nullptr && c == 0) atomicAdd(&deg[cur], ds);
#pragma unroll
            for (int i = 0; i < 16; i++) f[i] = 0.f;
            ds = 0.f;
            cur = ss[j];
        }
        acc16(ra[j], rb[j], vv[j], f);
        ds += vv[j];
    }
    float* p = out + (size_t)cur * 64 + c * 16;
#pragma unroll
    for (int i = 0; i < 4; i++)
        red4(p + 4 * i, f[4 * i], f[4 * i + 1], f[4 * i + 2], f[4 * i + 3]);
    if (deg != nullptr && c == 0) atomicAdd(&deg[cur], ds);
}

// ---------------- weight pre-transpose (fp32 -> fp16, [k][n] -> [n][k]) --------------
__global__ void transpose_w(const float* __restrict__ W1, const float* __restrict__ W3,
                            __half* __restrict__ W1T, __half* __restrict__ W3T) {
    int t = threadIdx.x;
    if (blockIdx.x == 0) {
        int n = t;
#pragma unroll 4
        for (int k = 0; k < 64; k++) W1T[n * 64 + k] = __float2half_rn(W1[k * 512 + n]);
    } else {
        int n = t & 63;
        int kb = (t >> 6) * 64;
#pragma unroll 4
        for (int k = kb; k < kb + 64; k++) W3T[n * 512 + k] = __float2half_rn(W3[k * 64 + n]);
    }
}

// ---------------- single-TF32 GEMM ----------------
// EPI 1: C = relu(acc + deg[m]*bias[n]) fp32; EPI 2: Ch = half(acc + bias[n]) fp16
template <int EPI>
__global__ __launch_bounds__(256) void mma_gemm(const float* __restrict__ A,
                                                const float* __restrict__ W,
                                                const float* __restrict__ bias,
                                                const float* __restrict__ deg,
                                                float* __restrict__ C, __half* __restrict__ Ch,
                                                int M, int K, int Nc) {
    __shared__ unsigned As[128][36];
    __shared__ unsigned Bs[32][72];

    const int tid = threadIdx.x, lane = tid & 31, wid = tid >> 5;
    const int bm = blockIdx.y * 128, bn0 = blockIdx.x * 64;
    const int m_base = (wid & 3) * 32, n_base = (wid >> 2) * 32;
    const int lr = lane >> 2, lk = lane & 3;

    float acc[2][4][4];
#pragma unroll
    for (int mi = 0; mi < 2; mi++)
#pragma unroll
        for (int ni = 0; ni < 4; ni++)
#pragma unroll
            for (int i = 0; i < 4; i++) acc[mi][ni][i] = 0.f;

    for (int k0 = 0; k0 < K; k0 += 32) {
#pragma unroll
        for (int p = 0; p < 4; p++) {
            int idx = tid + p * 256;
            int row = idx >> 3, q = idx & 7;
            float4 v = make_float4(0.f, 0.f, 0.f, 0.f);
            if (bm + row < M)
                v = *reinterpret_cast<const float4*>(A + (size_t)(bm + row) * K + k0 + q * 4);
            As[row][q * 4 + 0] = cvt_tf32(v.x);
            As[row][q * 4 + 1] = cvt_tf32(v.y);
            As[row][q * 4 + 2] = cvt_tf32(v.z);
            As[row][q * 4 + 3] = cvt_tf32(v.w);
        }
#pragma unroll
        for (int p = 0; p < 2; p++) {
            int idx = tid + p * 256;
            int kr = idx >> 4, q = idx & 15;
            float4 v = *reinterpret_cast<const float4*>(W + (size_t)(k0 + kr) * Nc + bn0 + q * 4);
            Bs[kr][q * 4 + 0] = cvt_tf32(v.x);
            Bs[kr][q * 4 + 1] = cvt_tf32(v.y);
            Bs[kr][q * 4 + 2] = cvt_tf32(v.z);
            Bs[kr][q * 4 + 3] = cvt_tf32(v.w);
        }
        __syncthreads();

#pragma unroll
        for (int kk = 0; kk < 4; kk++) {
            unsigned a[2][4], b[4][2];
#pragma unroll
            for (int mi = 0; mi < 2; mi++) {
                int r0 = m_base + mi * 16 + lr;
                a[mi][0] = As[r0][kk * 8 + lk];
                a[mi][1] = As[r0 + 8][kk * 8 + lk];
                a[mi][2] = As[r0][kk * 8 + lk + 4];
                a[mi][3] = As[r0 + 8][kk * 8 + lk + 4];
            }
#pragma unroll
            for (int ni = 0; ni < 4; ni++) {
                int cn = n_base + ni * 8 + lr;
                b[ni][0] = Bs[kk * 8 + lk][cn];
                b[ni][1] = Bs[kk * 8 + lk + 4][cn];
            }
#pragma unroll
            for (int mi = 0; mi < 2; mi++)
#pragma unroll
                for (int ni = 0; ni < 4; ni++) mma8(acc[mi][ni], a[mi], b[ni]);
        }
        __syncthreads();
    }

#pragma unroll
    for (int mi = 0; mi < 2; mi++)
#pragma unroll
        for (int ni = 0; ni < 4; ni++) {
#pragma unroll
            for (int hi = 0; hi < 2; hi++) {
                int row = m_base + mi * 16 + lr + hi * 8;
                int col = n_base + ni * 8 + 2 * lk;
                int gm = bm + row, gn = bn0 + col;
                if (gm < M) {
                    float v0 = acc[mi][ni][hi * 2 + 0];
                    float v1 = acc[mi][ni][hi * 2 + 1];
                    if (EPI == 1) {
                        float dg = deg[gm];
                        v0 = fmaxf(v0 + dg * bias[gn], 0.f);
                        v1 = fmaxf(v1 + dg * bias[gn + 1], 0.f);
                        C[(size_t)gm * Nc + gn] = v0;
                        C[(size_t)gm * Nc + gn + 1] = v1;
                    } else {
                        v0 += bias[gn];
                        v1 += bias[gn + 1];
                        *reinterpret_cast<__half2*>(Ch + (size_t)gm * Nc + gn) =
                            __floats2half2_rn(v0, v1);
                    }
                }
            }
        }
}

// ---------------- fused MLP (fp16 mma, pre-transposed weights, cp.async) -------------
__global__ __launch_bounds__(512, 1) void mlp16(const float* __restrict__ A,
                                                const __half* __restrict__ W1T,
                                                const float* __restrict__ b1,
                                                const float* __restrict__ aptr,
                                                const __half* __restrict__ W3T,
                                                const float* __restrict__ b3,
                                                float* __restrict__ C, int M) {
    extern __shared__ __half hsm[];
    __half(*As)[72] = (__half(*)[72])hsm;
    __half(*Hs)[72] = (__half(*)[72])(hsm + 256 * 72);
    const unsigned W1_OFF = 2 * 256 * 72;
    const unsigned W3_OFF = W1_OFF + 2 * 64 * 72;
    __half(*W1s)[64][72] = (__half(*)[64][72])(hsm + W1_OFF);
    __half(*W3s)[64][72] = (__half(*)[64][72])(hsm + W3_OFF);

    const int tid = threadIdx.x, lane = tid & 31, wid = tid >> 5;
    const int bm = blockIdx.x * 256;
    const int m_base = (wid & 7) * 32, n_base = (wid >> 3) * 32;
    const int g = lane >> 2, t = lane & 3;
    const float alpha = aptr[0];
    const unsigned sb = (unsigned)__cvta_generic_to_shared(hsm);

    auto issue = [&](int ch, int buf) {
        int n = tid >> 3, o = tid & 7;
        const __half* s1 = W1T + ((size_t)(ch * 64 + n)) * 64 + o * 8;
        unsigned d1 = sb + (W1_OFF + (unsigned)buf * 64 * 72 + n * 72 + o * 8) * 2u;
        CP16(d1, s1);
        const __half* s3 = W3T + (size_t)n * 512 + ch * 64 + o * 8;
        unsigned d3 = sb + (W3_OFF + (unsigned)buf * 64 * 72 + n * 72 + o * 8) * 2u;
        CP16(d3, s3);
        CP_COMMIT();
    };
    issue(0, 0);

#pragma unroll
    for (int p = 0; p < 8; p++) {
        int idx = tid + p * 512;
        int row = idx >> 4, q = idx & 15;
        float4 v = make_float4(0.f, 0.f, 0.f, 0.f);
        if (bm + row < M)
            v = *reinterpret_cast<const float4*>(A + (size_t)(bm + row) * 64 + q * 4);
        *reinterpret_cast<__half2*>(&As[row][q * 4]) = __floats2half2_rn(v.x, v.y);
        *reinterpret_cast<__half2*>(&As[row][q * 4 + 2]) = __floats2half2_rn(v.z, v.w);
    }

    float out_acc[2][4][4];
#pragma unroll
    for (int mi = 0; mi < 2; mi++)
#pragma unroll
        for (int ni = 0; ni < 4; ni++)
#pragma unroll
            for (int i = 0; i < 4; i++) out_acc[mi][ni][i] = 0.f;

    for (int ch = 0; ch < 8; ch++) {
        const int buf = ch & 1;
        CP_WAIT0();
        __syncthreads();
        if (ch < 7) issue(ch + 1, buf ^ 1);

        float h_acc[2][4][4];
#pragma unroll
        for (int mi = 0; mi < 2; mi++)
#pragma unroll
            for (int ni = 0; ni < 4; ni++)
#pragma unroll
                for (int i = 0; i < 4; i++) h_acc[mi][ni][i] = 0.f;

#pragma unroll
        for (int kk = 0; kk < 4; kk++) {
            unsigned a[2][4], b[4][2];
#pragma unroll
            for (int mi = 0; mi < 2; mi++) {
                int r0 = m_base + mi * 16 + g;
                a[mi][0] = *reinterpret_cast<const unsigned*>(&As[r0][kk * 16 + 2 * t]);
                a[mi][1] = *reinterpret_cast<const unsigned*>(&As[r0 + 8][kk * 16 + 2 * t]);
                a[mi][2] = *reinterpret_cast<const unsigned*>(&As[r0][kk * 16 + 2 * t + 8]);
                a[mi][3] = *reinterpret_cast<const unsigned*>(&As[r0 + 8][kk * 16 + 2 * t + 8]);
            }
#pragma unroll
            for (int ni = 0; ni < 4; ni++) {
                int cn = n_base + ni * 8 + g;
                b[ni][0] = *reinterpret_cast<const unsigned*>(&W1s[buf][cn][kk * 16 + 2 * t]);
                b[ni][1] = *reinterpret_cast<const unsigned*>(&W1s[buf][cn][kk * 16 + 2 * t + 8]);
            }
#pragma unroll
            for (int mi = 0; mi < 2; mi++)
#pragma unroll
                for (int ni = 0; ni < 4; ni++) mma16(h_acc[mi][ni], a[mi], b[ni]);
        }

#pragma unroll
        for (int mi = 0; mi < 2; mi++)
#pragma unroll
            for (int ni = 0; ni < 4; ni++) {
                int r0 = m_base + mi * 16 + g;
                int hc = n_base + ni * 8 + 2 * t;
                float bb0 = b1[ch * 64 + hc], bb1 = b1[ch * 64 + hc + 1];
                float v0 = h_acc[mi][ni][0] + bb0;
                float v1 = h_acc[mi][ni][1] + bb1;
                float v2 = h_acc[mi][ni][2] + bb0;
                float v3 = h_acc[mi][ni][3] + bb1;
                v0 = (v0 >= 0.f) ? v0 : alpha * v0;
                v1 = (v1 >= 0.f) ? v1 : alpha * v1;
                v2 = (v2 >= 0.f) ? v2 : alpha * v2;
                v3 = (v3 >= 0.f) ? v3 : alpha * v3;
                *reinterpret_cast<__half2*>(&Hs[r0][hc]) = __floats2half2_rn(v0, v1);
                *reinterpret_cast<__half2*>(&Hs[r0 + 8][hc]) = __floats2half2_rn(v2, v3);
            }
        __syncthreads();

#pragma unroll
        for (int kk = 0; kk < 4; kk++) {
            unsigned a[2][4], b[4][2];
#pragma unroll
            for (int mi = 0; mi < 2; mi++) {
                int r0 = m_base + mi * 16 + g;
                a[mi][0] = *reinterpret_cast<const unsigned*>(&Hs[r0][kk * 16 + 2 * t]);
                a[mi][1] = *reinterpret_cast<const unsigned*>(&Hs[r0 + 8][kk * 16 + 2 * t]);
                a[mi][2] = *reinterpret_cast<const unsigned*>(&Hs[r0][kk * 16 + 2 * t + 8]);
                a[mi][3] = *reinterpret_cast<const unsigned*>(&Hs[r0 + 8][kk * 16 + 2 * t + 8]);
            }
#pragma unroll
            for (int ni = 0; ni < 4; ni++) {
                int cn = n_base + ni * 8 + g;
                b[ni][0] = *reinterpret_cast<const unsigned*>(&W3s[buf][cn][kk * 16 + 2 * t]);
                b[ni][1] = *reinterpret_cast<const unsigned*>(&W3s[buf][cn][kk * 16 + 2 * t + 8]);
            }
#pragma unroll
            for (int mi = 0; mi < 2; mi++)
#pragma unroll
                for (int ni = 0; ni < 4; ni++) mma16(out_acc[mi][ni], a[mi], b[ni]);
        }
    }

#pragma unroll
    for (int mi = 0; mi < 2; mi++)
#pragma unroll
        for (int ni = 0; ni < 4; ni++)
#pragma unroll
            for (int i = 0; i < 4; i++) {
                int row = m_base + mi * 16 + g + ((i >= 2) ? 8 : 0);
                int col = n_base + ni * 8 + 2 * t + (i & 1);
                int gm = bm + row;
                if (gm < M) C[(size_t)gm * 64 + col] = out_acc[mi][ni][i] + b3[col];
            }
}

// ---------------- relu slots 0..2 in place; emit fp16 copies of slots 0,1 ------------
__global__ void relu_emit_half(float4* __restrict__ p, __half* __restrict__ h0,
                               __half* __restrict__ h1, int n4) {
    int i = blockIdx.x * blockDim.x + threadIdx.x;
    if (i < n4) {
        float4 v = p[i];
        v.x = fmaxf(v.x, 0.f);
        v.y = fmaxf(v.y, 0.f);
        v.z = fmaxf(v.z, 0.f);
        v.w = fmaxf(v.w, 0.f);
        p[i] = v;
        const int per_slot = NN * 16;
        if (i < 2 * per_slot) {
            __half* dst = (i < per_slot) ? h0 : h1;
            int off = (i < per_slot) ? i : i - per_slot;
            __half2 a = __floats2half2_rn(v.x, v.y);
            __half2 b = __floats2half2_rn(v.z, v.w);
            uint2 u;
            u.x = *reinterpret_cast<unsigned*>(&a);
            u.y = *reinterpret_cast<unsigned*>(&b);
            *reinterpret_cast<uint2*>(dst + (size_t)off * 4) = u;
        }
    }
}

// ---------------- sigmoid(buf / max(deg,1)) over slots 3,4 ----------------
__global__ void sigavg2_kernel(float* __restrict__ b3, float* __restrict__ b4,
                               const float* __restrict__ degN, const float* __restrict__ degD) {
    int i = blockIdx.x * blockDim.x + threadIdx.x;
    const int n = NN * 64;
    if (i < 2 * n) {
        float* buf = (i < n) ? b3 : b4;
        const float* deg = (i < n) ? degN : degD;
        int j = (i < n) ? i : i - n;
        float d = deg[j >> 6];
        d = (d > 1.f) ? d : 1.f;
        float x = buf[j] / d;
        buf[j] = 1.f / (1.f + expf(-x));
    }
}

// ---------------- discriminator ----------------
__global__ void disc_kernel(const float* __restrict__ Mo, const float* __restrict__ W,
                            const float* __restrict__ bptr, float* __restrict__ ret,
                            float* __restrict__ ret_a) {
    __shared__ float Ws[64][65];
    int tid = threadIdx.x;
    for (int i = tid; i < 4096; i += 128) Ws[i >> 6][i & 63] = W[i];
    __syncthreads();

    int warp = tid >> 5, lane = tid & 31;
    int node = blockIdx.x * 4 + warp;
    if (node >= NN) return;

    const float* z = Mo + (size_t)0 * NN * 64 + (size_t)node * 64;
    const float* zg = Mo + (size_t)1 * NN * 64 + (size_t)node * 64;
    const float* sz = Mo + (size_t)2 * NN * 64 + (size_t)node * 64;
    const float* gv = Mo + (size_t)3 * NN * 64 + (size_t)node * 64;
    const float* gg = Mo + (size_t)4 * NN * 64 + (size_t)node * 64;

    float r0 = 0.f, r1 = 0.f, a0 = 0.f, a1 = 0.f;
#pragma unroll
    for (int h = 0; h < 2; h++) {
        int d = lane + h * 32;
        float tgg = 0.f, tg = 0.f;
#pragma unroll
        for (int e = 0; e < 64; e++) {
            float w = Ws[d][e];
            tgg += w * gg[e];
            tg += w * gv[e];
        }
        r0 += z[d] * tgg;
        r1 += sz[d] * tgg;
        a0 += zg[d] * tg;
        a1 += sz[d] * tg;
    }
#pragma unroll
    for (int o = 16; o; o >>= 1) {
        r0 += __shfl_xor_sync(0xFFFFFFFFu, r0, o);
        r1 += __shfl_xor_sync(0xFFFFFFFFu, r1, o);
        a0 += __shfl_xor_sync(0xFFFFFFFFu, a0, o);
        a1 += __shfl_xor_sync(0xFFFFFFFFu, a1, o);
    }
    if (lane == 0) {
        float b = bptr[0];
        ret[(size_t)node * 2 + 0] = r0 + b;
        ret[(size_t)node * 2 + 1] = r1 + b;
        ret_a[(size_t)node * 2 + 0] = a0 + b;
        ret_a[(size_t)node * 2 + 1] = a1 + b;
    }
}

// =====================================================================================
extern "C" void kernel_launch(void* const* d_in, const int* in_sizes, int n_in, void* d_out,
                              int out_size) {
    (void)in_sizes; (void)n_in; (void)out_size;

    const float* feat      = (const float*)d_in[0];
    const int*   adj_src   = (const int*)d_in[1];
    const int*   adj_dst   = (const int*)d_in[2];
    const float* adj_val   = (const float*)d_in[3];
    const int*   gdc_src   = (const int*)d_in[4];
    const int*   gdc_dst   = (const int*)d_in[5];
    const float* gdc_val   = (const float*)d_in[6];
    const int*   neigh_src = (const int*)d_in[7];
    const int*   neigh_dst = (const int*)d_in[8];
    const float* neigh_val = (const float*)d_in[9];
    const int*   diff_src  = (const int*)d_in[10];
    const int*   diff_dst  = (const int*)d_in[11];
    const float* diff_val  = (const float*)d_in[12];
    const int*   perm      = (const int*)d_in[13];
    const float* W_enc     = (const float*)d_in[14];
    const float* b_enc     = (const float*)d_in[15];
    const float* W_dec     = (const float*)d_in[16];
    const float* b_dec     = (const float*)d_in[17];
    const float* W1        = (const float*)d_in[18];
    const float* b1        = (const float*)d_in[19];
    const float* prelu_a   = (const float*)d_in[20];
    const float* W3        = (const float*)d_in[21];
    const float* b3        = (const float*)d_in[22];
    const float* W_disc    = (const float*)d_in[23];
    const float* b_disc    = (const float*)d_in[24];

    int *CNTp, *ROWPTRp, *CURp, *ESRCp, *EDSTp, *EPDp;
    float *EVALp, *Sp, *MLPINp, *MLPOUTp, *DEGp;
    __half *Xhp, *Hh0p, *Hh1p, *W1Tp, *W3Tp;
    cudaGetSymbolAddress((void**)&CNTp, g_CNT);
    cudaGetSymbolAddress((void**)&ROWPTRp, g_ROWPTR);
    cudaGetSymbolAddress((void**)&CURp, g_CUR);
    cudaGetSymbolAddress((void**)&ESRCp, g_ESRC);
    cudaGetSymbolAddress((void**)&EDSTp, g_EDST);
    cudaGetSymbolAddress((void**)&EVALp, g_EVAL);
    cudaGetSymbolAddress((void**)&EPDp, g_EPD);
    cudaGetSymbolAddress((void**)&Xhp, g_Xh);
    cudaGetSymbolAddress((void**)&Hh0p, g_Hh0);
    cudaGetSymbolAddress((void**)&Hh1p, g_Hh1);
    cudaGetSymbolAddress((void**)&W1Tp, g_W1T);
    cudaGetSymbolAddress((void**)&W3Tp, g_W3T);
    cudaGetSymbolAddress((void**)&Sp, g_S);
    cudaGetSymbolAddress((void**)&MLPINp, g_MLPIN);
    cudaGetSymbolAddress((void**)&MLPOUTp, g_MLPOUT);
    cudaGetSymbolAddress((void**)&DEGp, g_DEG);

    float* out = (float*)d_out;
    float* emb = out;                       // [NN,256]
    float* ret = out + (size_t)NN * 256;    // [NN,2]
    float* ret_a = ret + (size_t)NN * 2;    // [NN,2]

    const int MLP_SMEM = (2 * 256 * 72 + 4 * 64 * 72) * 2;  // 110592 B
    static bool attr_set = false;
    if (!attr_set) {
        cudaFuncSetAttribute(mlp16, cudaFuncAttributeMaxDynamicSharedMemorySize, MLP_SMEM);
        attr_set = true;
    }

    const int MROWS = (NN + 127) / 128;               // 391
    const int EB = (EE + 255) / 256;                  // 3125
    const unsigned mg_blocks = ((unsigned)EE + 255u) / 256u;  // E threads (4 edges/thread x 4 thr)

    // zero accumulators
    cudaMemsetAsync(CNTp, 0, (size_t)NG4 * sizeof(int));
    cudaMemsetAsync(MLPINp, 0, (size_t)5 * NN * 64 * sizeof(float));
    cudaMemsetAsync(Sp, 0, (size_t)NN * 64 * sizeof(float));
    cudaMemsetAsync(DEGp, 0, (size_t)3 * NN * sizeof(float));

    // weight pre-transpose
    transpose_w<<<2, 512>>>(W1, W3, W1Tp, W3Tp);

    // ---- CSR build (edges sorted by src per graph) ----
    hist4<<<EB, 256>>>(adj_src, gdc_src, neigh_src, diff_src, CNTp);
    scan_kernel<<<1, 1024>>>(CNTp, ROWPTRp, CURp);
    scatter4<<<EB, 256>>>(adj_src, adj_dst, adj_val, gdc_src, gdc_dst, gdc_val, neigh_src,
                          neigh_dst, neigh_val, diff_src, diff_dst, diff_val, perm, CURp, ESRCp,
                          EDSTp, EVALp, EPDp);

    // ---- encoder: Xh = half(feat @ W_enc + b_enc), tf32 ----
    mma_gemm<2><<<dim3(1, MROWS), 256>>>(feat, W_enc, b_enc, nullptr, nullptr, Xhp, NN, 256, 64);

    // ---- stage 1: h (slot0, +degA), shuf_h (slot2, via epd), h_g (slot1) ----
    spmm_merge<<<mg_blocks, 256>>>(ESRCp, EDSTp, EVALp, Xhp, MLPINp + (size_t)0 * NN * 64, DEGp,
                                   EE);
    spmm_merge<<<mg_blocks, 256>>>(ESRCp, EPDp, EVALp, Xhp, MLPINp + (size_t)2 * NN * 64, nullptr,
                                   EE);
    spmm_merge<<<mg_blocks, 256>>>(ESRCp + EE, EDSTp + EE, EVALp + EE, Xhp,
                                   MLPINp + (size_t)1 * NN * 64, nullptr, EE);

    // ---- relu slots 0..2; fp16 copies of relu(h), relu(h_g) ----
    {
        int n4 = 3 * NN * 16;
        relu_emit_half<<<(n4 + 255) / 256, 256>>>((float4*)MLPINp, Hh0p, Hh1p, n4);
    }

    // ---- stage 2: adj over relu(h) -> S; neigh -> slot3 (+degN); diff -> slot4 (+degD)
    spmm_merge<<<mg_blocks, 256>>>(ESRCp, EDSTp, EVALp, Hh0p, Sp, nullptr, EE);
    spmm_merge<<<mg_blocks, 256>>>(ESRCp + 2 * EE, EDSTp + 2 * EE, EVALp + 2 * EE, Hh0p,
                                   MLPINp + (size_t)3 * NN * 64, DEGp + NN, EE);
    spmm_merge<<<mg_blocks, 256>>>(ESRCp + 3 * EE, EDSTp + 3 * EE, EVALp + 3 * EE, Hh1p,
                                   MLPINp + (size_t)4 * NN * 64, DEGp + 2 * NN, EE);

    // ---- emb = relu(S @ W_dec + deg_adj ⊗ b_dec)  (spmm linearity), tf32 ----
    mma_gemm<1><<<dim3(4, MROWS), 256>>>(Sp, W_dec, b_dec, DEGp, emb, nullptr, NN, 64, 256);

    // ---- sigmoid averages for slots 3,4 ----
    {
        int n2 = 2 * NN * 64;
        sigavg2_kernel<<<(n2 + 255) / 256, 256>>>(MLPINp + (size_t)3 * NN * 64,
                                                  MLPINp + (size_t)4 * NN * 64, DEGp + NN,
                                                  DEGp + 2 * NN);
    }

    // ---- fused batched MLP over all 5 inputs (fp16 tensor cores) ----
    {
        int M = 5 * NN;
        mlp16<<<(M + 255) / 256, 512, MLP_SMEM>>>(MLPINp, W1Tp, b1, prelu_a, W3Tp, b3, MLPOUTp, M);
    }

    // ---- discriminator heads ----
    disc_kernel<<<(NN + 3) / 4, 128>>>(MLPOUTp, W_disc, b_disc, ret, ret_a);
}

// round 11
// speedup vs baseline: 1.3547x; 1.3547x over previous
#include <cuda_runtime.h>
#include <cuda_fp16.h>
#include <math.h>

#define NN 50000
#define EE 800000

// ---------------- scratch (static device globals; no runtime alloc) ----------------
__device__ __half g_Xh[(size_t)NN * 64];           // feat@W_enc + b_enc (fp16, gather table)
__device__ float  g_STAGE[(size_t)5 * NN * 64];    // fp32 atomic staging: h,h_g,shuf_h,nsum,dsum
__device__ __half g_MLPINH[(size_t)5 * NN * 64];   // fp16 MLP inputs (slots 0/1 = gather tables)
__device__ float  g_S[(size_t)NN * 64];            // spmm(adj, relu_h)
__device__ float  g_MLPOUT[(size_t)5 * NN * 64];   // z, z_g, shuf_z, g, g_g
__device__ float  g_DEG[3 * NN];                   // [adj | neigh | diff]
__device__ __half g_W1T[512 * 64];                 // W1 transposed [n][k] fp16
__device__ __half g_W3T[64 * 512];                 // W3 transposed [n][k] fp16

// ---------------- mma helpers ----------------
__device__ __forceinline__ unsigned cvt_tf32(float x) {
    unsigned u;
    asm("cvt.rna.tf32.f32 %0, %1;" : "=r"(u) : "f"(x));
    return u;
}
__device__ __forceinline__ void mma8(float* c, const unsigned* a, const unsigned* b) {
    asm("mma.sync.aligned.m16n8k8.row.col.f32.tf32.tf32.f32 "
        "{%0,%1,%2,%3},{%4,%5,%6,%7},{%8,%9},{%0,%1,%2,%3};"
        : "+f"(c[0]), "+f"(c[1]), "+f"(c[2]), "+f"(c[3])
        : "r"(a[0]), "r"(a[1]), "r"(a[2]), "r"(a[3]), "r"(b[0]), "r"(b[1]));
}
__device__ __forceinline__ void mma16(float* c, const unsigned* a, const unsigned* b) {
    asm("mma.sync.aligned.m16n8k16.row.col.f32.f16.f16.f32 "
        "{%0,%1,%2,%3},{%4,%5,%6,%7},{%8,%9},{%0,%1,%2,%3};"
        : "+f"(c[0]), "+f"(c[1]), "+f"(c[2]), "+f"(c[3])
        : "r"(a[0]), "r"(a[1]), "r"(a[2]), "r"(a[3]), "r"(b[0]), "r"(b[1]));
}

#define CP16(sdst, gsrc) \
    asm volatile("cp.async.ca.shared.global [%0], [%1], 16;" ::"r"(sdst), "l"(gsrc))
#define CP_COMMIT() asm volatile("cp.async.commit_group;")
#define CP_WAIT0() asm volatile("cp.async.wait_group 0;" ::: "memory")

// ---------------- weight pre-transpose (fp32 -> fp16, [k][n] -> [n][k]) --------------
// blocks 0..7: W1T (64 n-rows each); blocks 8..15: W3T (8 n-rows each, 512 k)
__global__ void transpose_w(const float* __restrict__ W1, const float* __restrict__ W3,
                            __half* __restrict__ W1T, __half* __restrict__ W3T) {
    int b = blockIdx.x, t = threadIdx.x;
    if (b < 8) {
        // W1T[n][k], n in [b*64, b*64+64), k<64; 4096 elems, 512 threads x 8
        int n = b * 64 + (t >> 3);
        int k0 = (t & 7) * 8;
#pragma unroll
        for (int i = 0; i < 8; i++)
            W1T[n * 64 + k0 + i] = __float2half_rn(W1[(size_t)(k0 + i) * 512 + n]);
    } else {
        // W3T[n][k], n in [(b-8)*8, ...+8), k<512; 4096 elems
        int n = (b - 8) * 8 + (t >> 6);
        int k0 = (t & 63) * 8;
#pragma unroll
        for (int i = 0; i < 8; i++)
            W3T[n * 512 + k0 + i] = __float2half_rn(W3[(size_t)(k0 + i) * 64 + n]);
    }
}

// ---------------- single-TF32 GEMM ----------------
// EPI 1: C = relu(acc + deg[m]*bias[n]) fp32; EPI 2: Ch = half(acc + bias[n]) fp16
template <int EPI>
__global__ __launch_bounds__(256) void mma_gemm(const float* __restrict__ A,
                                                const float* __restrict__ W,
                                                const float* __restrict__ bias,
                                                const float* __restrict__ deg,
                                                float* __restrict__ C, __half* __restrict__ Ch,
                                                int M, int K, int Nc) {
    __shared__ unsigned As[128][36];
    __shared__ unsigned Bs[32][72];

    const int tid = threadIdx.x, lane = tid & 31, wid = tid >> 5;
    const int bm = blockIdx.y * 128, bn0 = blockIdx.x * 64;
    const int m_base = (wid & 3) * 32, n_base = (wid >> 2) * 32;
    const int lr = lane >> 2, lk = lane & 3;

    float acc[2][4][4];
#pragma unroll
    for (int mi = 0; mi < 2; mi++)
#pragma unroll
        for (int ni = 0; ni < 4; ni++)
#pragma unroll
            for (int i = 0; i < 4; i++) acc[mi][ni][i] = 0.f;

    for (int k0 = 0; k0 < K; k0 += 32) {
#pragma unroll
        for (int p = 0; p < 4; p++) {
            int idx = tid + p * 256;
            int row = idx >> 3, q = idx & 7;
            float4 v = make_float4(0.f, 0.f, 0.f, 0.f);
            if (bm + row < M)
                v = *reinterpret_cast<const float4*>(A + (size_t)(bm + row) * K + k0 + q * 4);
            As[row][q * 4 + 0] = cvt_tf32(v.x);
            As[row][q * 4 + 1] = cvt_tf32(v.y);
            As[row][q * 4 + 2] = cvt_tf32(v.z);
            As[row][q * 4 + 3] = cvt_tf32(v.w);
        }
#pragma unroll
        for (int p = 0; p < 2; p++) {
            int idx = tid + p * 256;
            int kr = idx >> 4, q = idx & 15;
            float4 v = *reinterpret_cast<const float4*>(W + (size_t)(k0 + kr) * Nc + bn0 + q * 4);
            Bs[kr][q * 4 + 0] = cvt_tf32(v.x);
            Bs[kr][q * 4 + 1] = cvt_tf32(v.y);
            Bs[kr][q * 4 + 2] = cvt_tf32(v.z);
            Bs[kr][q * 4 + 3] = cvt_tf32(v.w);
        }
        __syncthreads();

#pragma unroll
        for (int kk = 0; kk < 4; kk++) {
            unsigned a[2][4], b[4][2];
#pragma unroll
            for (int mi = 0; mi < 2; mi++) {
                int r0 = m_base + mi * 16 + lr;
                a[mi][0] = As[r0][kk * 8 + lk];
                a[mi][1] = As[r0 + 8][kk * 8 + lk];
                a[mi][2] = As[r0][kk * 8 + lk + 4];
                a[mi][3] = As[r0 + 8][kk * 8 + lk + 4];
            }
#pragma unroll
            for (int ni = 0; ni < 4; ni++) {
                int cn = n_base + ni * 8 + lr;
                b[ni][0] = Bs[kk * 8 + lk][cn];
                b[ni][1] = Bs[kk * 8 + lk + 4][cn];
            }
#pragma unroll
            for (int mi = 0; mi < 2; mi++)
#pragma unroll
                for (int ni = 0; ni < 4; ni++) mma8(acc[mi][ni], a[mi], b[ni]);
        }
        __syncthreads();
    }

#pragma unroll
    for (int mi = 0; mi < 2; mi++)
#pragma unroll
        for (int ni = 0; ni < 4; ni++) {
#pragma unroll
            for (int hi = 0; hi < 2; hi++) {
                int row = m_base + mi * 16 + lr + hi * 8;
                int col = n_base + ni * 8 + 2 * lk;
                int gm = bm + row, gn = bn0 + col;
                if (gm < M) {
                    float v0 = acc[mi][ni][hi * 2 + 0];
                    float v1 = acc[mi][ni][hi * 2 + 1];
                    if (EPI == 1) {
                        float dg = deg[gm];
                        v0 = fmaxf(v0 + dg * bias[gn], 0.f);
                        v1 = fmaxf(v1 + dg * bias[gn + 1], 0.f);
                        C[(size_t)gm * Nc + gn] = v0;
                        C[(size_t)gm * Nc + gn + 1] = v1;
                    } else {
                        v0 += bias[gn];
                        v1 += bias[gn + 1];
                        *reinterpret_cast<__half2*>(Ch + (size_t)gm * Nc + gn) =
                            __floats2half2_rn(v0, v1);
                    }
                }
            }
        }
}

// ---------------- fused MLP (fp16 mma, pre-transposed weights, fp16 A) ---------------
__global__ __launch_bounds__(512, 1) void mlp16(const __half* __restrict__ A,
                                                const __half* __restrict__ W1T,
                                                const float* __restrict__ b1,
                                                const float* __restrict__ aptr,
                                                const __half* __restrict__ W3T,
                                                const float* __restrict__ b3,
                                                float* __restrict__ C, int M) {
    extern __shared__ __half hsm[];
    __half(*As)[72] = (__half(*)[72])hsm;
    __half(*Hs)[72] = (__half(*)[72])(hsm + 256 * 72);
    const unsigned W1_OFF = 2 * 256 * 72;
    const unsigned W3_OFF = W1_OFF + 2 * 64 * 72;
    __half(*W1s)[64][72] = (__half(*)[64][72])(hsm + W1_OFF);
    __half(*W3s)[64][72] = (__half(*)[64][72])(hsm + W3_OFF);

    const int tid = threadIdx.x, lane = tid & 31, wid = tid >> 5;
    const int bm = blockIdx.x * 256;
    const int m_base = (wid & 7) * 32, n_base = (wid >> 3) * 32;
    const int g = lane >> 2, t = lane & 3;
    const float alpha = aptr[0];
    const unsigned sb = (unsigned)__cvta_generic_to_shared(hsm);

    auto issue = [&](int ch, int buf) {
        int n = tid >> 3, o = tid & 7;
        const __half* s1 = W1T + ((size_t)(ch * 64 + n)) * 64 + o * 8;
        unsigned d1 = sb + (W1_OFF + (unsigned)buf * 64 * 72 + n * 72 + o * 8) * 2u;
        CP16(d1, s1);
        const __half* s3 = W3T + (size_t)n * 512 + ch * 64 + o * 8;
        unsigned d3 = sb + (W3_OFF + (unsigned)buf * 64 * 72 + n * 72 + o * 8) * 2u;
        CP16(d3, s3);
        CP_COMMIT();
    };
    issue(0, 0);

    // A tile 256x64 fp16: straight uint4 copy (no conversion)
#pragma unroll
    for (int p = 0; p < 4; p++) {
        int idx = tid + p * 512;  // 2048 = 256 rows x 8 chunks of 8 halves
        int row = idx >> 3, q = idx & 7;
        uint4 u = make_uint4(0u, 0u, 0u, 0u);
        if (bm + row < M)
            u = *reinterpret_cast<const uint4*>(A + (size_t)(bm + row) * 64 + q * 8);
        *reinterpret_cast<uint4*>(&As[row][q * 8]) = u;
    }

    float out_acc[2][4][4];
#pragma unroll
    for (int mi = 0; mi < 2; mi++)
#pragma unroll
        for (int ni = 0; ni < 4; ni++)
#pragma unroll
            for (int i = 0; i < 4; i++) out_acc[mi][ni][i] = 0.f;

    for (int ch = 0; ch < 8; ch++) {
        const int buf = ch & 1;
        CP_WAIT0();
        __syncthreads();
        if (ch < 7) issue(ch + 1, buf ^ 1);

        float h_acc[2][4][4];
#pragma unroll
        for (int mi = 0; mi < 2; mi++)
#pragma unroll
            for (int ni = 0; ni < 4; ni++)
#pragma unroll
                for (int i = 0; i < 4; i++) h_acc[mi][ni][i] = 0.f;

#pragma unroll
        for (int kk = 0; kk < 4; kk++) {
            unsigned a[2][4], b[4][2];
#pragma unroll
            for (int mi = 0; mi < 2; mi++) {
                int r0 = m_base + mi * 16 + g;
                a[mi][0] = *reinterpret_cast<const unsigned*>(&As[r0][kk * 16 + 2 * t]);
                a[mi][1] = *reinterpret_cast<const unsigned*>(&As[r0 + 8][kk * 16 + 2 * t]);
                a[mi][2] = *reinterpret_cast<const unsigned*>(&As[r0][kk * 16 + 2 * t + 8]);
                a[mi][3] = *reinterpret_cast<const unsigned*>(&As[r0 + 8][kk * 16 + 2 * t + 8]);
            }
#pragma unroll
            for (int ni = 0; ni < 4; ni++) {
                int cn = n_base + ni * 8 + g;
                b[ni][0] = *reinterpret_cast<const unsigned*>(&W1s[buf][cn][kk * 16 + 2 * t]);
                b[ni][1] = *reinterpret_cast<const unsigned*>(&W1s[buf][cn][kk * 16 + 2 * t + 8]);
            }
#pragma unroll
            for (int mi = 0; mi < 2; mi++)
#pragma unroll
                for (int ni = 0; ni < 4; ni++) mma16(h_acc[mi][ni], a[mi], b[ni]);
        }

#pragma unroll
        for (int mi = 0; mi < 2; mi++)
#pragma unroll
            for (int ni = 0; ni < 4; ni++) {
                int r0 = m_base + mi * 16 + g;
                int hc = n_base + ni * 8 + 2 * t;
                float bb0 = b1[ch * 64 + hc], bb1 = b1[ch * 64 + hc + 1];
                float v0 = h_acc[mi][ni][0] + bb0;
                float v1 = h_acc[mi][ni][1] + bb1;
                float v2 = h_acc[mi][ni][2] + bb0;
                float v3 = h_acc[mi][ni][3] + bb1;
                v0 = (v0 >= 0.f) ? v0 : alpha * v0;
                v1 = (v1 >= 0.f) ? v1 : alpha * v1;
                v2 = (v2 >= 0.f) ? v2 : alpha * v2;
                v3 = (v3 >= 0.f) ? v3 : alpha * v3;
                *reinterpret_cast<__half2*>(&Hs[r0][hc]) = __floats2half2_rn(v0, v1);
                *reinterpret_cast<__half2*>(&Hs[r0 + 8][hc]) = __floats2half2_rn(v2, v3);
            }
        __syncthreads();

#pragma unroll
        for (int kk = 0; kk < 4; kk++) {
            unsigned a[2][4], b[4][2];
#pragma unroll
            for (int mi = 0; mi < 2; mi++) {
                int r0 = m_base + mi * 16 + g;
                a[mi][0] = *reinterpret_cast<const unsigned*>(&Hs[r0][kk * 16 + 2 * t]);
                a[mi][1] = *reinterpret_cast<const unsigned*>(&Hs[r0 + 8][kk * 16 + 2 * t]);
                a[mi][2] = *reinterpret_cast<const unsigned*>(&Hs[r0][kk * 16 + 2 * t + 8]);
                a[mi][3] = *reinterpret_cast<const unsigned*>(&Hs[r0 + 8][kk * 16 + 2 * t + 8]);
            }
#pragma unroll
            for (int ni = 0; ni < 4; ni++) {
                int cn = n_base + ni * 8 + g;
                b[ni][0] = *reinterpret_cast<const unsigned*>(&W3s[buf][cn][kk * 16 + 2 * t]);
                b[ni][1] = *reinterpret_cast<const unsigned*>(&W3s[buf][cn][kk * 16 + 2 * t + 8]);
            }
#pragma unroll
            for (int mi = 0; mi < 2; mi++)
#pragma unroll
                for (int ni = 0; ni < 4; ni++) mma16(out_acc[mi][ni], a[mi], b[ni]);
        }
    }

#pragma unroll
    for (int mi = 0; mi < 2; mi++)
#pragma unroll
        for (int ni = 0; ni < 4; ni++)
#pragma unroll
            for (int i = 0; i < 4; i++) {
                int row = m_base + mi * 16 + g + ((i >= 2) ? 8 : 0);
                int col = n_base + ni * 8 + 2 * t + (i & 1);
                int gm = bm + row;
                if (gm < M) C[(size_t)gm * 64 + col] = out_acc[mi][ni][i] + b3[col];
            }
}

// ---------------- fp16-gather SpMM (4 thr/edge, 16 cols each; optional degree) -------
__device__ __forceinline__ void gather8(const __half* base, unsigned off, float* f) {
    uint4 u = *reinterpret_cast<const uint4*>(base + off);
    const __half2* h = reinterpret_cast<const __half2*>(&u);
#pragma unroll
    for (int i = 0; i < 4; i++) {
        float2 a = __half22float2(h[i]);
        f[2 * i] = a.x;
        f[2 * i + 1] = a.y;
    }
}
__device__ __forceinline__ void red4(float* p, float a, float b, float c, float d) {
    asm volatile("red.global.add.v4.f32 [%0], {%1,%2,%3,%4};" ::"l"(p), "f"(a), "f"(b), "f"(c),
                 "f"(d)
                 : "memory");
}

__global__ void spmm64h(const int* __restrict__ src, const int* __restrict__ dst,
                        const float* __restrict__ val, const __half* __restrict__ X,
                        float* __restrict__ out, float* __restrict__ deg, int E) {
    unsigned gid = blockIdx.x * blockDim.x + threadIdx.x;
    unsigned e = gid >> 2;
    if (e >= (unsigned)E) return;
    unsigned c = gid & 3;
    int s = src[e];
    int d = dst[e];
    float v = val[e];
    float f[16];
    gather8(X, (unsigned)d * 64 + c * 16, f);
    gather8(X, (unsigned)d * 64 + c * 16 + 8, f + 8);
    float* p = out + (size_t)s * 64 + c * 16;
#pragma unroll
    for (int i = 0; i < 4; i++)
        red4(p + 4 * i, v * f[4 * i], v * f[4 * i + 1], v * f[4 * i + 2], v * f[4 * i + 3]);
    if (deg != nullptr && c == 0) atomicAdd(&deg[s], v);
}

// adj + shuffled-adj in one pass (shares index loads) + adj degree
__global__ void spmm64h_dual(const int* __restrict__ src, const int* __restrict__ dst,
                             const float* __restrict__ val, const int* __restrict__ perm,
                             const __half* __restrict__ X, float* __restrict__ out0,
                             float* __restrict__ out1, float* __restrict__ deg, int E) {
    unsigned gid = blockIdx.x * blockDim.x + threadIdx.x;
    unsigned e = gid >> 2;
    if (e >= (unsigned)E) return;
    unsigned c = gid & 3;
    int s = src[e];
    int d = dst[e];
    float v = val[e];
    int pd = perm[d];
    float f0[16], f1[16];
    gather8(X, (unsigned)d * 64 + c * 16, f0);
    gather8(X, (unsigned)d * 64 + c * 16 + 8, f0 + 8);
    gather8(X, (unsigned)pd * 64 + c * 16, f1);
    gather8(X, (unsigned)pd * 64 + c * 16 + 8, f1 + 8);
    float* p0 = out0 + (size_t)s * 64 + c * 16;
    float* p1 = out1 + (size_t)s * 64 + c * 16;
#pragma unroll
    for (int i = 0; i < 4; i++) {
        red4(p0 + 4 * i, v * f0[4 * i], v * f0[4 * i + 1], v * f0[4 * i + 2], v * f0[4 * i + 3]);
        red4(p1 + 4 * i, v * f1[4 * i], v * f1[4 * i + 1], v * f1[4 * i + 2], v * f1[4 * i + 3]);
    }
    if (c == 0) atomicAdd(&deg[s], v);
}

// ---------------- relu(stage slots 0..2) -> fp16 MLPINH slots 0..2 ----------------
__global__ void relu_to_half(const float4* __restrict__ stage, __half* __restrict__ hout,
                             int n4) {
    int i = blockIdx.x * blockDim.x + threadIdx.x;
    if (i < n4) {
        float4 v = stage[i];
        __half2 a = __floats2half2_rn(fmaxf(v.x, 0.f), fmaxf(v.y, 0.f));
        __half2 b = __floats2half2_rn(fmaxf(v.z, 0.f), fmaxf(v.w, 0.f));
        uint2 u;
        u.x = *reinterpret_cast<unsigned*>(&a);
        u.y = *reinterpret_cast<unsigned*>(&b);
        *reinterpret_cast<uint2*>(hout + (size_t)i * 4) = u;
    }
}

// ---------------- sigmoid(stage slots 3,4 / max(deg,1)) -> fp16 MLPINH 3,4 -----------
__global__ void sigavg_to_half(const float4* __restrict__ stage, __half* __restrict__ hout,
                               const float* __restrict__ degN, const float* __restrict__ degD) {
    int i = blockIdx.x * blockDim.x + threadIdx.x;
    const int n4 = NN * 16;  // float4s per slot
    if (i < 2 * n4) {
        int j = i * 4;  // element index across two slots
        const float* deg = (i < n4) ? degN : degD;
        int node = ((i < n4) ? j : (j - NN * 64)) >> 6;
        float d = deg[node];
        d = (d > 1.f) ? d : 1.f;
        float4 v = stage[i];
        float s0 = 1.f / (1.f + expf(-v.x / d));
        float s1 = 1.f / (1.f + expf(-v.y / d));
        float s2 = 1.f / (1.f + expf(-v.z / d));
        float s3 = 1.f / (1.f + expf(-v.w / d));
        __half2 a = __floats2half2_rn(s0, s1);
        __half2 b = __floats2half2_rn(s2, s3);
        uint2 u;
        u.x = *reinterpret_cast<unsigned*>(&a);
        u.y = *reinterpret_cast<unsigned*>(&b);
        *reinterpret_cast<uint2*>(hout + (size_t)i * 4) = u;
    }
}

// ---------------- discriminator ----------------
__global__ void disc_kernel(const float* __restrict__ Mo, const float* __restrict__ W,
                            const float* __restrict__ bptr, float* __restrict__ ret,
                            float* __restrict__ ret_a) {
    __shared__ float Ws[64][65];
    int tid = threadIdx.x;
    for (int i = tid; i < 4096; i += 128) Ws[i >> 6][i & 63] = W[i];
    __syncthreads();

    int warp = tid >> 5, lane = tid & 31;
    int node = blockIdx.x * 4 + warp;
    if (node >= NN) return;

    const float* z = Mo + (size_t)0 * NN * 64 + (size_t)node * 64;
    const float* zg = Mo + (size_t)1 * NN * 64 + (size_t)node * 64;
    const float* sz = Mo + (size_t)2 * NN * 64 + (size_t)node * 64;
    const float* gv = Mo + (size_t)3 * NN * 64 + (size_t)node * 64;
    const float* gg = Mo + (size_t)4 * NN * 64 + (size_t)node * 64;

    float r0 = 0.f, r1 = 0.f, a0 = 0.f, a1 = 0.f;
#pragma unroll
    for (int h = 0; h < 2; h++) {
        int d = lane + h * 32;
        float tgg = 0.f, tg = 0.f;
#pragma unroll
        for (int e = 0; e < 64; e++) {
            float w = Ws[d][e];
            tgg += w * gg[e];
            tg += w * gv[e];
        }
        r0 += z[d] * tgg;
        r1 += sz[d] * tgg;
        a0 += zg[d] * tg;
        a1 += sz[d] * tg;
    }
#pragma unroll
    for (int o = 16; o; o >>= 1) {
        r0 += __shfl_xor_sync(0xFFFFFFFFu, r0, o);
        r1 += __shfl_xor_sync(0xFFFFFFFFu, r1, o);
        a0 += __shfl_xor_sync(0xFFFFFFFFu, a0, o);
        a1 += __shfl_xor_sync(0xFFFFFFFFu, a1, o);
    }
    if (lane == 0) {
        float b = bptr[0];
        ret[(size_t)node * 2 + 0] = r0 + b;
        ret[(size_t)node * 2 + 1] = r1 + b;
        ret_a[(size_t)node * 2 + 0] = a0 + b;
        ret_a[(size_t)node * 2 + 1] = a1 + b;
    }
}

// =====================================================================================
extern "C" void kernel_launch(void* const* d_in, const int* in_sizes, int n_in, void* d_out,
                              int out_size) {
    (void)in_sizes; (void)n_in; (void)out_size;

    const float* feat      = (const float*)d_in[0];
    const int*   adj_src   = (const int*)d_in[1];
    const int*   adj_dst   = (const int*)d_in[2];
    const float* adj_val   = (const float*)d_in[3];
    const int*   gdc_src   = (const int*)d_in[4];
    const int*   gdc_dst   = (const int*)d_in[5];
    const float* gdc_val   = (const float*)d_in[6];
    const int*   neigh_src = (const int*)d_in[7];
    const int*   neigh_dst = (const int*)d_in[8];
    const float* neigh_val = (const float*)d_in[9];
    const int*   diff_src  = (const int*)d_in[10];
    const int*   diff_dst  = (const int*)d_in[11];
    const float* diff_val  = (const float*)d_in[12];
    const int*   perm      = (const int*)d_in[13];
    const float* W_enc     = (const float*)d_in[14];
    const float* b_enc     = (const float*)d_in[15];
    const float* W_dec     = (const float*)d_in[16];
    const float* b_dec     = (const float*)d_in[17];
    const float* W1        = (const float*)d_in[18];
    const float* b1        = (const float*)d_in[19];
    const float* prelu_a   = (const float*)d_in[20];
    const float* W3        = (const float*)d_in[21];
    const float* b3        = (const float*)d_in[22];
    const float* W_disc    = (const float*)d_in[23];
    const float* b_disc    = (const float*)d_in[24];

    __half *Xhp, *MLPINHp, *W1Tp, *W3Tp;
    float *STAGEp, *Sp, *MLPOUTp, *DEGp;
    cudaGetSymbolAddress((void**)&Xhp, g_Xh);
    cudaGetSymbolAddress((void**)&MLPINHp, g_MLPINH);
    cudaGetSymbolAddress((void**)&W1Tp, g_W1T);
    cudaGetSymbolAddress((void**)&W3Tp, g_W3T);
    cudaGetSymbolAddress((void**)&STAGEp, g_STAGE);
    cudaGetSymbolAddress((void**)&Sp, g_S);
    cudaGetSymbolAddress((void**)&MLPOUTp, g_MLPOUT);
    cudaGetSymbolAddress((void**)&DEGp, g_DEG);

    float* out = (float*)d_out;
    float* emb = out;                       // [NN,256]
    float* ret = out + (size_t)NN * 256;    // [NN,2]
    float* ret_a = ret + (size_t)NN * 2;    // [NN,2]

    const int MLP_SMEM = (2 * 256 * 72 + 4 * 64 * 72) * 2;  // 110592 B
    static bool attr_set = false;
    if (!attr_set) {
        cudaFuncSetAttribute(mlp16, cudaFuncAttributeMaxDynamicSharedMemorySize, MLP_SMEM);
        attr_set = true;
    }

    const int MROWS = (NN + 127) / 128;                               // 391
    const unsigned spmm_blocks = ((unsigned)EE * 4u + 255u) / 256u;   // 12500

    // zero accumulators
    cudaMemsetAsync(STAGEp, 0, (size_t)5 * NN * 64 * sizeof(float));
    cudaMemsetAsync(Sp, 0, (size_t)NN * 64 * sizeof(float));
    cudaMemsetAsync(DEGp, 0, (size_t)3 * NN * sizeof(float));

    // weight pre-transpose (16 parallel blocks)
    transpose_w<<<16, 512>>>(W1, W3, W1Tp, W3Tp);

    // Xh = half(feat @ W_enc + b_enc)  [NN,64]  (tf32)
    mma_gemm<2><<<dim3(1, MROWS), 256>>>(feat, W_enc, b_enc, nullptr, nullptr, Xhp, NN, 256, 64);

    // h (stage0) + shuf_h (stage2) in one pass (+ adj degree); h_g (stage1)
    spmm64h_dual<<<spmm_blocks, 256>>>(adj_src, adj_dst, adj_val, perm, Xhp,
                                       STAGEp + (size_t)0 * NN * 64,
                                       STAGEp + (size_t)2 * NN * 64, DEGp, EE);
    spmm64h<<<spmm_blocks, 256>>>(gdc_src, gdc_dst, gdc_val, Xhp, STAGEp + (size_t)1 * NN * 64,
                                  nullptr, EE);

    // relu stage 0..2 -> fp16 MLPINH slots 0..2 (slot0/1 double as stage-2 gather tables)
    {
        int n4 = 3 * NN * 16;
        relu_to_half<<<(n4 + 255) / 256, 256>>>((const float4*)STAGEp, MLPINHp, n4);
    }

    // S = spmm(adj, relu_h); neigh -> stage3 (+degN); diff -> stage4 (+degD)
    spmm64h<<<spmm_blocks, 256>>>(adj_src, adj_dst, adj_val, MLPINHp, Sp, nullptr, EE);
    spmm64h<<<spmm_blocks, 256>>>(neigh_src, neigh_dst, neigh_val, MLPINHp,
                                  STAGEp + (size_t)3 * NN * 64, DEGp + NN, EE);
    spmm64h<<<spmm_blocks, 256>>>(diff_src, diff_dst, diff_val, MLPINHp + (size_t)NN * 64,
                                  STAGEp + (size_t)4 * NN * 64, DEGp + 2 * NN, EE);

    // emb = relu(S @ W_dec + deg_adj ⊗ b_dec)  (spmm linearity), tf32
    mma_gemm<1><<<dim3(4, MROWS), 256>>>(Sp, W_dec, b_dec, DEGp, emb, nullptr, NN, 64, 256);

    // sigmoid averages -> fp16 MLPINH slots 3,4
    {
        int n2 = 2 * NN * 16;
        sigavg_to_half<<<(n2 + 255) / 256, 256>>>((const float4*)(STAGEp + (size_t)3 * NN * 64),
                                                  MLPINHp + (size_t)3 * NN * 64, DEGp + NN,
                                                  DEGp + 2 * NN);
    }

    // fused batched MLP over all 5 fp16 inputs
    {
        int M = 5 * NN;
        mlp16<<<(M + 255) / 256, 512, MLP_SMEM>>>(MLPINHp, W1Tp, b1, prelu_a, W3Tp, b3, MLPOUTp,
                                                  M);
    }

    // discriminator heads
    disc_kernel<<<(NN + 3) / 4, 128>>>(MLPOUTp, W_disc, b_disc, ret, ret_a);
}

// round 12
// speedup vs baseline: 1.3640x; 1.0068x over previous
#include <cuda_runtime.h>
#include <cuda_fp16.h>
#include <math.h>

#define NN 50000
#define EE 800000

// ---------------- scratch (static device globals; no runtime alloc) ----------------
__device__ __half g_Xh[(size_t)NN * 64];           // feat@W_enc + b_enc (fp16, gather table)
__device__ float  g_STAGE[(size_t)5 * NN * 64];    // fp32 atomic staging: h,h_g,shuf_h,nsum,dsum
__device__ __half g_MLPINH[(size_t)5 * NN * 64];   // fp16 MLP inputs (slots 0/1 = gather tables)
__device__ float  g_S[(size_t)NN * 64];            // spmm(adj, relu_h)
__device__ float  g_MLPOUT[(size_t)5 * NN * 64];   // z, z_g, shuf_z, g, g_g
__device__ float  g_DEG[3 * NN];                   // [adj | neigh | diff]
__device__ __half g_W1T[512 * 64];                 // W1 transposed [n][k] fp16
__device__ __half g_W3T[64 * 512];                 // W3 transposed [n][k] fp16

// ---------------- mma helpers ----------------
__device__ __forceinline__ unsigned cvt_tf32(float x) {
    unsigned u;
    asm("cvt.rna.tf32.f32 %0, %1;" : "=r"(u) : "f"(x));
    return u;
}
__device__ __forceinline__ void mma8(float* c, const unsigned* a, const unsigned* b) {
    asm("mma.sync.aligned.m16n8k8.row.col.f32.tf32.tf32.f32 "
        "{%0,%1,%2,%3},{%4,%5,%6,%7},{%8,%9},{%0,%1,%2,%3};"
        : "+f"(c[0]), "+f"(c[1]), "+f"(c[2]), "+f"(c[3])
        : "r"(a[0]), "r"(a[1]), "r"(a[2]), "r"(a[3]), "r"(b[0]), "r"(b[1]));
}
__device__ __forceinline__ void mma16(float* c, const unsigned* a, const unsigned* b) {
    asm("mma.sync.aligned.m16n8k16.row.col.f32.f16.f16.f32 "
        "{%0,%1,%2,%3},{%4,%5,%6,%7},{%8,%9},{%0,%1,%2,%3};"
        : "+f"(c[0]), "+f"(c[1]), "+f"(c[2]), "+f"(c[3])
        : "r"(a[0]), "r"(a[1]), "r"(a[2]), "r"(a[3]), "r"(b[0]), "r"(b[1]));
}

#define CP16(sdst, gsrc) \
    asm volatile("cp.async.ca.shared.global [%0], [%1], 16;" ::"r"(sdst), "l"(gsrc))
#define CP_COMMIT() asm volatile("cp.async.commit_group;")
#define CP_WAIT0() asm volatile("cp.async.wait_group 0;" ::: "memory")

// ---------------- weight pre-transpose (fp32 -> fp16, [k][n] -> [n][k]) --------------
__global__ void transpose_w(const float* __restrict__ W1, const float* __restrict__ W3,
                            __half* __restrict__ W1T, __half* __restrict__ W3T) {
    int b = blockIdx.x, t = threadIdx.x;
    if (b < 8) {
        int n = b * 64 + (t >> 3);
        int k0 = (t & 7) * 8;
#pragma unroll
        for (int i = 0; i < 8; i++)
            W1T[n * 64 + k0 + i] = __float2half_rn(W1[(size_t)(k0 + i) * 512 + n]);
    } else {
        int n = (b - 8) * 8 + (t >> 6);
        int k0 = (t & 63) * 8;
#pragma unroll
        for (int i = 0; i < 8; i++)
            W3T[n * 512 + k0 + i] = __float2half_rn(W3[(size_t)(k0 + i) * 64 + n]);
    }
}

// ---------------- single-TF32 GEMM ----------------
// EPI 1: C = relu(acc + deg[m]*bias[n]) fp32; EPI 2: Ch = half(acc + bias[n]) fp16
template <int EPI>
__global__ __launch_bounds__(256) void mma_gemm(const float* __restrict__ A,
                                                const float* __restrict__ W,
                                                const float* __restrict__ bias,
                                                const float* __restrict__ deg,
                                                float* __restrict__ C, __half* __restrict__ Ch,
                                                int M, int K, int Nc) {
    __shared__ unsigned As[128][36];
    __shared__ unsigned Bs[32][72];

    const int tid = threadIdx.x, lane = tid & 31, wid = tid >> 5;
    const int bm = blockIdx.y * 128, bn0 = blockIdx.x * 64;
    const int m_base = (wid & 3) * 32, n_base = (wid >> 2) * 32;
    const int lr = lane >> 2, lk = lane & 3;

    float acc[2][4][4];
#pragma unroll
    for (int mi = 0; mi < 2; mi++)
#pragma unroll
        for (int ni = 0; ni < 4; ni++)
#pragma unroll
            for (int i = 0; i < 4; i++) acc[mi][ni][i] = 0.f;

    for (int k0 = 0; k0 < K; k0 += 32) {
#pragma unroll
        for (int p = 0; p < 4; p++) {
            int idx = tid + p * 256;
            int row = idx >> 3, q = idx & 7;
            float4 v = make_float4(0.f, 0.f, 0.f, 0.f);
            if (bm + row < M)
                v = *reinterpret_cast<const float4*>(A + (size_t)(bm + row) * K + k0 + q * 4);
            As[row][q * 4 + 0] = cvt_tf32(v.x);
            As[row][q * 4 + 1] = cvt_tf32(v.y);
            As[row][q * 4 + 2] = cvt_tf32(v.z);
            As[row][q * 4 + 3] = cvt_tf32(v.w);
        }
#pragma unroll
        for (int p = 0; p < 2; p++) {
            int idx = tid + p * 256;
            int kr = idx >> 4, q = idx & 15;
            float4 v = *reinterpret_cast<const float4*>(W + (size_t)(k0 + kr) * Nc + bn0 + q * 4);
            Bs[kr][q * 4 + 0] = cvt_tf32(v.x);
            Bs[kr][q * 4 + 1] = cvt_tf32(v.y);
            Bs[kr][q * 4 + 2] = cvt_tf32(v.z);
            Bs[kr][q * 4 + 3] = cvt_tf32(v.w);
        }
        __syncthreads();

#pragma unroll
        for (int kk = 0; kk < 4; kk++) {
            unsigned a[2][4], b[4][2];
#pragma unroll
            for (int mi = 0; mi < 2; mi++) {
                int r0 = m_base + mi * 16 + lr;
                a[mi][0] = As[r0][kk * 8 + lk];
                a[mi][1] = As[r0 + 8][kk * 8 + lk];
                a[mi][2] = As[r0][kk * 8 + lk + 4];
                a[mi][3] = As[r0 + 8][kk * 8 + lk + 4];
            }
#pragma unroll
            for (int ni = 0; ni < 4; ni++) {
                int cn = n_base + ni * 8 + lr;
                b[ni][0] = Bs[kk * 8 + lk][cn];
                b[ni][1] = Bs[kk * 8 + lk + 4][cn];
            }
#pragma unroll
            for (int mi = 0; mi < 2; mi++)
#pragma unroll
                for (int ni = 0; ni < 4; ni++) mma8(acc[mi][ni], a[mi], b[ni]);
        }
        __syncthreads();
    }

#pragma unroll
    for (int mi = 0; mi < 2; mi++)
#pragma unroll
        for (int ni = 0; ni < 4; ni++) {
#pragma unroll
            for (int hi = 0; hi < 2; hi++) {
                int row = m_base + mi * 16 + lr + hi * 8;
                int col = n_base + ni * 8 + 2 * lk;
                int gm = bm + row, gn = bn0 + col;
                if (gm < M) {
                    float v0 = acc[mi][ni][hi * 2 + 0];
                    float v1 = acc[mi][ni][hi * 2 + 1];
                    if (EPI == 1) {
                        float dg = deg[gm];
                        v0 = fmaxf(v0 + dg * bias[gn], 0.f);
                        v1 = fmaxf(v1 + dg * bias[gn + 1], 0.f);
                        C[(size_t)gm * Nc + gn] = v0;
                        C[(size_t)gm * Nc + gn + 1] = v1;
                    } else {
                        v0 += bias[gn];
                        v1 += bias[gn + 1];
                        *reinterpret_cast<__half2*>(Ch + (size_t)gm * Nc + gn) =
                            __floats2half2_rn(v0, v1);
                    }
                }
            }
        }
}

// ---------------- fused MLP (fp16 mma, pre-transposed weights, fp16 A) ---------------
__global__ __launch_bounds__(512, 1) void mlp16(const __half* __restrict__ A,
                                                const __half* __restrict__ W1T,
                                                const float* __restrict__ b1,
                                                const float* __restrict__ aptr,
                                                const __half* __restrict__ W3T,
                                                const float* __restrict__ b3,
                                                float* __restrict__ C, int M) {
    extern __shared__ __half hsm[];
    __half(*As)[72] = (__half(*)[72])hsm;
    __half(*Hs)[72] = (__half(*)[72])(hsm + 256 * 72);
    const unsigned W1_OFF = 2 * 256 * 72;
    const unsigned W3_OFF = W1_OFF + 2 * 64 * 72;
    __half(*W1s)[64][72] = (__half(*)[64][72])(hsm + W1_OFF);
    __half(*W3s)[64][72] = (__half(*)[64][72])(hsm + W3_OFF);

    const int tid = threadIdx.x, lane = tid & 31, wid = tid >> 5;
    const int bm = blockIdx.x * 256;
    const int m_base = (wid & 7) * 32, n_base = (wid >> 3) * 32;
    const int g = lane >> 2, t = lane & 3;
    const float alpha = aptr[0];
    const unsigned sb = (unsigned)__cvta_generic_to_shared(hsm);

    auto issue = [&](int ch, int buf) {
        int n = tid >> 3, o = tid & 7;
        const __half* s1 = W1T + ((size_t)(ch * 64 + n)) * 64 + o * 8;
        unsigned d1 = sb + (W1_OFF + (unsigned)buf * 64 * 72 + n * 72 + o * 8) * 2u;
        CP16(d1, s1);
        const __half* s3 = W3T + (size_t)n * 512 + ch * 64 + o * 8;
        unsigned d3 = sb + (W3_OFF + (unsigned)buf * 64 * 72 + n * 72 + o * 8) * 2u;
        CP16(d3, s3);
        CP_COMMIT();
    };
    issue(0, 0);

    // A tile 256x64 fp16: straight uint4 copy
#pragma unroll
    for (int p = 0; p < 4; p++) {
        int idx = tid + p * 512;
        int row = idx >> 3, q = idx & 7;
        uint4 u = make_uint4(0u, 0u, 0u, 0u);
        if (bm + row < M)
            u = *reinterpret_cast<const uint4*>(A + (size_t)(bm + row) * 64 + q * 8);
        *reinterpret_cast<uint4*>(&As[row][q * 8]) = u;
    }

    float out_acc[2][4][4];
#pragma unroll
    for (int mi = 0; mi < 2; mi++)
#pragma unroll
        for (int ni = 0; ni < 4; ni++)
#pragma unroll
            for (int i = 0; i < 4; i++) out_acc[mi][ni][i] = 0.f;

    for (int ch = 0; ch < 8; ch++) {
        const int buf = ch & 1;
        CP_WAIT0();
        __syncthreads();
        if (ch < 7) issue(ch + 1, buf ^ 1);

        float h_acc[2][4][4];
#pragma unroll
        for (int mi = 0; mi < 2; mi++)
#pragma unroll
            for (int ni = 0; ni < 4; ni++)
#pragma unroll
                for (int i = 0; i < 4; i++) h_acc[mi][ni][i] = 0.f;

#pragma unroll
        for (int kk = 0; kk < 4; kk++) {
            unsigned a[2][4], b[4][2];
#pragma unroll
            for (int mi = 0; mi < 2; mi++) {
                int r0 = m_base + mi * 16 + g;
                a[mi][0] = *reinterpret_cast<const unsigned*>(&As[r0][kk * 16 + 2 * t]);
                a[mi][1] = *reinterpret_cast<const unsigned*>(&As[r0 + 8][kk * 16 + 2 * t]);
                a[mi][2] = *reinterpret_cast<const unsigned*>(&As[r0][kk * 16 + 2 * t + 8]);
                a[mi][3] = *reinterpret_cast<const unsigned*>(&As[r0 + 8][kk * 16 + 2 * t + 8]);
            }
#pragma unroll
            for (int ni = 0; ni < 4; ni++) {
                int cn = n_base + ni * 8 + g;
                b[ni][0] = *reinterpret_cast<const unsigned*>(&W1s[buf][cn][kk * 16 + 2 * t]);
                b[ni][1] = *reinterpret_cast<const unsigned*>(&W1s[buf][cn][kk * 16 + 2 * t + 8]);
            }
#pragma unroll
            for (int mi = 0; mi < 2; mi++)
#pragma unroll
                for (int ni = 0; ni < 4; ni++) mma16(h_acc[mi][ni], a[mi], b[ni]);
        }

#pragma unroll
        for (int mi = 0; mi < 2; mi++)
#pragma unroll
            for (int ni = 0; ni < 4; ni++) {
                int r0 = m_base + mi * 16 + g;
                int hc = n_base + ni * 8 + 2 * t;
                float bb0 = b1[ch * 64 + hc], bb1 = b1[ch * 64 + hc + 1];
                float v0 = h_acc[mi][ni][0] + bb0;
                float v1 = h_acc[mi][ni][1] + bb1;
                float v2 = h_acc[mi][ni][2] + bb0;
                float v3 = h_acc[mi][ni][3] + bb1;
                v0 = (v0 >= 0.f) ? v0 : alpha * v0;
                v1 = (v1 >= 0.f) ? v1 : alpha * v1;
                v2 = (v2 >= 0.f) ? v2 : alpha * v2;
                v3 = (v3 >= 0.f) ? v3 : alpha * v3;
                *reinterpret_cast<__half2*>(&Hs[r0][hc]) = __floats2half2_rn(v0, v1);
                *reinterpret_cast<__half2*>(&Hs[r0 + 8][hc]) = __floats2half2_rn(v2, v3);
            }
        __syncthreads();

#pragma unroll
        for (int kk = 0; kk < 4; kk++) {
            unsigned a[2][4], b[4][2];
#pragma unroll
            for (int mi = 0; mi < 2; mi++) {
                int r0 = m_base + mi * 16 + g;
                a[mi][0] = *reinterpret_cast<const unsigned*>(&Hs[r0][kk * 16 + 2 * t]);
                a[mi][1] = *reinterpret_cast<const unsigned*>(&Hs[r0 + 8][kk * 16 + 2 * t]);
                a[mi][2] = *reinterpret_cast<const unsigned*>(&Hs[r0][kk * 16 + 2 * t + 8]);
                a[mi][3] = *reinterpret_cast<const unsigned*>(&Hs[r0 + 8][kk * 16 + 2 * t + 8]);
            }
#pragma unroll
            for (int ni = 0; ni < 4; ni++) {
                int cn = n_base + ni * 8 + g;
                b[ni][0] = *reinterpret_cast<const unsigned*>(&W3s[buf][cn][kk * 16 + 2 * t]);
                b[ni][1] = *reinterpret_cast<const unsigned*>(&W3s[buf][cn][kk * 16 + 2 * t + 8]);
            }
#pragma unroll
            for (int mi = 0; mi < 2; mi++)
#pragma unroll
                for (int ni = 0; ni < 4; ni++) mma16(out_acc[mi][ni], a[mi], b[ni]);
        }
    }

#pragma unroll
    for (int mi = 0; mi < 2; mi++)
#pragma unroll
        for (int ni = 0; ni < 4; ni++)
#pragma unroll
            for (int i = 0; i < 4; i++) {
                int row = m_base + mi * 16 + g + ((i >= 2) ? 8 : 0);
                int col = n_base + ni * 8 + 2 * t + (i & 1);
                int gm = bm + row;
                if (gm < M) C[(size_t)gm * 64 + col] = out_acc[mi][ni][i] + b3[col];
            }
}

// ---------------- fp16-gather SpMM primitives ----------------
__device__ __forceinline__ void red4(float* p, float a, float b, float c, float d) {
    asm volatile("red.global.add.v4.f32 [%0], {%1,%2,%3,%4};" ::"l"(p), "f"(a), "f"(b), "f"(c),
                 "f"(d)
                 : "memory");
}
__device__ __forceinline__ void mulred16(const uint4& ra, const uint4& rb, float v, float* p) {
    const __half2* ha = reinterpret_cast<const __half2*>(&ra);
    const __half2* hb = reinterpret_cast<const __half2*>(&rb);
    float f[16];
#pragma unroll
    for (int i = 0; i < 4; i++) {
        float2 x = __half22float2(ha[i]);
        f[2 * i] = v * x.x;
        f[2 * i + 1] = v * x.y;
        float2 y = __half22float2(hb[i]);
        f[8 + 2 * i] = v * y.x;
        f[8 + 2 * i + 1] = v * y.y;
    }
#pragma unroll
    for (int i = 0; i < 4; i++)
        red4(p + 4 * i, f[4 * i], f[4 * i + 1], f[4 * i + 2], f[4 * i + 3]);
}

// spmm body: 2 edges per thread (q and q+E/2), 4 threads/edge (16 cols each).
__device__ __forceinline__ void spmm2_body(unsigned gid, const int* __restrict__ src,
                                           const int* __restrict__ dst,
                                           const float* __restrict__ val,
                                           const __half* __restrict__ X, float* __restrict__ out,
                                           float* __restrict__ deg, int E) {
    unsigned half_e = (unsigned)E >> 1;
    unsigned q = gid >> 2;
    if (q >= half_e) return;
    unsigned c = gid & 3;
    unsigned e1 = q + half_e;
    int s0 = src[q], d0 = dst[q];
    float v0 = val[q];
    int s1 = src[e1], d1 = dst[e1];
    float v1 = val[e1];
    const __half* g0 = X + (size_t)(unsigned)d0 * 64 + c * 16;
    const __half* g1 = X + (size_t)(unsigned)d1 * 64 + c * 16;
    uint4 ra0 = *reinterpret_cast<const uint4*>(g0);
    uint4 rb0 = *reinterpret_cast<const uint4*>(g0 + 8);
    uint4 ra1 = *reinterpret_cast<const uint4*>(g1);
    uint4 rb1 = *reinterpret_cast<const uint4*>(g1 + 8);
    mulred16(ra0, rb0, v0, out + (size_t)s0 * 64 + c * 16);
    mulred16(ra1, rb1, v1, out + (size_t)s1 * 64 + c * 16);
    if (deg != nullptr && c == 0) {
        atomicAdd(&deg[s0], v0);
        atomicAdd(&deg[s1], v1);
    }
}

__global__ __launch_bounds__(256) void spmm64h2(const int* __restrict__ src,
                                                const int* __restrict__ dst,
                                                const float* __restrict__ val,
                                                const __half* __restrict__ X,
                                                float* __restrict__ out,
                                                float* __restrict__ deg, int E) {
    unsigned gid = blockIdx.x * blockDim.x + threadIdx.x;
    spmm2_body(gid, src, dst, val, X, out, deg, E);
}

// stage 2 fused: seg 0 = adj->S, seg 1 = neigh->stage3 (+degN), seg 2 = diff->stage4 (+degD)
__global__ __launch_bounds__(256) void spmm_stage2_all(
    const int* __restrict__ sA, const int* __restrict__ dA, const float* __restrict__ vA,
    const int* __restrict__ sN, const int* __restrict__ dN, const float* __restrict__ vN,
    const int* __restrict__ sD, const int* __restrict__ dD, const float* __restrict__ vD,
    const __half* __restrict__ H0, const __half* __restrict__ H1, float* __restrict__ S,
    float* __restrict__ st3, float* __restrict__ st4, float* __restrict__ degN,
    float* __restrict__ degD, int E, int segBlocks) {
    int seg = blockIdx.x / segBlocks;
    int blk = blockIdx.x - seg * segBlocks;
    unsigned gid = (unsigned)blk * blockDim.x + threadIdx.x;
    if (seg == 0) {
        spmm2_body(gid, sA, dA, vA, H0, S, nullptr, E);
    } else if (seg == 1) {
        spmm2_body(gid, sN, dN, vN, H0, st3, degN, E);
    } else {
        spmm2_body(gid, sD, dD, vD, H1, st4, degD, E);
    }
}

// adj + shuffled-adj in one pass (shares index loads) + adj degree (1 edge/thread)
__global__ void spmm64h_dual(const int* __restrict__ src, const int* __restrict__ dst,
                             const float* __restrict__ val, const int* __restrict__ perm,
                             const __half* __restrict__ X, float* __restrict__ out0,
                             float* __restrict__ out1, float* __restrict__ deg, int E) {
    unsigned gid = blockIdx.x * blockDim.x + threadIdx.x;
    unsigned e = gid >> 2;
    if (e >= (unsigned)E) return;
    unsigned c = gid & 3;
    int s = src[e];
    int d = dst[e];
    float v = val[e];
    int pd = perm[d];
    const __half* g0 = X + (unsigned)d * 64 + c * 16;
    const __half* g1 = X + (unsigned)pd * 64 + c * 16;
    uint4 ra0 = *reinterpret_cast<const uint4*>(g0);
    uint4 rb0 = *reinterpret_cast<const uint4*>(g0 + 8);
    uint4 ra1 = *reinterpret_cast<const uint4*>(g1);
    uint4 rb1 = *reinterpret_cast<const uint4*>(g1 + 8);
    mulred16(ra0, rb0, v, out0 + (size_t)s * 64 + c * 16);
    mulred16(ra1, rb1, v, out1 + (size_t)s * 64 + c * 16);
    if (c == 0) atomicAdd(&deg[s], v);
}

// ---------------- relu(stage slots 0..2) -> fp16 MLPINH slots 0..2 ----------------
__global__ void relu_to_half(const float4* __restrict__ stage, __half* __restrict__ hout,
                             int n4) {
    int i = blockIdx.x * blockDim.x + threadIdx.x;
    if (i < n4) {
        float4 v = stage[i];
        __half2 a = __floats2half2_rn(fmaxf(v.x, 0.f), fmaxf(v.y, 0.f));
        __half2 b = __floats2half2_rn(fmaxf(v.z, 0.f), fmaxf(v.w, 0.f));
        uint2 u;
        u.x = *reinterpret_cast<unsigned*>(&a);
        u.y = *reinterpret_cast<unsigned*>(&b);
        *reinterpret_cast<uint2*>(hout + (size_t)i * 4) = u;
    }
}

// ---------------- sigmoid(stage slots 3,4 / max(deg,1)) -> fp16 MLPINH 3,4 -----------
__global__ void sigavg_to_half(const float4* __restrict__ stage, __half* __restrict__ hout,
                               const float* __restrict__ degN, const float* __restrict__ degD) {
    int i = blockIdx.x * blockDim.x + threadIdx.x;
    const int n4 = NN * 16;
    if (i < 2 * n4) {
        int j = i * 4;
        const float* deg = (i < n4) ? degN : degD;
        int node = ((i < n4) ? j : (j - NN * 64)) >> 6;
        float d = deg[node];
        d = (d > 1.f) ? d : 1.f;
        float4 v = stage[i];
        float s0 = 1.f / (1.f + expf(-v.x / d));
        float s1 = 1.f / (1.f + expf(-v.y / d));
        float s2 = 1.f / (1.f + expf(-v.z / d));
        float s3 = 1.f / (1.f + expf(-v.w / d));
        __half2 a = __floats2half2_rn(s0, s1);
        __half2 b = __floats2half2_rn(s2, s3);
        uint2 u;
        u.x = *reinterpret_cast<unsigned*>(&a);
        u.y = *reinterpret_cast<unsigned*>(&b);
        *reinterpret_cast<uint2*>(hout + (size_t)i * 4) = u;
    }
}

// ---------------- discriminator ----------------
__global__ void disc_kernel(const float* __restrict__ Mo, const float* __restrict__ W,
                            const float* __restrict__ bptr, float* __restrict__ ret,
                            float* __restrict__ ret_a) {
    __shared__ float Ws[64][65];
    int tid = threadIdx.x;
    for (int i = tid; i < 4096; i += 128) Ws[i >> 6][i & 63] = W[i];
    __syncthreads();

    int warp = tid >> 5, lane = tid & 31;
    int node = blockIdx.x * 4 + warp;
    if (node >= NN) return;

    const float* z = Mo + (size_t)0 * NN * 64 + (size_t)node * 64;
    const float* zg = Mo + (size_t)1 * NN * 64 + (size_t)node * 64;
    const float* sz = Mo + (size_t)2 * NN * 64 + (size_t)node * 64;
    const float* gv = Mo + (size_t)3 * NN * 64 + (size_t)node * 64;
    const float* gg = Mo + (size_t)4 * NN * 64 + (size_t)node * 64;

    float r0 = 0.f, r1 = 0.f, a0 = 0.f, a1 = 0.f;
#pragma unroll
    for (int h = 0; h < 2; h++) {
        int d = lane + h * 32;
        float tgg = 0.f, tg = 0.f;
#pragma unroll
        for (int e = 0; e < 64; e++) {
            float w = Ws[d][e];
            tgg += w * gg[e];
            tg += w * gv[e];
        }
        r0 += z[d] * tgg;
        r1 += sz[d] * tgg;
        a0 += zg[d] * tg;
        a1 += sz[d] * tg;
    }
#pragma unroll
    for (int o = 16; o; o >>= 1) {
        r0 += __shfl_xor_sync(0xFFFFFFFFu, r0, o);
        r1 += __shfl_xor_sync(0xFFFFFFFFu, r1, o);
        a0 += __shfl_xor_sync(0xFFFFFFFFu, a0, o);
        a1 += __shfl_xor_sync(0xFFFFFFFFu, a1, o);
    }
    if (lane == 0) {
        float b = bptr[0];
        ret[(size_t)node * 2 + 0] = r0 + b;
        ret[(size_t)node * 2 + 1] = r1 + b;
        ret_a[(size_t)node * 2 + 0] = a0 + b;
        ret_a[(size_t)node * 2 + 1] = a1 + b;
    }
}

// =====================================================================================
extern "C" void kernel_launch(void* const* d_in, const int* in_sizes, int n_in, void* d_out,
                              int out_size) {
    (void)in_sizes; (void)n_in; (void)out_size;

    const float* feat      = (const float*)d_in[0];
    const int*   adj_src   = (const int*)d_in[1];
    const int*   adj_dst   = (const int*)d_in[2];
    const float* adj_val   = (const float*)d_in[3];
    const int*   gdc_src   = (const int*)d_in[4];
    const int*   gdc_dst   = (const int*)d_in[5];
    const float* gdc_val   = (const float*)d_in[6];
    const int*   neigh_src = (const int*)d_in[7];
    const int*   neigh_dst = (const int*)d_in[8];
    const float* neigh_val = (const float*)d_in[9];
    const int*   diff_src  = (const int*)d_in[10];
    const int*   diff_dst  = (const int*)d_in[11];
    const float* diff_val  = (const float*)d_in[12];
    const int*   perm      = (const int*)d_in[13];
    const float* W_enc     = (const float*)d_in[14];
    const float* b_enc     = (const float*)d_in[15];
    const float* W_dec     = (const float*)d_in[16];
    const float* b_dec     = (const float*)d_in[17];
    const float* W1        = (const float*)d_in[18];
    const float* b1        = (const float*)d_in[19];
    const float* prelu_a   = (const float*)d_in[20];
    const float* W3        = (const float*)d_in[21];
    const float* b3        = (const float*)d_in[22];
    const float* W_disc    = (const float*)d_in[23];
    const float* b_disc    = (const float*)d_in[24];

    __half *Xhp, *MLPINHp, *W1Tp, *W3Tp;
    float *STAGEp, *Sp, *MLPOUTp, *DEGp;
    cudaGetSymbolAddress((void**)&Xhp, g_Xh);
    cudaGetSymbolAddress((void**)&MLPINHp, g_MLPINH);
    cudaGetSymbolAddress((void**)&W1Tp, g_W1T);
    cudaGetSymbolAddress((void**)&W3Tp, g_W3T);
    cudaGetSymbolAddress((void**)&STAGEp, g_STAGE);
    cudaGetSymbolAddress((void**)&Sp, g_S);
    cudaGetSymbolAddress((void**)&MLPOUTp, g_MLPOUT);
    cudaGetSymbolAddress((void**)&DEGp, g_DEG);

    float* out = (float*)d_out;
    float* emb = out;                       // [NN,256]
    float* ret = out + (size_t)NN * 256;    // [NN,2]
    float* ret_a = ret + (size_t)NN * 2;    // [NN,2]

    const int MLP_SMEM = (2 * 256 * 72 + 4 * 64 * 72) * 2;  // 110592 B
    static bool attr_set = false;
    if (!attr_set) {
        cudaFuncSetAttribute(mlp16, cudaFuncAttributeMaxDynamicSharedMemorySize, MLP_SMEM);
        attr_set = true;
    }

    const int MROWS = (NN + 127) / 128;                               // 391
    const unsigned dual_blocks = ((unsigned)EE * 4u + 255u) / 256u;   // 12500
    const int seg_blocks = ((EE / 2) * 4 + 255) / 256;                // 6250

    // zero accumulators
    cudaMemsetAsync(STAGEp, 0, (size_t)5 * NN * 64 * sizeof(float));
    cudaMemsetAsync(Sp, 0, (size_t)NN * 64 * sizeof(float));
    cudaMemsetAsync(DEGp, 0, (size_t)3 * NN * sizeof(float));

    // weight pre-transpose (parallel, independent)
    transpose_w<<<16, 512>>>(W1, W3, W1Tp, W3Tp);

    // Xh = half(feat @ W_enc + b_enc)  [NN,64]  (tf32)
    mma_gemm<2><<<dim3(1, MROWS), 256>>>(feat, W_enc, b_enc, nullptr, nullptr, Xhp, NN, 256, 64);

    // stage 1: h (stage0) + shuf_h (stage2) + adj degree; h_g (stage1)
    spmm64h_dual<<<dual_blocks, 256>>>(adj_src, adj_dst, adj_val, perm, Xhp,
                                       STAGEp + (size_t)0 * NN * 64,
                                       STAGEp + (size_t)2 * NN * 64, DEGp, EE);
    spmm64h2<<<seg_blocks, 256>>>(gdc_src, gdc_dst, gdc_val, Xhp, STAGEp + (size_t)1 * NN * 64,
                                  nullptr, EE);

    // relu stage 0..2 -> fp16 MLPINH slots 0..2 (slot0/1 double as stage-2 gather tables)
    {
        int n4 = 3 * NN * 16;
        relu_to_half<<<(n4 + 255) / 256, 256>>>((const float4*)STAGEp, MLPINHp, n4);
    }

    // stage 2 (fused): adj->S, neigh->stage3 (+degN), diff->stage4 (+degD)
    spmm_stage2_all<<<3 * seg_blocks, 256>>>(adj_src, adj_dst, adj_val, neigh_src, neigh_dst,
                                             neigh_val, diff_src, diff_dst, diff_val, MLPINHp,
                                             MLPINHp + (size_t)NN * 64, Sp,
                                             STAGEp + (size_t)3 * NN * 64,
                                             STAGEp + (size_t)4 * NN * 64, DEGp + NN,
                                             DEGp + 2 * NN, EE, seg_blocks);

    // emb = relu(S @ W_dec + deg_adj ⊗ b_dec)  (spmm linearity), tf32
    mma_gemm<1><<<dim3(4, MROWS), 256>>>(Sp, W_dec, b_dec, DEGp, emb, nullptr, NN, 64, 256);

    // sigmoid averages -> fp16 MLPINH slots 3,4
    {
        int n2 = 2 * NN * 16;
        sigavg_to_half<<<(n2 + 255) / 256, 256>>>((const float4*)(STAGEp + (size_t)3 * NN * 64),
                                                  MLPINHp + (size_t)3 * NN * 64, DEGp + NN,
                                                  DEGp + 2 * NN);
    }

    // fused batched MLP over all 5 fp16 inputs
    {
        int M = 5 * NN;
        mlp16<<<(M + 255) / 256, 512, MLP_SMEM>>>(MLPINHp, W1Tp, b1, prelu_a, W3Tp, b3, MLPOUTp,
                                                  M);
    }

    // discriminator heads
    disc_kernel<<<(NN + 3) / 4, 128>>>(MLPOUTp, W_disc, b_disc, ret, ret_a);
}

// round 13
// speedup vs baseline: 1.3658x; 1.0013x over previous
#include <cuda_runtime.h>
#include <cuda_fp16.h>
#include <math.h>

#define NN 50000
#define EE 800000

// ---------------- scratch (static device globals; no runtime alloc) ----------------
__device__ __half g_Xh[(size_t)NN * 64];           // feat@W_enc + b_enc (fp16, gather table)
__device__ float  g_STAGE[(size_t)5 * NN * 64];    // fp32 atomic staging: h,h_g,shuf_h,nsum,dsum
__device__ __half g_MLPINH[(size_t)5 * NN * 64];   // fp16 MLP inputs (slots 0/1 = gather tables)
__device__ float  g_S[(size_t)NN * 64];            // spmm(adj, relu_h)
__device__ float  g_MLPOUT[(size_t)5 * NN * 64];   // z, z_g, shuf_z, g, g_g
__device__ float  g_DEG[3 * NN];                   // [adj | neigh | diff]
__device__ __half g_W1T[512 * 64];                 // W1 transposed [n][k] fp16
__device__ __half g_W3T[64 * 512];                 // W3 transposed [n][k] fp16

// ---------------- mma helpers ----------------
__device__ __forceinline__ unsigned cvt_tf32(float x) {
    unsigned u;
    asm("cvt.rna.tf32.f32 %0, %1;" : "=r"(u) : "f"(x));
    return u;
}
__device__ __forceinline__ void mma8(float* c, const unsigned* a, const unsigned* b) {
    asm("mma.sync.aligned.m16n8k8.row.col.f32.tf32.tf32.f32 "
        "{%0,%1,%2,%3},{%4,%5,%6,%7},{%8,%9},{%0,%1,%2,%3};"
        : "+f"(c[0]), "+f"(c[1]), "+f"(c[2]), "+f"(c[3])
        : "r"(a[0]), "r"(a[1]), "r"(a[2]), "r"(a[3]), "r"(b[0]), "r"(b[1]));
}
__device__ __forceinline__ void mma16(float* c, const unsigned* a, const unsigned* b) {
    asm("mma.sync.aligned.m16n8k16.row.col.f32.f16.f16.f32 "
        "{%0,%1,%2,%3},{%4,%5,%6,%7},{%8,%9},{%0,%1,%2,%3};"
        : "+f"(c[0]), "+f"(c[1]), "+f"(c[2]), "+f"(c[3])
        : "r"(a[0]), "r"(a[1]), "r"(a[2]), "r"(a[3]), "r"(b[0]), "r"(b[1]));
}
// ldmatrix x4: loads 4 8x8 b16 tiles; lane l supplies row address.
__device__ __forceinline__ void ldm_x4(unsigned* r, unsigned saddr) {
    asm volatile("ldmatrix.sync.aligned.m8n8.x4.shared.b16 {%0,%1,%2,%3}, [%4];"
                 : "=r"(r[0]), "=r"(r[1]), "=r"(r[2]), "=r"(r[3])
                 : "r"(saddr));
}

#define CP16(sdst, gsrc) \
    asm volatile("cp.async.ca.shared.global [%0], [%1], 16;" ::"r"(sdst), "l"(gsrc))
#define CP_COMMIT() asm volatile("cp.async.commit_group;")
#define CP_WAIT0() asm volatile("cp.async.wait_group 0;" ::: "memory")

// ---------------- weight pre-transpose (fp32 -> fp16, [k][n] -> [n][k]) --------------
__global__ void transpose_w(const float* __restrict__ W1, const float* __restrict__ W3,
                            __half* __restrict__ W1T, __half* __restrict__ W3T) {
    int b = blockIdx.x, t = threadIdx.x;
    if (b < 8) {
        int n = b * 64 + (t >> 3);
        int k0 = (t & 7) * 8;
#pragma unroll
        for (int i = 0; i < 8; i++)
            W1T[n * 64 + k0 + i] = __float2half_rn(W1[(size_t)(k0 + i) * 512 + n]);
    } else {
        int n = (b - 8) * 8 + (t >> 6);
        int k0 = (t & 63) * 8;
#pragma unroll
        for (int i = 0; i < 8; i++)
            W3T[n * 512 + k0 + i] = __float2half_rn(W3[(size_t)(k0 + i) * 64 + n]);
    }
}

// ---------------- single-TF32 GEMM ----------------
// EPI 1: C = relu(acc + deg[m]*bias[n]) fp32; EPI 2: Ch = half(acc + bias[n]) fp16
template <int EPI>
__global__ __launch_bounds__(256) void mma_gemm(const float* __restrict__ A,
                                                const float* __restrict__ W,
                                                const float* __restrict__ bias,
                                                const float* __restrict__ deg,
                                                float* __restrict__ C, __half* __restrict__ Ch,
                                                int M, int K, int Nc) {
    __shared__ unsigned As[128][36];
    __shared__ unsigned Bs[32][72];

    const int tid = threadIdx.x, lane = tid & 31, wid = tid >> 5;
    const int bm = blockIdx.y * 128, bn0 = blockIdx.x * 64;
    const int m_base = (wid & 3) * 32, n_base = (wid >> 2) * 32;
    const int lr = lane >> 2, lk = lane & 3;

    float acc[2][4][4];
#pragma unroll
    for (int mi = 0; mi < 2; mi++)
#pragma unroll
        for (int ni = 0; ni < 4; ni++)
#pragma unroll
            for (int i = 0; i < 4; i++) acc[mi][ni][i] = 0.f;

    for (int k0 = 0; k0 < K; k0 += 32) {
#pragma unroll
        for (int p = 0; p < 4; p++) {
            int idx = tid + p * 256;
            int row = idx >> 3, q = idx & 7;
            float4 v = make_float4(0.f, 0.f, 0.f, 0.f);
            if (bm + row < M)
                v = *reinterpret_cast<const float4*>(A + (size_t)(bm + row) * K + k0 + q * 4);
            As[row][q * 4 + 0] = cvt_tf32(v.x);
            As[row][q * 4 + 1] = cvt_tf32(v.y);
            As[row][q * 4 + 2] = cvt_tf32(v.z);
            As[row][q * 4 + 3] = cvt_tf32(v.w);
        }
#pragma unroll
        for (int p = 0; p < 2; p++) {
            int idx = tid + p * 256;
            int kr = idx >> 4, q = idx & 15;
            float4 v = *reinterpret_cast<const float4*>(W + (size_t)(k0 + kr) * Nc + bn0 + q * 4);
            Bs[kr][q * 4 + 0] = cvt_tf32(v.x);
            Bs[kr][q * 4 + 1] = cvt_tf32(v.y);
            Bs[kr][q * 4 + 2] = cvt_tf32(v.z);
            Bs[kr][q * 4 + 3] = cvt_tf32(v.w);
        }
        __syncthreads();

#pragma unroll
        for (int kk = 0; kk < 4; kk++) {
            unsigned a[2][4], b[4][2];
#pragma unroll
            for (int mi = 0; mi < 2; mi++) {
                int r0 = m_base + mi * 16 + lr;
                a[mi][0] = As[r0][kk * 8 + lk];
                a[mi][1] = As[r0 + 8][kk * 8 + lk];
                a[mi][2] = As[r0][kk * 8 + lk + 4];
                a[mi][3] = As[r0 + 8][kk * 8 + lk + 4];
            }
#pragma unroll
            for (int ni = 0; ni < 4; ni++) {
                int cn = n_base + ni * 8 + lr;
                b[ni][0] = Bs[kk * 8 + lk][cn];
                b[ni][1] = Bs[kk * 8 + lk + 4][cn];
            }
#pragma unroll
            for (int mi = 0; mi < 2; mi++)
#pragma unroll
                for (int ni = 0; ni < 4; ni++) mma8(acc[mi][ni], a[mi], b[ni]);
        }
        __syncthreads();
    }

#pragma unroll
    for (int mi = 0; mi < 2; mi++)
#pragma unroll
        for (int ni = 0; ni < 4; ni++) {
#pragma unroll
            for (int hi = 0; hi < 2; hi++) {
                int row = m_base + mi * 16 + lr + hi * 8;
                int col = n_base + ni * 8 + 2 * lk;
                int gm = bm + row, gn = bn0 + col;
                if (gm < M) {
                    float v0 = acc[mi][ni][hi * 2 + 0];
                    float v1 = acc[mi][ni][hi * 2 + 1];
                    if (EPI == 1) {
                        float dg = deg[gm];
                        v0 = fmaxf(v0 + dg * bias[gn], 0.f);
                        v1 = fmaxf(v1 + dg * bias[gn + 1], 0.f);
                        C[(size_t)gm * Nc + gn] = v0;
                        C[(size_t)gm * Nc + gn + 1] = v1;
                    } else {
                        v0 += bias[gn];
                        v1 += bias[gn + 1];
                        *reinterpret_cast<__half2*>(Ch + (size_t)gm * Nc + gn) =
                            __floats2half2_rn(v0, v1);
                    }
                }
            }
        }
}

// ---------------- fused MLP (fp16 mma + ldmatrix, pre-transposed weights) ------------
// BM=256, 512 threads (16 warps: 8m x 2n). A/H fragments via ldmatrix.x4.
__global__ __launch_bounds__(512, 1) void mlp16(const __half* __restrict__ A,
                                                const __half* __restrict__ W1T,
                                                const float* __restrict__ b1,
                                                const float* __restrict__ aptr,
                                                const __half* __restrict__ W3T,
                                                const float* __restrict__ b3,
                                                float* __restrict__ C, int M) {
    extern __shared__ __half hsm[];
    __half(*As)[72] = (__half(*)[72])hsm;
    __half(*Hs)[72] = (__half(*)[72])(hsm + 256 * 72);
    const unsigned W1_OFF = 2 * 256 * 72;
    const unsigned W3_OFF = W1_OFF + 2 * 64 * 72;
    __half(*W1s)[64][72] = (__half(*)[64][72])(hsm + W1_OFF);
    __half(*W3s)[64][72] = (__half(*)[64][72])(hsm + W3_OFF);

    const int tid = threadIdx.x, lane = tid & 31, wid = tid >> 5;
    const int bm = blockIdx.x * 256;
    const int m_base = (wid & 7) * 32, n_base = (wid >> 3) * 32;
    const int g = lane >> 2, t = lane & 3;
    const float alpha = aptr[0];
    const unsigned sb = (unsigned)__cvta_generic_to_shared(hsm);

    // ldmatrix lane-address components: row = base + (lane&15), col-half = (lane>>4)*8
    const unsigned lrow = (unsigned)(lane & 15);
    const unsigned lcol8 = (unsigned)((lane >> 4) << 3);
    // byte addr of A-frag tile (mi, kk): sb + ((m_base+mi*16+lrow)*72 + kk*16 + lcol8)*2
    const unsigned aAddr0 = sb + ((m_base + lrow) * 72 + lcol8) * 2u;           // mi=0, kk=0
    const unsigned hAddr0 = sb + 256 * 72 * 2u + ((m_base + lrow) * 72 + lcol8) * 2u;
    const unsigned MI_STEP = 16 * 72 * 2u;   // +16 rows
    const unsigned KK_STEP = 16 * 2u;        // +16 halves

    auto issue = [&](int ch, int buf) {
        int n = tid >> 3, o = tid & 7;
        const __half* s1 = W1T + ((size_t)(ch * 64 + n)) * 64 + o * 8;
        unsigned d1 = sb + (W1_OFF + (unsigned)buf * 64 * 72 + n * 72 + o * 8) * 2u;
        CP16(d1, s1);
        const __half* s3 = W3T + (size_t)n * 512 + ch * 64 + o * 8;
        unsigned d3 = sb + (W3_OFF + (unsigned)buf * 64 * 72 + n * 72 + o * 8) * 2u;
        CP16(d3, s3);
        CP_COMMIT();
    };
    issue(0, 0);

    // A tile 256x64 fp16: straight uint4 copy
#pragma unroll
    for (int p = 0; p < 4; p++) {
        int idx = tid + p * 512;
        int row = idx >> 3, q = idx & 7;
        uint4 u = make_uint4(0u, 0u, 0u, 0u);
        if (bm + row < M)
            u = *reinterpret_cast<const uint4*>(A + (size_t)(bm + row) * 64 + q * 8);
        *reinterpret_cast<uint4*>(&As[row][q * 8]) = u;
    }

    float out_acc[2][4][4];
#pragma unroll
    for (int mi = 0; mi < 2; mi++)
#pragma unroll
        for (int ni = 0; ni < 4; ni++)
#pragma unroll
            for (int i = 0; i < 4; i++) out_acc[mi][ni][i] = 0.f;

    for (int ch = 0; ch < 8; ch++) {
        const int buf = ch & 1;
        CP_WAIT0();
        __syncthreads();
        if (ch < 7) issue(ch + 1, buf ^ 1);

        float h_acc[2][4][4];
#pragma unroll
        for (int mi = 0; mi < 2; mi++)
#pragma unroll
            for (int ni = 0; ni < 4; ni++)
#pragma unroll
                for (int i = 0; i < 4; i++) h_acc[mi][ni][i] = 0.f;

#pragma unroll
        for (int kk = 0; kk < 4; kk++) {
            unsigned a[2][4], b[4][2];
            ldm_x4(a[0], aAddr0 + kk * KK_STEP);
            ldm_x4(a[1], aAddr0 + MI_STEP + kk * KK_STEP);
#pragma unroll
            for (int ni = 0; ni < 4; ni++) {
                int cn = n_base + ni * 8 + g;
                b[ni][0] = *reinterpret_cast<const unsigned*>(&W1s[buf][cn][kk * 16 + 2 * t]);
                b[ni][1] = *reinterpret_cast<const unsigned*>(&W1s[buf][cn][kk * 16 + 2 * t + 8]);
            }
#pragma unroll
            for (int mi = 0; mi < 2; mi++)
#pragma unroll
                for (int ni = 0; ni < 4; ni++) mma16(h_acc[mi][ni], a[mi], b[ni]);
        }

#pragma unroll
        for (int mi = 0; mi < 2; mi++)
#pragma unroll
            for (int ni = 0; ni < 4; ni++) {
                int r0 = m_base + mi * 16 + g;
                int hc = n_base + ni * 8 + 2 * t;
                float bb0 = b1[ch * 64 + hc], bb1 = b1[ch * 64 + hc + 1];
                float v0 = h_acc[mi][ni][0] + bb0;
                float v1 = h_acc[mi][ni][1] + bb1;
                float v2 = h_acc[mi][ni][2] + bb0;
                float v3 = h_acc[mi][ni][3] + bb1;
                v0 = (v0 >= 0.f) ? v0 : alpha * v0;
                v1 = (v1 >= 0.f) ? v1 : alpha * v1;
                v2 = (v2 >= 0.f) ? v2 : alpha * v2;
                v3 = (v3 >= 0.f) ? v3 : alpha * v3;
                *reinterpret_cast<__half2*>(&Hs[r0][hc]) = __floats2half2_rn(v0, v1);
                *reinterpret_cast<__half2*>(&Hs[r0 + 8][hc]) = __floats2half2_rn(v2, v3);
            }
        __syncthreads();

#pragma unroll
        for (int kk = 0; kk < 4; kk++) {
            unsigned a[2][4], b[4][2];
            ldm_x4(a[0], hAddr0 + kk * KK_STEP);
            ldm_x4(a[1], hAddr0 + MI_STEP + kk * KK_STEP);
#pragma unroll
            for (int ni = 0; ni < 4; ni++) {
                int cn = n_base + ni * 8 + g;
                b[ni][0] = *reinterpret_cast<const unsigned*>(&W3s[buf][cn][kk * 16 + 2 * t]);
                b[ni][1] = *reinterpret_cast<const unsigned*>(&W3s[buf][cn][kk * 16 + 2 * t + 8]);
            }
#pragma unroll
            for (int mi = 0; mi < 2; mi++)
#pragma unroll
                for (int ni = 0; ni < 4; ni++) mma16(out_acc[mi][ni], a[mi], b[ni]);
        }
    }

#pragma unroll
    for (int mi = 0; mi < 2; mi++)
#pragma unroll
        for (int ni = 0; ni < 4; ni++)
#pragma unroll
            for (int i = 0; i < 4; i++) {
                int row = m_base + mi * 16 + g + ((i >= 2) ? 8 : 0);
                int col = n_base + ni * 8 + 2 * t + (i & 1);
                int gm = bm + row;
                if (gm < M) C[(size_t)gm * 64 + col] = out_acc[mi][ni][i] + b3[col];
            }
}

// ---------------- fp16-gather SpMM primitives ----------------
__device__ __forceinline__ void red4(float* p, float a, float b, float c, float d) {
    asm volatile("red.global.add.v4.f32 [%0], {%1,%2,%3,%4};" ::"l"(p), "f"(a), "f"(b), "f"(c),
                 "f"(d)
                 : "memory");
}
__device__ __forceinline__ void mulred16(const uint4& ra, const uint4& rb, float v, float* p) {
    const __half2* ha = reinterpret_cast<const __half2*>(&ra);
    const __half2* hb = reinterpret_cast<const __half2*>(&rb);
    float f[16];
#pragma unroll
    for (int i = 0; i < 4; i++) {
        float2 x = __half22float2(ha[i]);
        f[2 * i] = v * x.x;
        f[2 * i + 1] = v * x.y;
        float2 y = __half22float2(hb[i]);
        f[8 + 2 * i] = v * y.x;
        f[8 + 2 * i + 1] = v * y.y;
    }
#pragma unroll
    for (int i = 0; i < 4; i++)
        red4(p + 4 * i, f[4 * i], f[4 * i + 1], f[4 * i + 2], f[4 * i + 3]);
}

// spmm body: 2 edges per thread (q and q+E/2), 4 threads/edge (16 cols each).
__device__ __forceinline__ void spmm2_body(unsigned gid, const int* __restrict__ src,
                                           const int* __restrict__ dst,
                                           const float* __restrict__ val,
                                           const __half* __restrict__ X, float* __restrict__ out,
                                           float* __restrict__ deg, int E) {
    unsigned half_e = (unsigned)E >> 1;
    unsigned q = gid >> 2;
    if (q >= half_e) return;
    unsigned c = gid & 3;
    unsigned e1 = q + half_e;
    int s0 = src[q], d0 = dst[q];
    float v0 = val[q];
    int s1 = src[e1], d1 = dst[e1];
    float v1 = val[e1];
    const __half* g0 = X + (size_t)(unsigned)d0 * 64 + c * 16;
    const __half* g1 = X + (size_t)(unsigned)d1 * 64 + c * 16;
    uint4 ra0 = *reinterpret_cast<const uint4*>(g0);
    uint4 rb0 = *reinterpret_cast<const uint4*>(g0 + 8);
    uint4 ra1 = *reinterpret_cast<const uint4*>(g1);
    uint4 rb1 = *reinterpret_cast<const uint4*>(g1 + 8);
    mulred16(ra0, rb0, v0, out + (size_t)s0 * 64 + c * 16);
    mulred16(ra1, rb1, v1, out + (size_t)s1 * 64 + c * 16);
    if (deg != nullptr && c == 0) {
        atomicAdd(&deg[s0], v0);
        atomicAdd(&deg[s1], v1);
    }
}

__global__ __launch_bounds__(256) void spmm64h2(const int* __restrict__ src,
                                                const int* __restrict__ dst,
                                                const float* __restrict__ val,
                                                const __half* __restrict__ X,
                                                float* __restrict__ out,
                                                float* __restrict__ deg, int E) {
    unsigned gid = blockIdx.x * blockDim.x + threadIdx.x;
    spmm2_body(gid, src, dst, val, X, out, deg, E);
}

// stage 2 fused: seg 0 = adj->S, seg 1 = neigh->stage3 (+degN), seg 2 = diff->stage4 (+degD)
__global__ __launch_bounds__(256) void spmm_stage2_all(
    const int* __restrict__ sA, const int* __restrict__ dA, const float* __restrict__ vA,
    const int* __restrict__ sN, const int* __restrict__ dN, const float* __restrict__ vN,
    const int* __restrict__ sD, const int* __restrict__ dD, const float* __restrict__ vD,
    const __half* __restrict__ H0, const __half* __restrict__ H1, float* __restrict__ S,
    float* __restrict__ st3, float* __restrict__ st4, float* __restrict__ degN,
    float* __restrict__ degD, int E, int segBlocks) {
    int seg = blockIdx.x / segBlocks;
    int blk = blockIdx.x - seg * segBlocks;
    unsigned gid = (unsigned)blk * blockDim.x + threadIdx.x;
    if (seg == 0) {
        spmm2_body(gid, sA, dA, vA, H0, S, nullptr, E);
    } else if (seg == 1) {
        spmm2_body(gid, sN, dN, vN, H0, st3, degN, E);
    } else {
        spmm2_body(gid, sD, dD, vD, H1, st4, degD, E);
    }
}

// adj + shuffled-adj in one pass (shares index loads) + adj degree (1 edge/thread)
__global__ void spmm64h_dual(const int* __restrict__ src, const int* __restrict__ dst,
                             const float* __restrict__ val, const int* __restrict__ perm,
                             const __half* __restrict__ X, float* __restrict__ out0,
                             float* __restrict__ out1, float* __restrict__ deg, int E) {
    unsigned gid = blockIdx.x * blockDim.x + threadIdx.x;
    unsigned e = gid >> 2;
    if (e >= (unsigned)E) return;
    unsigned c = gid & 3;
    int s = src[e];
    int d = dst[e];
    float v = val[e];
    int pd = perm[d];
    const __half* g0 = X + (unsigned)d * 64 + c * 16;
    const __half* g1 = X + (unsigned)pd * 64 + c * 16;
    uint4 ra0 = *reinterpret_cast<const uint4*>(g0);
    uint4 rb0 = *reinterpret_cast<const uint4*>(g0 + 8);
    uint4 ra1 = *reinterpret_cast<const uint4*>(g1);
    uint4 rb1 = *reinterpret_cast<const uint4*>(g1 + 8);
    mulred16(ra0, rb0, v, out0 + (size_t)s * 64 + c * 16);
    mulred16(ra1, rb1, v, out1 + (size_t)s * 64 + c * 16);
    if (c == 0) atomicAdd(&deg[s], v);
}

// ---------------- relu(stage slots 0..2) -> fp16 MLPINH slots 0..2 ----------------
__global__ void relu_to_half(const float4* __restrict__ stage, __half* __restrict__ hout,
                             int n4) {
    int i = blockIdx.x * blockDim.x + threadIdx.x;
    if (i < n4) {
        float4 v = stage[i];
        __half2 a = __floats2half2_rn(fmaxf(v.x, 0.f), fmaxf(v.y, 0.f));
        __half2 b = __floats2half2_rn(fmaxf(v.z, 0.f), fmaxf(v.w, 0.f));
        uint2 u;
        u.x = *reinterpret_cast<unsigned*>(&a);
        u.y = *reinterpret_cast<unsigned*>(&b);
        *reinterpret_cast<uint2*>(hout + (size_t)i * 4) = u;
    }
}

// ---------------- sigmoid(stage slots 3,4 / max(deg,1)) -> fp16 MLPINH 3,4 -----------
__global__ void sigavg_to_half(const float4* __restrict__ stage, __half* __restrict__ hout,
                               const float* __restrict__ degN, const float* __restrict__ degD) {
    int i = blockIdx.x * blockDim.x + threadIdx.x;
    const int n4 = NN * 16;
    if (i < 2 * n4) {
        int j = i * 4;
        const float* deg = (i < n4) ? degN : degD;
        int node = ((i < n4) ? j : (j - NN * 64)) >> 6;
        float d = deg[node];
        d = (d > 1.f) ? d : 1.f;
        float4 v = stage[i];
        float s0 = 1.f / (1.f + expf(-v.x / d));
        float s1 = 1.f / (1.f + expf(-v.y / d));
        float s2 = 1.f / (1.f + expf(-v.z / d));
        float s3 = 1.f / (1.f + expf(-v.w / d));
        __half2 a = __floats2half2_rn(s0, s1);
        __half2 b = __floats2half2_rn(s2, s3);
        uint2 u;
        u.x = *reinterpret_cast<unsigned*>(&a);
        u.y = *reinterpret_cast<unsigned*>(&b);
        *reinterpret_cast<uint2*>(hout + (size_t)i * 4) = u;
    }
}

// ---------------- discriminator ----------------
__global__ void disc_kernel(const float* __restrict__ Mo, const float* __restrict__ W,
                            const float* __restrict__ bptr, float* __restrict__ ret,
                            float* __restrict__ ret_a) {
    __shared__ float Ws[64][65];
    int tid = threadIdx.x;
    for (int i = tid; i < 4096; i += 128) Ws[i >> 6][i & 63] = W[i];
    __syncthreads();

    int warp = tid >> 5, lane = tid & 31;
    int node = blockIdx.x * 4 + warp;
    if (node >= NN) return;

    const float* z = Mo + (size_t)0 * NN * 64 + (size_t)node * 64;
    const float* zg = Mo + (size_t)1 * NN * 64 + (size_t)node * 64;
    const float* sz = Mo + (size_t)2 * NN * 64 + (size_t)node * 64;
    const float* gv = Mo + (size_t)3 * NN * 64 + (size_t)node * 64;
    const float* gg = Mo + (size_t)4 * NN * 64 + (size_t)node * 64;

    float r0 = 0.f, r1 = 0.f, a0 = 0.f, a1 = 0.f;
#pragma unroll
    for (int h = 0; h < 2; h++) {
        int d = lane + h * 32;
        float tgg = 0.f, tg = 0.f;
#pragma unroll
        for (int e = 0; e < 64; e++) {
            float w = Ws[d][e];
            tgg += w * gg[e];
            tg += w * gv[e];
        }
        r0 += z[d] * tgg;
        r1 += sz[d] * tgg;
        a0 += zg[d] * tg;
        a1 += sz[d] * tg;
    }
#pragma unroll
    for (int o = 16; o; o >>= 1) {
        r0 += __shfl_xor_sync(0xFFFFFFFFu, r0, o);
        r1 += __shfl_xor_sync(0xFFFFFFFFu, r1, o);
        a0 += __shfl_xor_sync(0xFFFFFFFFu, a0, o);
        a1 += __shfl_xor_sync(0xFFFFFFFFu, a1, o);
    }
    if (lane == 0) {
        float b = bptr[0];
        ret[(size_t)node * 2 + 0] = r0 + b;
        ret[(size_t)node * 2 + 1] = r1 + b;
        ret_a[(size_t)node * 2 + 0] = a0 + b;
        ret_a[(size_t)node * 2 + 1] = a1 + b;
    }
}

// =====================================================================================
extern "C" void kernel_launch(void* const* d_in, const int* in_sizes, int n_in, void* d_out,
                              int out_size) {
    (void)in_sizes; (void)n_in; (void)out_size;

    const float* feat      = (const float*)d_in[0];
    const int*   adj_src   = (const int*)d_in[1];
    const int*   adj_dst   = (const int*)d_in[2];
    const float* adj_val   = (const float*)d_in[3];
    const int*   gdc_src   = (const int*)d_in[4];
    const int*   gdc_dst   = (const int*)d_in[5];
    const float* gdc_val   = (const float*)d_in[6];
    const int*   neigh_src = (const int*)d_in[7];
    const int*   neigh_dst = (const int*)d_in[8];
    const float* neigh_val = (const float*)d_in[9];
    const int*   diff_src  = (const int*)d_in[10];
    const int*   diff_dst  = (const int*)d_in[11];
    const float* diff_val  = (const float*)d_in[12];
    const int*   perm      = (const int*)d_in[13];
    const float* W_enc     = (const float*)d_in[14];
    const float* b_enc     = (const float*)d_in[15];
    const float* W_dec     = (const float*)d_in[16];
    const float* b_dec     = (const float*)d_in[17];
    const float* W1        = (const float*)d_in[18];
    const float* b1        = (const float*)d_in[19];
    const float* prelu_a   = (const float*)d_in[20];
    const float* W3        = (const float*)d_in[21];
    const float* b3        = (const float*)d_in[22];
    const float* W_disc    = (const float*)d_in[23];
    const float* b_disc    = (const float*)d_in[24];

    __half *Xhp, *MLPINHp, *W1Tp, *W3Tp;
    float *STAGEp, *Sp, *MLPOUTp, *DEGp;
    cudaGetSymbolAddress((void**)&Xhp, g_Xh);
    cudaGetSymbolAddress((void**)&MLPINHp, g_MLPINH);
    cudaGetSymbolAddress((void**)&W1Tp, g_W1T);
    cudaGetSymbolAddress((void**)&W3Tp, g_W3T);
    cudaGetSymbolAddress((void**)&STAGEp, g_STAGE);
    cudaGetSymbolAddress((void**)&Sp, g_S);
    cudaGetSymbolAddress((void**)&MLPOUTp, g_MLPOUT);
    cudaGetSymbolAddress((void**)&DEGp, g_DEG);

    float* out = (float*)d_out;
    float* emb = out;                       // [NN,256]
    float* ret = out + (size_t)NN * 256;    // [NN,2]
    float* ret_a = ret + (size_t)NN * 2;    // [NN,2]

    const int MLP_SMEM = (2 * 256 * 72 + 4 * 64 * 72) * 2;  // 110592 B
    static bool attr_set = false;
    if (!attr_set) {
        cudaFuncSetAttribute(mlp16, cudaFuncAttributeMaxDynamicSharedMemorySize, MLP_SMEM);
        attr_set = true;
    }

    const int MROWS = (NN + 127) / 128;                               // 391
    const unsigned dual_blocks = ((unsigned)EE * 4u + 255u) / 256u;   // 12500
    const int seg_blocks = ((EE / 2) * 4 + 255) / 256;                // 6250

    // zero accumulators
    cudaMemsetAsync(STAGEp, 0, (size_t)5 * NN * 64 * sizeof(float));
    cudaMemsetAsync(Sp, 0, (size_t)NN * 64 * sizeof(float));
    cudaMemsetAsync(DEGp, 0, (size_t)3 * NN * sizeof(float));

    // weight pre-transpose (parallel, independent)
    transpose_w<<<16, 512>>>(W1, W3, W1Tp, W3Tp);

    // Xh = half(feat @ W_enc + b_enc)  [NN,64]  (tf32)
    mma_gemm<2><<<dim3(1, MROWS), 256>>>(feat, W_enc, b_enc, nullptr, nullptr, Xhp, NN, 256, 64);

    // stage 1: h (stage0) + shuf_h (stage2) + adj degree; h_g (stage1)
    spmm64h_dual<<<dual_blocks, 256>>>(adj_src, adj_dst, adj_val, perm, Xhp,
                                       STAGEp + (size_t)0 * NN * 64,
                                       STAGEp + (size_t)2 * NN * 64, DEGp, EE);
    spmm64h2<<<seg_blocks, 256>>>(gdc_src, gdc_dst, gdc_val, Xhp, STAGEp + (size_t)1 * NN * 64,
                                  nullptr, EE);

    // relu stage 0..2 -> fp16 MLPINH slots 0..2 (slot0/1 double as stage-2 gather tables)
    {
        int n4 = 3 * NN * 16;
        relu_to_half<<<(n4 + 255) / 256, 256>>>((const float4*)STAGEp, MLPINHp, n4);
    }

    // stage 2 (fused): adj->S, neigh->stage3 (+degN), diff->stage4 (+degD)
    spmm_stage2_all<<<3 * seg_blocks, 256>>>(adj_src, adj_dst, adj_val, neigh_src, neigh_dst,
                                             neigh_val, diff_src, diff_dst, diff_val, MLPINHp,
                                             MLPINHp + (size_t)NN * 64, Sp,
                                             STAGEp + (size_t)3 * NN * 64,
                                             STAGEp + (size_t)4 * NN * 64, DEGp + NN,
                                             DEGp + 2 * NN, EE, seg_blocks);

    // emb = relu(S @ W_dec + deg_adj ⊗ b_dec)  (spmm linearity), tf32
    mma_gemm<1><<<dim3(4, MROWS), 256>>>(Sp, W_dec, b_dec, DEGp, emb, nullptr, NN, 64, 256);

    // sigmoid averages -> fp16 MLPINH slots 3,4
    {
        int n2 = 2 * NN * 16;
        sigavg_to_half<<<(n2 + 255) / 256, 256>>>((const float4*)(STAGEp + (size_t)3 * NN * 64),
                                                  MLPINHp + (size_t)3 * NN * 64, DEGp + NN,
                                                  DEGp + 2 * NN);
    }

    // fused batched MLP over all 5 fp16 inputs (ldmatrix + fp16 mma)
    {
        int M = 5 * NN;
        mlp16<<<(M + 255) / 256, 512, MLP_SMEM>>>(MLPINHp, W1Tp, b1, prelu_a, W3Tp, b3, MLPOUTp,
                                                  M);
    }

    // discriminator heads
    disc_kernel<<<(NN + 3) / 4, 128>>>(MLPOUTp, W_disc, b_disc, ret, ret_a);
}

// round 14
// speedup vs baseline: 1.4078x; 1.0307x over previous
#include <cuda_runtime.h>
#include <cuda_fp16.h>
#include <math.h>

#define NN 50000
#define EE 800000

// ---------------- scratch (static device globals; no runtime alloc) ----------------
__device__ __half g_Xh[(size_t)NN * 64];           // feat@W_enc + b_enc (fp16, gather table)
__device__ float  g_STAGE[(size_t)5 * NN * 64];    // fp32 atomic staging: h,h_g,shuf_h,nsum,dsum
__device__ __half g_MLPINH[(size_t)5 * NN * 64];   // fp16 MLP inputs (slots 0/1 = gather tables)
__device__ float  g_S[(size_t)NN * 64];            // spmm(adj, relu_h)
__device__ float  g_MLPOUT[(size_t)5 * NN * 64];   // z, z_g, shuf_z, g, g_g
__device__ float  g_DEG[3 * NN];                   // [adj | neigh | diff]
__device__ __half g_W1T[512 * 64];                 // W1 transposed [n][k] fp16
__device__ __half g_W3T[64 * 512];                 // W3 transposed [n][k] fp16

// ---------------- mma helpers ----------------
__device__ __forceinline__ unsigned cvt_tf32(float x) {
    unsigned u;
    asm("cvt.rna.tf32.f32 %0, %1;" : "=r"(u) : "f"(x));
    return u;
}
__device__ __forceinline__ void mma8(float* c, const unsigned* a, const unsigned* b) {
    asm("mma.sync.aligned.m16n8k8.row.col.f32.tf32.tf32.f32 "
        "{%0,%1,%2,%3},{%4,%5,%6,%7},{%8,%9},{%0,%1,%2,%3};"
        : "+f"(c[0]), "+f"(c[1]), "+f"(c[2]), "+f"(c[3])
        : "r"(a[0]), "r"(a[1]), "r"(a[2]), "r"(a[3]), "r"(b[0]), "r"(b[1]));
}
__device__ __forceinline__ void mma16(float* c, const unsigned* a, const unsigned* b) {
    asm("mma.sync.aligned.m16n8k16.row.col.f32.f16.f16.f32 "
        "{%0,%1,%2,%3},{%4,%5,%6,%7},{%8,%9},{%0,%1,%2,%3};"
        : "+f"(c[0]), "+f"(c[1]), "+f"(c[2]), "+f"(c[3])
        : "r"(a[0]), "r"(a[1]), "r"(a[2]), "r"(a[3]), "r"(b[0]), "r"(b[1]));
}
__device__ __forceinline__ void ldm_x4(unsigned* r, unsigned saddr) {
    asm volatile("ldmatrix.sync.aligned.m8n8.x4.shared.b16 {%0,%1,%2,%3}, [%4];"
                 : "=r"(r[0]), "=r"(r[1]), "=r"(r[2]), "=r"(r[3])
                 : "r"(saddr));
}

#define CP16(sdst, gsrc) \
    asm volatile("cp.async.ca.shared.global [%0], [%1], 16;" ::"r"(sdst), "l"(gsrc))
#define CP_COMMIT() asm volatile("cp.async.commit_group;")
#define CP_WAIT0() asm volatile("cp.async.wait_group 0;" ::: "memory")

// ---------------- weight pre-transpose (fp32 -> fp16, [k][n] -> [n][k]) --------------
__global__ void transpose_w(const float* __restrict__ W1, const float* __restrict__ W3,
                            __half* __restrict__ W1T, __half* __restrict__ W3T) {
    int b = blockIdx.x, t = threadIdx.x;
    if (b < 8) {
        int n = b * 64 + (t >> 3);
        int k0 = (t & 7) * 8;
#pragma unroll
        for (int i = 0; i < 8; i++)
            W1T[n * 64 + k0 + i] = __float2half_rn(W1[(size_t)(k0 + i) * 512 + n]);
    } else {
        int n = (b - 8) * 8 + (t >> 6);
        int k0 = (t & 63) * 8;
#pragma unroll
        for (int i = 0; i < 8; i++)
            W3T[n * 512 + k0 + i] = __float2half_rn(W3[(size_t)(k0 + i) * 64 + n]);
    }
}

// ---------------- single-TF32 GEMM ----------------
// EPI 1: C = relu(acc + deg[m]*bias[n]) fp32; EPI 2: Ch = half(acc + bias[n]) fp16
template <int EPI>
__global__ __launch_bounds__(256) void mma_gemm(const float* __restrict__ A,
                                                const float* __restrict__ W,
                                                const float* __restrict__ bias,
                                                const float* __restrict__ deg,
                                                float* __restrict__ C, __half* __restrict__ Ch,
                                                int M, int K, int Nc) {
    __shared__ unsigned As[128][36];
    __shared__ unsigned Bs[32][72];

    const int tid = threadIdx.x, lane = tid & 31, wid = tid >> 5;
    const int bm = blockIdx.y * 128, bn0 = blockIdx.x * 64;
    const int m_base = (wid & 3) * 32, n_base = (wid >> 2) * 32;
    const int lr = lane >> 2, lk = lane & 3;

    float acc[2][4][4];
#pragma unroll
    for (int mi = 0; mi < 2; mi++)
#pragma unroll
        for (int ni = 0; ni < 4; ni++)
#pragma unroll
            for (int i = 0; i < 4; i++) acc[mi][ni][i] = 0.f;

    for (int k0 = 0; k0 < K; k0 += 32) {
#pragma unroll
        for (int p = 0; p < 4; p++) {
            int idx = tid + p * 256;
            int row = idx >> 3, q = idx & 7;
            float4 v = make_float4(0.f, 0.f, 0.f, 0.f);
            if (bm + row < M)
                v = *reinterpret_cast<const float4*>(A + (size_t)(bm + row) * K + k0 + q * 4);
            As[row][q * 4 + 0] = cvt_tf32(v.x);
            As[row][q * 4 + 1] = cvt_tf32(v.y);
            As[row][q * 4 + 2] = cvt_tf32(v.z);
            As[row][q * 4 + 3] = cvt_tf32(v.w);
        }
#pragma unroll
        for (int p = 0; p < 2; p++) {
            int idx = tid + p * 256;
            int kr = idx >> 4, q = idx & 15;
            float4 v = *reinterpret_cast<const float4*>(W + (size_t)(k0 + kr) * Nc + bn0 + q * 4);
            Bs[kr][q * 4 + 0] = cvt_tf32(v.x);
            Bs[kr][q * 4 + 1] = cvt_tf32(v.y);
            Bs[kr][q * 4 + 2] = cvt_tf32(v.z);
            Bs[kr][q * 4 + 3] = cvt_tf32(v.w);
        }
        __syncthreads();

#pragma unroll
        for (int kk = 0; kk < 4; kk++) {
            unsigned a[2][4], b[4][2];
#pragma unroll
            for (int mi = 0; mi < 2; mi++) {
                int r0 = m_base + mi * 16 + lr;
                a[mi][0] = As[r0][kk * 8 + lk];
                a[mi][1] = As[r0 + 8][kk * 8 + lk];
                a[mi][2] = As[r0][kk * 8 + lk + 4];
                a[mi][3] = As[r0 + 8][kk * 8 + lk + 4];
            }
#pragma unroll
            for (int ni = 0; ni < 4; ni++) {
                int cn = n_base + ni * 8 + lr;
                b[ni][0] = Bs[kk * 8 + lk][cn];
                b[ni][1] = Bs[kk * 8 + lk + 4][cn];
            }
#pragma unroll
            for (int mi = 0; mi < 2; mi++)
#pragma unroll
                for (int ni = 0; ni < 4; ni++) mma8(acc[mi][ni], a[mi], b[ni]);
        }
        __syncthreads();
    }

#pragma unroll
    for (int mi = 0; mi < 2; mi++)
#pragma unroll
        for (int ni = 0; ni < 4; ni++) {
#pragma unroll
            for (int hi = 0; hi < 2; hi++) {
                int row = m_base + mi * 16 + lr + hi * 8;
                int col = n_base + ni * 8 + 2 * lk;
                int gm = bm + row, gn = bn0 + col;
                if (gm < M) {
                    float v0 = acc[mi][ni][hi * 2 + 0];
                    float v1 = acc[mi][ni][hi * 2 + 1];
                    if (EPI == 1) {
                        float dg = deg[gm];
                        v0 = fmaxf(v0 + dg * bias[gn], 0.f);
                        v1 = fmaxf(v1 + dg * bias[gn + 1], 0.f);
                        C[(size_t)gm * Nc + gn] = v0;
                        C[(size_t)gm * Nc + gn + 1] = v1;
                    } else {
                        v0 += bias[gn];
                        v1 += bias[gn + 1];
                        *reinterpret_cast<__half2*>(Ch + (size_t)gm * Nc + gn) =
                            __floats2half2_rn(v0, v1);
                    }
                }
            }
        }
}

// ---------------- fused MLP (fp16 mma + ldmatrix), BM=128, 2 CTAs/SM -----------------
// 256 threads (8 warps: 4m x 2n, warp tile 32x32). smem 73728 B -> 2 CTAs/SM.
__global__ __launch_bounds__(256, 2) void mlp16(const __half* __restrict__ A,
                                                const __half* __restrict__ W1T,
                                                const float* __restrict__ b1,
                                                const float* __restrict__ aptr,
                                                const __half* __restrict__ W3T,
                                                const float* __restrict__ b3,
                                                float* __restrict__ C, int M) {
    extern __shared__ __half hsm[];
    __half(*As)[72] = (__half(*)[72])hsm;                      // 128 x 72
    __half(*Hs)[72] = (__half(*)[72])(hsm + 128 * 72);         // 128 x 72
    const unsigned W1_OFF = 2 * 128 * 72;                      // halves
    const unsigned W3_OFF = W1_OFF + 2 * 64 * 72;
    __half(*W1s)[64][72] = (__half(*)[64][72])(hsm + W1_OFF);  // [2][64][72]
    __half(*W3s)[64][72] = (__half(*)[64][72])(hsm + W3_OFF);

    const int tid = threadIdx.x, lane = tid & 31, wid = tid >> 5;
    const int bm = blockIdx.x * 128;
    const int m_base = (wid & 3) * 32, n_base = (wid >> 2) * 32;
    const int g = lane >> 2, t = lane & 3;
    const float alpha = aptr[0];
    const unsigned sb = (unsigned)__cvta_generic_to_shared(hsm);

    const unsigned lrow = (unsigned)(lane & 15);
    const unsigned lcol8 = (unsigned)((lane >> 4) << 3);
    const unsigned aAddr0 = sb + ((m_base + lrow) * 72 + lcol8) * 2u;
    const unsigned hAddr0 = sb + 128 * 72 * 2u + ((m_base + lrow) * 72 + lcol8) * 2u;
    const unsigned MI_STEP = 16 * 72 * 2u;
    const unsigned KK_STEP = 16 * 2u;

    auto issue = [&](int ch, int buf) {
#pragma unroll
        for (int j = 0; j < 2; j++) {
            int idx = tid + j * 256;
            int n = idx >> 3, o = idx & 7;
            const __half* s1 = W1T + ((size_t)(ch * 64 + n)) * 64 + o * 8;
            unsigned d1 = sb + (W1_OFF + (unsigned)buf * 64 * 72 + n * 72 + o * 8) * 2u;
            CP16(d1, s1);
            const __half* s3 = W3T + (size_t)n * 512 + ch * 64 + o * 8;
            unsigned d3 = sb + (W3_OFF + (unsigned)buf * 64 * 72 + n * 72 + o * 8) * 2u;
            CP16(d3, s3);
        }
        CP_COMMIT();
    };
    issue(0, 0);

    // A tile 128x64 fp16: straight uint4 copy (1024 uint4, 256 thr x 4)
#pragma unroll
    for (int p = 0; p < 4; p++) {
        int idx = tid + p * 256;
        int row = idx >> 3, q = idx & 7;
        uint4 u = make_uint4(0u, 0u, 0u, 0u);
        if (bm + row < M)
            u = *reinterpret_cast<const uint4*>(A + (size_t)(bm + row) * 64 + q * 8);
        *reinterpret_cast<uint4*>(&As[row][q * 8]) = u;
    }

    float out_acc[2][4][4];
#pragma unroll
    for (int mi = 0; mi < 2; mi++)
#pragma unroll
        for (int ni = 0; ni < 4; ni++)
#pragma unroll
            for (int i = 0; i < 4; i++) out_acc[mi][ni][i] = 0.f;

    for (int ch = 0; ch < 8; ch++) {
        const int buf = ch & 1;
        CP_WAIT0();
        __syncthreads();
        if (ch < 7) issue(ch + 1, buf ^ 1);

        float h_acc[2][4][4];
#pragma unroll
        for (int mi = 0; mi < 2; mi++)
#pragma unroll
            for (int ni = 0; ni < 4; ni++)
#pragma unroll
                for (int i = 0; i < 4; i++) h_acc[mi][ni][i] = 0.f;

#pragma unroll
        for (int kk = 0; kk < 4; kk++) {
            unsigned a[2][4], b[4][2];
            ldm_x4(a[0], aAddr0 + kk * KK_STEP);
            ldm_x4(a[1], aAddr0 + MI_STEP + kk * KK_STEP);
#pragma unroll
            for (int ni = 0; ni < 4; ni++) {
                int cn = n_base + ni * 8 + g;
                b[ni][0] = *reinterpret_cast<const unsigned*>(&W1s[buf][cn][kk * 16 + 2 * t]);
                b[ni][1] = *reinterpret_cast<const unsigned*>(&W1s[buf][cn][kk * 16 + 2 * t + 8]);
            }
#pragma unroll
            for (int mi = 0; mi < 2; mi++)
#pragma unroll
                for (int ni = 0; ni < 4; ni++) mma16(h_acc[mi][ni], a[mi], b[ni]);
        }

#pragma unroll
        for (int mi = 0; mi < 2; mi++)
#pragma unroll
            for (int ni = 0; ni < 4; ni++) {
                int r0 = m_base + mi * 16 + g;
                int hc = n_base + ni * 8 + 2 * t;
                float bb0 = b1[ch * 64 + hc], bb1 = b1[ch * 64 + hc + 1];
                float v0 = h_acc[mi][ni][0] + bb0;
                float v1 = h_acc[mi][ni][1] + bb1;
                float v2 = h_acc[mi][ni][2] + bb0;
                float v3 = h_acc[mi][ni][3] + bb1;
                v0 = (v0 >= 0.f) ? v0 : alpha * v0;
                v1 = (v1 >= 0.f) ? v1 : alpha * v1;
                v2 = (v2 >= 0.f) ? v2 : alpha * v2;
                v3 = (v3 >= 0.f) ? v3 : alpha * v3;
                *reinterpret_cast<__half2*>(&Hs[r0][hc]) = __floats2half2_rn(v0, v1);
                *reinterpret_cast<__half2*>(&Hs[r0 + 8][hc]) = __floats2half2_rn(v2, v3);
            }
        __syncthreads();

#pragma unroll
        for (int kk = 0; kk < 4; kk++) {
            unsigned a[2][4], b[4][2];
            ldm_x4(a[0], hAddr0 + kk * KK_STEP);
            ldm_x4(a[1], hAddr0 + MI_STEP + kk * KK_STEP);
#pragma unroll
            for (int ni = 0; ni < 4; ni++) {
                int cn = n_base + ni * 8 + g;
                b[ni][0] = *reinterpret_cast<const unsigned*>(&W3s[buf][cn][kk * 16 + 2 * t]);
                b[ni][1] = *reinterpret_cast<const unsigned*>(&W3s[buf][cn][kk * 16 + 2 * t + 8]);
            }
#pragma unroll
            for (int mi = 0; mi < 2; mi++)
#pragma unroll
                for (int ni = 0; ni < 4; ni++) mma16(out_acc[mi][ni], a[mi], b[ni]);
        }
    }

#pragma unroll
    for (int mi = 0; mi < 2; mi++)
#pragma unroll
        for (int ni = 0; ni < 4; ni++)
#pragma unroll
            for (int i = 0; i < 4; i++) {
                int row = m_base + mi * 16 + g + ((i >= 2) ? 8 : 0);
                int col = n_base + ni * 8 + 2 * t + (i & 1);
                int gm = bm + row;
                if (gm < M) C[(size_t)gm * 64 + col] = out_acc[mi][ni][i] + b3[col];
            }
}

// ---------------- fp16-gather SpMM primitives ----------------
__device__ __forceinline__ void red4(float* p, float a, float b, float c, float d) {
    asm volatile("red.global.add.v4.f32 [%0], {%1,%2,%3,%4};" ::"l"(p), "f"(a), "f"(b), "f"(c),
                 "f"(d)
                 : "memory");
}
__device__ __forceinline__ void mulred16(const uint4& ra, const uint4& rb, float v, float* p) {
    const __half2* ha = reinterpret_cast<const __half2*>(&ra);
    const __half2* hb = reinterpret_cast<const __half2*>(&rb);
    float f[16];
#pragma unroll
    for (int i = 0; i < 4; i++) {
        float2 x = __half22float2(ha[i]);
        f[2 * i] = v * x.x;
        f[2 * i + 1] = v * x.y;
        float2 y = __half22float2(hb[i]);
        f[8 + 2 * i] = v * y.x;
        f[8 + 2 * i + 1] = v * y.y;
    }
#pragma unroll
    for (int i = 0; i < 4; i++)
        red4(p + 4 * i, f[4 * i], f[4 * i + 1], f[4 * i + 2], f[4 * i + 3]);
}

// spmm body: 2 edges per thread (q and q+E/2), 4 threads/edge (16 cols each).
__device__ __forceinline__ void spmm2_body(unsigned gid, const int* __restrict__ src,
                                           const int* __restrict__ dst,
                                           const float* __restrict__ val,
                                           const __half* __restrict__ X, float* __restrict__ out,
                                           float* __restrict__ deg, int E) {
    unsigned half_e = (unsigned)E >> 1;
    unsigned q = gid >> 2;
    if (q >= half_e) return;
    unsigned c = gid & 3;
    unsigned e1 = q + half_e;
    int s0 = src[q], d0 = dst[q];
    float v0 = val[q];
    int s1 = src[e1], d1 = dst[e1];
    float v1 = val[e1];
    const __half* g0 = X + (size_t)(unsigned)d0 * 64 + c * 16;
    const __half* g1 = X + (size_t)(unsigned)d1 * 64 + c * 16;
    uint4 ra0 = *reinterpret_cast<const uint4*>(g0);
    uint4 rb0 = *reinterpret_cast<const uint4*>(g0 + 8);
    uint4 ra1 = *reinterpret_cast<const uint4*>(g1);
    uint4 rb1 = *reinterpret_cast<const uint4*>(g1 + 8);
    mulred16(ra0, rb0, v0, out + (size_t)s0 * 64 + c * 16);
    mulred16(ra1, rb1, v1, out + (size_t)s1 * 64 + c * 16);
    if (deg != nullptr && c == 0) {
        atomicAdd(&deg[s0], v0);
        atomicAdd(&deg[s1], v1);
    }
}

__global__ __launch_bounds__(256) void spmm64h2(const int* __restrict__ src,
                                                const int* __restrict__ dst,
                                                const float* __restrict__ val,
                                                const __half* __restrict__ X,
                                                float* __restrict__ out,
                                                float* __restrict__ deg, int E) {
    unsigned gid = blockIdx.x * blockDim.x + threadIdx.x;
    spmm2_body(gid, src, dst, val, X, out, deg, E);
}

// stage 2 fused: seg 0 = adj->S, seg 1 = neigh->stage3 (+degN), seg 2 = diff->stage4 (+degD)
__global__ __launch_bounds__(256) void spmm_stage2_all(
    const int* __restrict__ sA, const int* __restrict__ dA, const float* __restrict__ vA,
    const int* __restrict__ sN, const int* __restrict__ dN, const float* __restrict__ vN,
    const int* __restrict__ sD, const int* __restrict__ dD, const float* __restrict__ vD,
    const __half* __restrict__ H0, const __half* __restrict__ H1, float* __restrict__ S,
    float* __restrict__ st3, float* __restrict__ st4, float* __restrict__ degN,
    float* __restrict__ degD, int E, int segBlocks) {
    int seg = blockIdx.x / segBlocks;
    int blk = blockIdx.x - seg * segBlocks;
    unsigned gid = (unsigned)blk * blockDim.x + threadIdx.x;
    if (seg == 0) {
        spmm2_body(gid, sA, dA, vA, H0, S, nullptr, E);
    } else if (seg == 1) {
        spmm2_body(gid, sN, dN, vN, H0, st3, degN, E);
    } else {
        spmm2_body(gid, sD, dD, vD, H1, st4, degD, E);
    }
}

// adj + shuffled-adj in one pass (shares index loads) + adj degree (1 edge/thread)
__global__ void spmm64h_dual(const int* __restrict__ src, const int* __restrict__ dst,
                             const float* __restrict__ val, const int* __restrict__ perm,
                             const __half* __restrict__ X, float* __restrict__ out0,
                             float* __restrict__ out1, float* __restrict__ deg, int E) {
    unsigned gid = blockIdx.x * blockDim.x + threadIdx.x;
    unsigned e = gid >> 2;
    if (e >= (unsigned)E) return;
    unsigned c = gid & 3;
    int s = src[e];
    int d = dst[e];
    float v = val[e];
    int pd = perm[d];
    const __half* g0 = X + (unsigned)d * 64 + c * 16;
    const __half* g1 = X + (unsigned)pd * 64 + c * 16;
    uint4 ra0 = *reinterpret_cast<const uint4*>(g0);
    uint4 rb0 = *reinterpret_cast<const uint4*>(g0 + 8);
    uint4 ra1 = *reinterpret_cast<const uint4*>(g1);
    uint4 rb1 = *reinterpret_cast<const uint4*>(g1 + 8);
    mulred16(ra0, rb0, v, out0 + (size_t)s * 64 + c * 16);
    mulred16(ra1, rb1, v, out1 + (size_t)s * 64 + c * 16);
    if (c == 0) atomicAdd(&deg[s], v);
}

// ---------------- relu(stage slots 0..2) -> fp16 MLPINH slots 0..2 ----------------
__global__ void relu_to_half(const float4* __restrict__ stage, __half* __restrict__ hout,
                             int n4) {
    int i = blockIdx.x * blockDim.x + threadIdx.x;
    if (i < n4) {
        float4 v = stage[i];
        __half2 a = __floats2half2_rn(fmaxf(v.x, 0.f), fmaxf(v.y, 0.f));
        __half2 b = __floats2half2_rn(fmaxf(v.z, 0.f), fmaxf(v.w, 0.f));
        uint2 u;
        u.x = *reinterpret_cast<unsigned*>(&a);
        u.y = *reinterpret_cast<unsigned*>(&b);
        *reinterpret_cast<uint2*>(hout + (size_t)i * 4) = u;
    }
}

// ---------------- sigmoid(stage slots 3,4 / max(deg,1)) -> fp16 MLPINH 3,4 -----------
__global__ void sigavg_to_half(const float4* __restrict__ stage, __half* __restrict__ hout,
                               const float* __restrict__ degN, const float* __restrict__ degD) {
    int i = blockIdx.x * blockDim.x + threadIdx.x;
    const int n4 = NN * 16;
    if (i < 2 * n4) {
        int j = i * 4;
        const float* deg = (i < n4) ? degN : degD;
        int node = ((i < n4) ? j : (j - NN * 64)) >> 6;
        float d = deg[node];
        d = (d > 1.f) ? d : 1.f;
        float4 v = stage[i];
        float s0 = 1.f / (1.f + expf(-v.x / d));
        float s1 = 1.f / (1.f + expf(-v.y / d));
        float s2 = 1.f / (1.f + expf(-v.z / d));
        float s3 = 1.f / (1.f + expf(-v.w / d));
        __half2 a = __floats2half2_rn(s0, s1);
        __half2 b = __floats2half2_rn(s2, s3);
        uint2 u;
        u.x = *reinterpret_cast<unsigned*>(&a);
        u.y = *reinterpret_cast<unsigned*>(&b);
        *reinterpret_cast<uint2*>(hout + (size_t)i * 4) = u;
    }
}

// ---------------- discriminator ----------------
__global__ void disc_kernel(const float* __restrict__ Mo, const float* __restrict__ W,
                            const float* __restrict__ bptr, float* __restrict__ ret,
                            float* __restrict__ ret_a) {
    __shared__ float Ws[64][65];
    int tid = threadIdx.x;
    for (int i = tid; i < 4096; i += 128) Ws[i >> 6][i & 63] = W[i];
    __syncthreads();

    int warp = tid >> 5, lane = tid & 31;
    int node = blockIdx.x * 4 + warp;
    if (node >= NN) return;

    const float* z = Mo + (size_t)0 * NN * 64 + (size_t)node * 64;
    const float* zg = Mo + (size_t)1 * NN * 64 + (size_t)node * 64;
    const float* sz = Mo + (size_t)2 * NN * 64 + (size_t)node * 64;
    const float* gv = Mo + (size_t)3 * NN * 64 + (size_t)node * 64;
    const float* gg = Mo + (size_t)4 * NN * 64 + (size_t)node * 64;

    float r0 = 0.f, r1 = 0.f, a0 = 0.f, a1 = 0.f;
#pragma unroll
    for (int h = 0; h < 2; h++) {
        int d = lane + h * 32;
        float tgg = 0.f, tg = 0.f;
#pragma unroll
        for (int e = 0; e < 64; e++) {
            float w = Ws[d][e];
            tgg += w * gg[e];
            tg += w * gv[e];
        }
        r0 += z[d] * tgg;
        r1 += sz[d] * tgg;
        a0 += zg[d] * tg;
        a1 += sz[d] * tg;
    }
#pragma unroll
    for (int o = 16; o; o >>= 1) {
        r0 += __shfl_xor_sync(0xFFFFFFFFu, r0, o);
        r1 += __shfl_xor_sync(0xFFFFFFFFu, r1, o);
        a0 += __shfl_xor_sync(0xFFFFFFFFu, a0, o);
        a1 += __shfl_xor_sync(0xFFFFFFFFu, a1, o);
    }
    if (lane == 0) {
        float b = bptr[0];
        ret[(size_t)node * 2 + 0] = r0 + b;
        ret[(size_t)node * 2 + 1] = r1 + b;
        ret_a[(size_t)node * 2 + 0] = a0 + b;
        ret_a[(size_t)node * 2 + 1] = a1 + b;
    }
}

// =====================================================================================
extern "C" void kernel_launch(void* const* d_in, const int* in_sizes, int n_in, void* d_out,
                              int out_size) {
    (void)in_sizes; (void)n_in; (void)out_size;

    const float* feat      = (const float*)d_in[0];
    const int*   adj_src   = (const int*)d_in[1];
    const int*   adj_dst   = (const int*)d_in[2];
    const float* adj_val   = (const float*)d_in[3];
    const int*   gdc_src   = (const int*)d_in[4];
    const int*   gdc_dst   = (const int*)d_in[5];
    const float* gdc_val   = (const float*)d_in[6];
    const int*   neigh_src = (const int*)d_in[7];
    const int*   neigh_dst = (const int*)d_in[8];
    const float* neigh_val = (const float*)d_in[9];
    const int*   diff_src  = (const int*)d_in[10];
    const int*   diff_dst  = (const int*)d_in[11];
    const float* diff_val  = (const float*)d_in[12];
    const int*   perm      = (const int*)d_in[13];
    const float* W_enc     = (const float*)d_in[14];
    const float* b_enc     = (const float*)d_in[15];
    const float* W_dec     = (const float*)d_in[16];
    const float* b_dec     = (const float*)d_in[17];
    const float* W1        = (const float*)d_in[18];
    const float* b1        = (const float*)d_in[19];
    const float* prelu_a   = (const float*)d_in[20];
    const float* W3        = (const float*)d_in[21];
    const float* b3        = (const float*)d_in[22];
    const float* W_disc    = (const float*)d_in[23];
    const float* b_disc    = (const float*)d_in[24];

    __half *Xhp, *MLPINHp, *W1Tp, *W3Tp;
    float *STAGEp, *Sp, *MLPOUTp, *DEGp;
    cudaGetSymbolAddress((void**)&Xhp, g_Xh);
    cudaGetSymbolAddress((void**)&MLPINHp, g_MLPINH);
    cudaGetSymbolAddress((void**)&W1Tp, g_W1T);
    cudaGetSymbolAddress((void**)&W3Tp, g_W3T);
    cudaGetSymbolAddress((void**)&STAGEp, g_STAGE);
    cudaGetSymbolAddress((void**)&Sp, g_S);
    cudaGetSymbolAddress((void**)&MLPOUTp, g_MLPOUT);
    cudaGetSymbolAddress((void**)&DEGp, g_DEG);

    float* out = (float*)d_out;
    float* emb = out;                       // [NN,256]
    float* ret = out + (size_t)NN * 256;    // [NN,2]
    float* ret_a = ret + (size_t)NN * 2;    // [NN,2]

    const int MLP_SMEM = (2 * 128 * 72 + 4 * 64 * 72) * 2;  // 73728 B -> 2 CTAs/SM
    static bool attr_set = false;
    if (!attr_set) {
        cudaFuncSetAttribute(mlp16, cudaFuncAttributeMaxDynamicSharedMemorySize, MLP_SMEM);
        attr_set = true;
    }

    const int MROWS = (NN + 127) / 128;                               // 391
    const unsigned dual_blocks = ((unsigned)EE * 4u + 255u) / 256u;   // 12500
    const int seg_blocks = ((EE / 2) * 4 + 255) / 256;                // 6250

    // zero accumulators
    cudaMemsetAsync(STAGEp, 0, (size_t)5 * NN * 64 * sizeof(float));
    cudaMemsetAsync(Sp, 0, (size_t)NN * 64 * sizeof(float));
    cudaMemsetAsync(DEGp, 0, (size_t)3 * NN * sizeof(float));

    // weight pre-transpose (parallel, independent)
    transpose_w<<<16, 512>>>(W1, W3, W1Tp, W3Tp);

    // Xh = half(feat @ W_enc + b_enc)  [NN,64]  (tf32)
    mma_gemm<2><<<dim3(1, MROWS), 256>>>(feat, W_enc, b_enc, nullptr, nullptr, Xhp, NN, 256, 64);

    // stage 1: h (stage0) + shuf_h (stage2) + adj degree; h_g (stage1)
    spmm64h_dual<<<dual_blocks, 256>>>(adj_src, adj_dst, adj_val, perm, Xhp,
                                       STAGEp + (size_t)0 * NN * 64,
                                       STAGEp + (size_t)2 * NN * 64, DEGp, EE);
    spmm64h2<<<seg_blocks, 256>>>(gdc_src, gdc_dst, gdc_val, Xhp, STAGEp + (size_t)1 * NN * 64,
                                  nullptr, EE);

    // relu stage 0..2 -> fp16 MLPINH slots 0..2 (slot0/1 double as stage-2 gather tables)
    {
        int n4 = 3 * NN * 16;
        relu_to_half<<<(n4 + 255) / 256, 256>>>((const float4*)STAGEp, MLPINHp, n4);
    }

    // stage 2 (fused): adj->S, neigh->stage3 (+degN), diff->stage4 (+degD)
    spmm_stage2_all<<<3 * seg_blocks, 256>>>(adj_src, adj_dst, adj_val, neigh_src, neigh_dst,
                                             neigh_val, diff_src, diff_dst, diff_val, MLPINHp,
                                             MLPINHp + (size_t)NN * 64, Sp,
                                             STAGEp + (size_t)3 * NN * 64,
                                             STAGEp + (size_t)4 * NN * 64, DEGp + NN,
                                             DEGp + 2 * NN, EE, seg_blocks);

    // emb = relu(S @ W_dec + deg_adj ⊗ b_dec)  (spmm linearity), tf32
    mma_gemm<1><<<dim3(4, MROWS), 256>>>(Sp, W_dec, b_dec, DEGp, emb, nullptr, NN, 64, 256);

    // sigmoid averages -> fp16 MLPINH slots 3,4
    {
        int n2 = 2 * NN * 16;
        sigavg_to_half<<<(n2 + 255) / 256, 256>>>((const float4*)(STAGEp + (size_t)3 * NN * 64),
                                                  MLPINHp + (size_t)3 * NN * 64, DEGp + NN,
                                                  DEGp + 2 * NN);
    }

    // fused batched MLP over all 5 fp16 inputs (BM=128, 2 CTAs/SM)
    {
        int M = 5 * NN;
        mlp16<<<(M + 127) / 128, 256, MLP_SMEM>>>(MLPINHp, W1Tp, b1, prelu_a, W3Tp, b3, MLPOUTp,
                                                  M);
    }

    // discriminator heads
    disc_kernel<<<(NN + 3) / 4, 128>>>(MLPOUTp, W_disc, b_disc, ret, ret_a);
}

// round 15
// speedup vs baseline: 1.4260x; 1.0129x over previous
#include <cuda_runtime.h>
#include <cuda_fp16.h>
#include <math.h>

#define NN 50000
#define EE 800000

// ---------------- scratch (static device globals; no runtime alloc) ----------------
__device__ __half g_Xh[(size_t)NN * 64];           // feat@W_enc + b_enc (fp16, gather table)
__device__ float  g_STAGE[(size_t)5 * NN * 64];    // fp32 atomic staging: h,h_g,shuf_h,nsum,dsum
__device__ __half g_MLPINH[(size_t)5 * NN * 64];   // fp16 MLP inputs (slots 0/1 = gather tables)
__device__ float  g_S[(size_t)NN * 64];            // spmm(adj, relu_h)
__device__ float  g_MLPOUT[(size_t)5 * NN * 64];   // z, z_g, shuf_z, g, g_g
__device__ float  g_DEG[3 * NN];                   // [adj | neigh | diff]
__device__ __half g_W1T[512 * 64];                 // W1 transposed [n][k] fp16
__device__ __half g_W3T[64 * 512];                 // W3 transposed [n][k] fp16

// ---------------- mma helpers ----------------
__device__ __forceinline__ unsigned cvt_tf32(float x) {
    unsigned u;
    asm("cvt.rna.tf32.f32 %0, %1;" : "=r"(u) : "f"(x));
    return u;
}
__device__ __forceinline__ void mma8(float* c, const unsigned* a, const unsigned* b) {
    asm("mma.sync.aligned.m16n8k8.row.col.f32.tf32.tf32.f32 "
        "{%0,%1,%2,%3},{%4,%5,%6,%7},{%8,%9},{%0,%1,%2,%3};"
        : "+f"(c[0]), "+f"(c[1]), "+f"(c[2]), "+f"(c[3])
        : "r"(a[0]), "r"(a[1]), "r"(a[2]), "r"(a[3]), "r"(b[0]), "r"(b[1]));
}
__device__ __forceinline__ void mma16(float* c, const unsigned* a, const unsigned* b) {
    asm("mma.sync.aligned.m16n8k16.row.col.f32.f16.f16.f32 "
        "{%0,%1,%2,%3},{%4,%5,%6,%7},{%8,%9},{%0,%1,%2,%3};"
        : "+f"(c[0]), "+f"(c[1]), "+f"(c[2]), "+f"(c[3])
        : "r"(a[0]), "r"(a[1]), "r"(a[2]), "r"(a[3]), "r"(b[0]), "r"(b[1]));
}
__device__ __forceinline__ void ldm_x4(unsigned* r, unsigned saddr) {
    asm volatile("ldmatrix.sync.aligned.m8n8.x4.shared.b16 {%0,%1,%2,%3}, [%4];"
                 : "=r"(r[0]), "=r"(r[1]), "=r"(r[2]), "=r"(r[3])
                 : "r"(saddr));
}

#define CP16(sdst, gsrc) \
    asm volatile("cp.async.ca.shared.global [%0], [%1], 16;" ::"r"(sdst), "l"(gsrc))
#define CP_COMMIT() asm volatile("cp.async.commit_group;")
#define CP_WAIT0() asm volatile("cp.async.wait_group 0;" ::: "memory")

// ---------------- weight pre-transpose (fp32 -> fp16, [k][n] -> [n][k]) --------------
__global__ void transpose_w(const float* __restrict__ W1, const float* __restrict__ W3,
                            __half* __restrict__ W1T, __half* __restrict__ W3T) {
    int b = blockIdx.x, t = threadIdx.x;
    if (b < 8) {
        int n = b * 64 + (t >> 3);
        int k0 = (t & 7) * 8;
#pragma unroll
        for (int i = 0; i < 8; i++)
            W1T[n * 64 + k0 + i] = __float2half_rn(W1[(size_t)(k0 + i) * 512 + n]);
    } else {
        int n = (b - 8) * 8 + (t >> 6);
        int k0 = (t & 63) * 8;
#pragma unroll
        for (int i = 0; i < 8; i++)
            W3T[n * 512 + k0 + i] = __float2half_rn(W3[(size_t)(k0 + i) * 64 + n]);
    }
}

// ---------------- single-TF32 GEMM ----------------
// EPI 1: C = relu(acc + deg[m]*bias[n]) fp32; EPI 2: Ch = half(acc + bias[n]) fp16
template <int EPI>
__global__ __launch_bounds__(256) void mma_gemm(const float* __restrict__ A,
                                                const float* __restrict__ W,
                                                const float* __restrict__ bias,
                                                const float* __restrict__ deg,
                                                float* __restrict__ C, __half* __restrict__ Ch,
                                                int M, int K, int Nc) {
    __shared__ unsigned As[128][36];
    __shared__ unsigned Bs[32][72];

    const int tid = threadIdx.x, lane = tid & 31, wid = tid >> 5;
    const int bm = blockIdx.y * 128, bn0 = blockIdx.x * 64;
    const int m_base = (wid & 3) * 32, n_base = (wid >> 2) * 32;
    const int lr = lane >> 2, lk = lane & 3;

    float acc[2][4][4];
#pragma unroll
    for (int mi = 0; mi < 2; mi++)
#pragma unroll
        for (int ni = 0; ni < 4; ni++)
#pragma unroll
            for (int i = 0; i < 4; i++) acc[mi][ni][i] = 0.f;

    for (int k0 = 0; k0 < K; k0 += 32) {
#pragma unroll
        for (int p = 0; p < 4; p++) {
            int idx = tid + p * 256;
            int row = idx >> 3, q = idx & 7;
            float4 v = make_float4(0.f, 0.f, 0.f, 0.f);
            if (bm + row < M)
                v = *reinterpret_cast<const float4*>(A + (size_t)(bm + row) * K + k0 + q * 4);
            As[row][q * 4 + 0] = cvt_tf32(v.x);
            As[row][q * 4 + 1] = cvt_tf32(v.y);
            As[row][q * 4 + 2] = cvt_tf32(v.z);
            As[row][q * 4 + 3] = cvt_tf32(v.w);
        }
#pragma unroll
        for (int p = 0; p < 2; p++) {
            int idx = tid + p * 256;
            int kr = idx >> 4, q = idx & 15;
            float4 v = *reinterpret_cast<const float4*>(W + (size_t)(k0 + kr) * Nc + bn0 + q * 4);
            Bs[kr][q * 4 + 0] = cvt_tf32(v.x);
            Bs[kr][q * 4 + 1] = cvt_tf32(v.y);
            Bs[kr][q * 4 + 2] = cvt_tf32(v.z);
            Bs[kr][q * 4 + 3] = cvt_tf32(v.w);
        }
        __syncthreads();

#pragma unroll
        for (int kk = 0; kk < 4; kk++) {
            unsigned a[2][4], b[4][2];
#pragma unroll
            for (int mi = 0; mi < 2; mi++) {
                int r0 = m_base + mi * 16 + lr;
                a[mi][0] = As[r0][kk * 8 + lk];
                a[mi][1] = As[r0 + 8][kk * 8 + lk];
                a[mi][2] = As[r0][kk * 8 + lk + 4];
                a[mi][3] = As[r0 + 8][kk * 8 + lk + 4];
            }
#pragma unroll
            for (int ni = 0; ni < 4; ni++) {
                int cn = n_base + ni * 8 + lr;
                b[ni][0] = Bs[kk * 8 + lk][cn];
                b[ni][1] = Bs[kk * 8 + lk + 4][cn];
            }
#pragma unroll
            for (int mi = 0; mi < 2; mi++)
#pragma unroll
                for (int ni = 0; ni < 4; ni++) mma8(acc[mi][ni], a[mi], b[ni]);
        }
        __syncthreads();
    }

#pragma unroll
    for (int mi = 0; mi < 2; mi++)
#pragma unroll
        for (int ni = 0; ni < 4; ni++) {
#pragma unroll
            for (int hi = 0; hi < 2; hi++) {
                int row = m_base + mi * 16 + lr + hi * 8;
                int col = n_base + ni * 8 + 2 * lk;
                int gm = bm + row, gn = bn0 + col;
                if (gm < M) {
                    float v0 = acc[mi][ni][hi * 2 + 0];
                    float v1 = acc[mi][ni][hi * 2 + 1];
                    if (EPI == 1) {
                        float dg = deg[gm];
                        v0 = fmaxf(v0 + dg * bias[gn], 0.f);
                        v1 = fmaxf(v1 + dg * bias[gn + 1], 0.f);
                        C[(size_t)gm * Nc + gn] = v0;
                        C[(size_t)gm * Nc + gn + 1] = v1;
                    } else {
                        v0 += bias[gn];
                        v1 += bias[gn + 1];
                        *reinterpret_cast<__half2*>(Ch + (size_t)gm * Nc + gn) =
                            __floats2half2_rn(v0, v1);
                    }
                }
            }
        }
}

// ---------------- fused MLP v3: register-resident hidden (C->A frag reuse) -----------
// BM=128, 256 threads (8 warps, each warp: 16 rows x ALL 64 hidden/out cols).
// Stage-1 C frags are bias+prelu'd in registers and reused directly as stage-2 A frags.
// No Hs smem, 1 barrier per chunk. smem = As + 2x(W1,W3) chunk buffers = 55296 B.
__global__ __launch_bounds__(256, 2) void mlp16(const __half* __restrict__ A,
                                                const __half* __restrict__ W1T,
                                                const float* __restrict__ b1,
                                                const float* __restrict__ aptr,
                                                const __half* __restrict__ W3T,
                                                const float* __restrict__ b3,
                                                float* __restrict__ C, int M) {
    extern __shared__ __half hsm[];
    __half(*As)[72] = (__half(*)[72])hsm;                      // 128 x 72
    const unsigned W1_OFF = 128 * 72;                          // halves
    const unsigned W3_OFF = W1_OFF + 2 * 64 * 72;
    __half(*W1s)[64][72] = (__half(*)[64][72])(hsm + W1_OFF);  // [2][64][72]
    __half(*W3s)[64][72] = (__half(*)[64][72])(hsm + W3_OFF);

    const int tid = threadIdx.x, lane = tid & 31, wid = tid >> 5;
    const int bm = blockIdx.x * 128;
    const int m_base = wid * 16;               // each warp owns 16 rows, all 64 cols
    const int g = lane >> 2, t = lane & 3;
    const float alpha = aptr[0];
    const unsigned sb = (unsigned)__cvta_generic_to_shared(hsm);

    const unsigned lrow = (unsigned)(lane & 15);
    const unsigned lcol8 = (unsigned)((lane >> 4) << 3);
    const unsigned aAddr0 = sb + ((m_base + lrow) * 72 + lcol8) * 2u;
    const unsigned KK_STEP = 16 * 2u;          // +16 halves per k-block

    auto issue = [&](int ch, int buf) {
#pragma unroll
        for (int j = 0; j < 2; j++) {
            int idx = tid + j * 256;
            int n = idx >> 3, o = idx & 7;
            const __half* s1 = W1T + ((size_t)(ch * 64 + n)) * 64 + o * 8;
            unsigned d1 = sb + (W1_OFF + (unsigned)buf * 64 * 72 + n * 72 + o * 8) * 2u;
            CP16(d1, s1);
            const __half* s3 = W3T + (size_t)n * 512 + ch * 64 + o * 8;
            unsigned d3 = sb + (W3_OFF + (unsigned)buf * 64 * 72 + n * 72 + o * 8) * 2u;
            CP16(d3, s3);
        }
        CP_COMMIT();
    };
    issue(0, 0);

    // A tile 128x64 fp16: straight uint4 copy
#pragma unroll
    for (int p = 0; p < 4; p++) {
        int idx = tid + p * 256;
        int row = idx >> 3, q = idx & 7;
        uint4 u = make_uint4(0u, 0u, 0u, 0u);
        if (bm + row < M)
            u = *reinterpret_cast<const uint4*>(A + (size_t)(bm + row) * 64 + q * 8);
        *reinterpret_cast<uint4*>(&As[row][q * 8]) = u;
    }

    float out_acc[8][4];
#pragma unroll
    for (int ni = 0; ni < 8; ni++)
#pragma unroll
        for (int i = 0; i < 4; i++) out_acc[ni][i] = 0.f;

    for (int ch = 0; ch < 8; ch++) {
        const int buf = ch & 1;
        CP_WAIT0();
        __syncthreads();  // weights(ch) visible (and As on ch==0)
        if (ch < 7) issue(ch + 1, buf ^ 1);

        // ---- stage 1: H[16 x 64] = A[16 x 64] @ W1chunk ----
        float h_acc[8][4];
#pragma unroll
        for (int ni = 0; ni < 8; ni++)
#pragma unroll
            for (int i = 0; i < 4; i++) h_acc[ni][i] = 0.f;

#pragma unroll
        for (int kb = 0; kb < 4; kb++) {
            unsigned a[4];
            ldm_x4(a, aAddr0 + kb * KK_STEP);
#pragma unroll
            for (int ni = 0; ni < 8; ni++) {
                unsigned b[2];
                int cn = ni * 8 + g;
                b[0] = *reinterpret_cast<const unsigned*>(&W1s[buf][cn][kb * 16 + 2 * t]);
                b[1] = *reinterpret_cast<const unsigned*>(&W1s[buf][cn][kb * 16 + 2 * t + 8]);
                mma16(h_acc[ni], a, b);
            }
        }

        // ---- bias + prelu in registers, pack as stage-2 A fragments ----
        unsigned hlo[8], hhi[8];  // hlo[ni]=(row g, cols ni*8+2t..+1), hhi: row g+8
#pragma unroll
        for (int ni = 0; ni < 8; ni++) {
            int hc = ni * 8 + 2 * t;
            float bb0 = b1[ch * 64 + hc], bb1 = b1[ch * 64 + hc + 1];
            float v0 = h_acc[ni][0] + bb0;
            float v1 = h_acc[ni][1] + bb1;
            float v2 = h_acc[ni][2] + bb0;
            float v3 = h_acc[ni][3] + bb1;
            v0 = (v0 >= 0.f) ? v0 : alpha * v0;
            v1 = (v1 >= 0.f) ? v1 : alpha * v1;
            v2 = (v2 >= 0.f) ? v2 : alpha * v2;
            v3 = (v3 >= 0.f) ? v3 : alpha * v3;
            __half2 lo = __floats2half2_rn(v0, v1);
            __half2 hi = __floats2half2_rn(v2, v3);
            hlo[ni] = *reinterpret_cast<unsigned*>(&lo);
            hhi[ni] = *reinterpret_cast<unsigned*>(&hi);
        }

        // ---- stage 2: out += H @ W3chunk (A frags = packed stage-1 C frags) ----
#pragma unroll
        for (int kb = 0; kb < 4; kb++) {
            unsigned a[4] = {hlo[2 * kb], hhi[2 * kb], hlo[2 * kb + 1], hhi[2 * kb + 1]};
#pragma unroll
            for (int ni = 0; ni < 8; ni++) {
                unsigned b[2];
                int cn = ni * 8 + g;
                b[0] = *reinterpret_cast<const unsigned*>(&W3s[buf][cn][kb * 16 + 2 * t]);
                b[1] = *reinterpret_cast<const unsigned*>(&W3s[buf][cn][kb * 16 + 2 * t + 8]);
                mma16(out_acc[ni], a, b);
            }
        }
    }

    // epilogue: out_acc[ni] -> C rows (g, g+8), cols ni*8+2t..+1
#pragma unroll
    for (int ni = 0; ni < 8; ni++) {
        int col = ni * 8 + 2 * t;
        int gm0 = bm + m_base + g;
        int gm1 = gm0 + 8;
        if (gm0 < M) {
            float2 v = make_float2(out_acc[ni][0] + b3[col], out_acc[ni][1] + b3[col + 1]);
            *reinterpret_cast<float2*>(C + (size_t)gm0 * 64 + col) = v;
        }
        if (gm1 < M) {
            float2 v = make_float2(out_acc[ni][2] + b3[col], out_acc[ni][3] + b3[col + 1]);
            *reinterpret_cast<float2*>(C + (size_t)gm1 * 64 + col) = v;
        }
    }
}

// ---------------- fp16-gather SpMM primitives ----------------
__device__ __forceinline__ void red4(float* p, float a, float b, float c, float d) {
    asm volatile("red.global.add.v4.f32 [%0], {%1,%2,%3,%4};" ::"l"(p), "f"(a), "f"(b), "f"(c),
                 "f"(d)
                 : "memory");
}
__device__ __forceinline__ void mulred16(const uint4& ra, const uint4& rb, float v, float* p) {
    const __half2* ha = reinterpret_cast<const __half2*>(&ra);
    const __half2* hb = reinterpret_cast<const __half2*>(&rb);
    float f[16];
#pragma unroll
    for (int i = 0; i < 4; i++) {
        float2 x = __half22float2(ha[i]);
        f[2 * i] = v * x.x;
        f[2 * i + 1] = v * x.y;
        float2 y = __half22float2(hb[i]);
        f[8 + 2 * i] = v * y.x;
        f[8 + 2 * i + 1] = v * y.y;
    }
#pragma unroll
    for (int i = 0; i < 4; i++)
        red4(p + 4 * i, f[4 * i], f[4 * i + 1], f[4 * i + 2], f[4 * i + 3]);
}

// spmm body: 2 edges per thread (q and q+E/2), 4 threads/edge (16 cols each).
__device__ __forceinline__ void spmm2_body(unsigned gid, const int* __restrict__ src,
                                           const int* __restrict__ dst,
                                           const float* __restrict__ val,
                                           const __half* __restrict__ X, float* __restrict__ out,
                                           float* __restrict__ deg, int E) {
    unsigned half_e = (unsigned)E >> 1;
    unsigned q = gid >> 2;
    if (q >= half_e) return;
    unsigned c = gid & 3;
    unsigned e1 = q + half_e;
    int s0 = src[q], d0 = dst[q];
    float v0 = val[q];
    int s1 = src[e1], d1 = dst[e1];
    float v1 = val[e1];
    const __half* g0 = X + (size_t)(unsigned)d0 * 64 + c * 16;
    const __half* g1 = X + (size_t)(unsigned)d1 * 64 + c * 16;
    uint4 ra0 = *reinterpret_cast<const uint4*>(g0);
    uint4 rb0 = *reinterpret_cast<const uint4*>(g0 + 8);
    uint4 ra1 = *reinterpret_cast<const uint4*>(g1);
    uint4 rb1 = *reinterpret_cast<const uint4*>(g1 + 8);
    mulred16(ra0, rb0, v0, out + (size_t)s0 * 64 + c * 16);
    mulred16(ra1, rb1, v1, out + (size_t)s1 * 64 + c * 16);
    if (deg != nullptr && c == 0) {
        atomicAdd(&deg[s0], v0);
        atomicAdd(&deg[s1], v1);
    }
}

__global__ __launch_bounds__(256) void spmm64h2(const int* __restrict__ src,
                                                const int* __restrict__ dst,
                                                const float* __restrict__ val,
                                                const __half* __restrict__ X,
                                                float* __restrict__ out,
                                                float* __restrict__ deg, int E) {
    unsigned gid = blockIdx.x * blockDim.x + threadIdx.x;
    spmm2_body(gid, src, dst, val, X, out, deg, E);
}

// stage 2 fused: seg 0 = adj->S, seg 1 = neigh->stage3 (+degN), seg 2 = diff->stage4 (+degD)
__global__ __launch_bounds__(256) void spmm_stage2_all(
    const int* __restrict__ sA, const int* __restrict__ dA, const float* __restrict__ vA,
    const int* __restrict__ sN, const int* __restrict__ dN, const float* __restrict__ vN,
    const int* __restrict__ sD, const int* __restrict__ dD, const float* __restrict__ vD,
    const __half* __restrict__ H0, const __half* __restrict__ H1, float* __restrict__ S,
    float* __restrict__ st3, float* __restrict__ st4, float* __restrict__ degN,
    float* __restrict__ degD, int E, int segBlocks) {
    int seg = blockIdx.x / segBlocks;
    int blk = blockIdx.x - seg * segBlocks;
    unsigned gid = (unsigned)blk * blockDim.x + threadIdx.x;
    if (seg == 0) {
        spmm2_body(gid, sA, dA, vA, H0, S, nullptr, E);
    } else if (seg == 1) {
        spmm2_body(gid, sN, dN, vN, H0, st3, degN, E);
    } else {
        spmm2_body(gid, sD, dD, vD, H1, st4, degD, E);
    }
}

// adj + shuffled-adj in one pass (shares index loads) + adj degree (1 edge/thread)
__global__ void spmm64h_dual(const int* __restrict__ src, const int* __restrict__ dst,
                             const float* __restrict__ val, const int* __restrict__ perm,
                             const __half* __restrict__ X, float* __restrict__ out0,
                             float* __restrict__ out1, float* __restrict__ deg, int E) {
    unsigned gid = blockIdx.x * blockDim.x + threadIdx.x;
    unsigned e = gid >> 2;
    if (e >= (unsigned)E) return;
    unsigned c = gid & 3;
    int s = src[e];
    int d = dst[e];
    float v = val[e];
    int pd = perm[d];
    const __half* g0 = X + (unsigned)d * 64 + c * 16;
    const __half* g1 = X + (unsigned)pd * 64 + c * 16;
    uint4 ra0 = *reinterpret_cast<const uint4*>(g0);
    uint4 rb0 = *reinterpret_cast<const uint4*>(g0 + 8);
    uint4 ra1 = *reinterpret_cast<const uint4*>(g1);
    uint4 rb1 = *reinterpret_cast<const uint4*>(g1 + 8);
    mulred16(ra0, rb0, v, out0 + (size_t)s * 64 + c * 16);
    mulred16(ra1, rb1, v, out1 + (size_t)s * 64 + c * 16);
    if (c == 0) atomicAdd(&deg[s], v);
}

// ---------------- relu(stage slots 0..2) -> fp16 MLPINH slots 0..2 ----------------
__global__ void relu_to_half(const float4* __restrict__ stage, __half* __restrict__ hout,
                             int n4) {
    int i = blockIdx.x * blockDim.x + threadIdx.x;
    if (i < n4) {
        float4 v = stage[i];
        __half2 a = __floats2half2_rn(fmaxf(v.x, 0.f), fmaxf(v.y, 0.f));
        __half2 b = __floats2half2_rn(fmaxf(v.z, 0.f), fmaxf(v.w, 0.f));
        uint2 u;
        u.x = *reinterpret_cast<unsigned*>(&a);
        u.y = *reinterpret_cast<unsigned*>(&b);
        *reinterpret_cast<uint2*>(hout + (size_t)i * 4) = u;
    }
}

// ---------------- sigmoid(stage slots 3,4 / max(deg,1)) -> fp16 MLPINH 3,4 -----------
__global__ void sigavg_to_half(const float4* __restrict__ stage, __half* __restrict__ hout,
                               const float* __restrict__ degN, const float* __restrict__ degD) {
    int i = blockIdx.x * blockDim.x + threadIdx.x;
    const int n4 = NN * 16;
    if (i < 2 * n4) {
        int j = i * 4;
        const float* deg = (i < n4) ? degN : degD;
        int node = ((i < n4) ? j : (j - NN * 64)) >> 6;
        float d = deg[node];
        d = (d > 1.f) ? d : 1.f;
        float4 v = stage[i];
        float s0 = 1.f / (1.f + expf(-v.x / d));
        float s1 = 1.f / (1.f + expf(-v.y / d));
        float s2 = 1.f / (1.f + expf(-v.z / d));
        float s3 = 1.f / (1.f + expf(-v.w / d));
        __half2 a = __floats2half2_rn(s0, s1);
        __half2 b = __floats2half2_rn(s2, s3);
        uint2 u;
        u.x = *reinterpret_cast<unsigned*>(&a);
        u.y = *reinterpret_cast<unsigned*>(&b);
        *reinterpret_cast<uint2*>(hout + (size_t)i * 4) = u;
    }
}

// ---------------- discriminator ----------------
__global__ void disc_kernel(const float* __restrict__ Mo, const float* __restrict__ W,
                            const float* __restrict__ bptr, float* __restrict__ ret,
                            float* __restrict__ ret_a) {
    __shared__ float Ws[64][65];
    int tid = threadIdx.x;
    for (int i = tid; i < 4096; i += 128) Ws[i >> 6][i & 63] = W[i];
    __syncthreads();

    int warp = tid >> 5, lane = tid & 31;
    int node = blockIdx.x * 4 + warp;
    if (node >= NN) return;

    const float* z = Mo + (size_t)0 * NN * 64 + (size_t)node * 64;
    const float* zg = Mo + (size_t)1 * NN * 64 + (size_t)node * 64;
    const float* sz = Mo + (size_t)2 * NN * 64 + (size_t)node * 64;
    const float* gv = Mo + (size_t)3 * NN * 64 + (size_t)node * 64;
    const float* gg = Mo + (size_t)4 * NN * 64 + (size_t)node * 64;

    float r0 = 0.f, r1 = 0.f, a0 = 0.f, a1 = 0.f;
#pragma unroll
    for (int h = 0; h < 2; h++) {
        int d = lane + h * 32;
        float tgg = 0.f, tg = 0.f;
#pragma unroll
        for (int e = 0; e < 64; e++) {
            float w = Ws[d][e];
            tgg += w * gg[e];
            tg += w * gv[e];
        }
        r0 += z[d] * tgg;
        r1 += sz[d] * tgg;
        a0 += zg[d] * tg;
        a1 += sz[d] * tg;
    }
#pragma unroll
    for (int o = 16; o; o >>= 1) {
        r0 += __shfl_xor_sync(0xFFFFFFFFu, r0, o);
        r1 += __shfl_xor_sync(0xFFFFFFFFu, r1, o);
        a0 += __shfl_xor_sync(0xFFFFFFFFu, a0, o);
        a1 += __shfl_xor_sync(0xFFFFFFFFu, a1, o);
    }
    if (lane == 0) {
        float b = bptr[0];
        ret[(size_t)node * 2 + 0] = r0 + b;
        ret[(size_t)node * 2 + 1] = r1 + b;
        ret_a[(size_t)node * 2 + 0] = a0 + b;
        ret_a[(size_t)node * 2 + 1] = a1 + b;
    }
}

// =====================================================================================
extern "C" void kernel_launch(void* const* d_in, const int* in_sizes, int n_in, void* d_out,
                              int out_size) {
    (void)in_sizes; (void)n_in; (void)out_size;

    const float* feat      = (const float*)d_in[0];
    const int*   adj_src   = (const int*)d_in[1];
    const int*   adj_dst   = (const int*)d_in[2];
    const float* adj_val   = (const float*)d_in[3];
    const int*   gdc_src   = (const int*)d_in[4];
    const int*   gdc_dst   = (const int*)d_in[5];
    const float* gdc_val   = (const float*)d_in[6];
    const int*   neigh_src = (const int*)d_in[7];
    const int*   neigh_dst = (const int*)d_in[8];
    const float* neigh_val = (const float*)d_in[9];
    const int*   diff_src  = (const int*)d_in[10];
    const int*   diff_dst  = (const int*)d_in[11];
    const float* diff_val  = (const float*)d_in[12];
    const int*   perm      = (const int*)d_in[13];
    const float* W_enc     = (const float*)d_in[14];
    const float* b_enc     = (const float*)d_in[15];
    const float* W_dec     = (const float*)d_in[16];
    const float* b_dec     = (const float*)d_in[17];
    const float* W1        = (const float*)d_in[18];
    const float* b1        = (const float*)d_in[19];
    const float* prelu_a   = (const float*)d_in[20];
    const float* W3        = (const float*)d_in[21];
    const float* b3        = (const float*)d_in[22];
    const float* W_disc    = (const float*)d_in[23];
    const float* b_disc    = (const float*)d_in[24];

    __half *Xhp, *MLPINHp, *W1Tp, *W3Tp;
    float *STAGEp, *Sp, *MLPOUTp, *DEGp;
    cudaGetSymbolAddress((void**)&Xhp, g_Xh);
    cudaGetSymbolAddress((void**)&MLPINHp, g_MLPINH);
    cudaGetSymbolAddress((void**)&W1Tp, g_W1T);
    cudaGetSymbolAddress((void**)&W3Tp, g_W3T);
    cudaGetSymbolAddress((void**)&STAGEp, g_STAGE);
    cudaGetSymbolAddress((void**)&Sp, g_S);
    cudaGetSymbolAddress((void**)&MLPOUTp, g_MLPOUT);
    cudaGetSymbolAddress((void**)&DEGp, g_DEG);

    float* out = (float*)d_out;
    float* emb = out;                       // [NN,256]
    float* ret = out + (size_t)NN * 256;    // [NN,2]
    float* ret_a = ret + (size_t)NN * 2;    // [NN,2]

    const int MLP_SMEM = (128 * 72 + 4 * 64 * 72) * 2;  // 55296 B -> 2 CTAs/SM (reg-capped)
    static bool attr_set = false;
    if (!attr_set) {
        cudaFuncSetAttribute(mlp16, cudaFuncAttributeMaxDynamicSharedMemorySize, MLP_SMEM);
        attr_set = true;
    }

    const int MROWS = (NN + 127) / 128;                               // 391
    const unsigned dual_blocks = ((unsigned)EE * 4u + 255u) / 256u;   // 12500
    const int seg_blocks = ((EE / 2) * 4 + 255) / 256;                // 6250

    // zero accumulators
    cudaMemsetAsync(STAGEp, 0, (size_t)5 * NN * 64 * sizeof(float));
    cudaMemsetAsync(Sp, 0, (size_t)NN * 64 * sizeof(float));
    cudaMemsetAsync(DEGp, 0, (size_t)3 * NN * sizeof(float));

    // weight pre-transpose (parallel, independent)
    transpose_w<<<16, 512>>>(W1, W3, W1Tp, W3Tp);

    // Xh = half(feat @ W_enc + b_enc)  [NN,64]  (tf32)
    mma_gemm<2><<<dim3(1, MROWS), 256>>>(feat, W_enc, b_enc, nullptr, nullptr, Xhp, NN, 256, 64);

    // stage 1: h (stage0) + shuf_h (stage2) + adj degree; h_g (stage1)
    spmm64h_dual<<<dual_blocks, 256>>>(adj_src, adj_dst, adj_val, perm, Xhp,
                                       STAGEp + (size_t)0 * NN * 64,
                                       STAGEp + (size_t)2 * NN * 64, DEGp, EE);
    spmm64h2<<<seg_blocks, 256>>>(gdc_src, gdc_dst, gdc_val, Xhp, STAGEp + (size_t)1 * NN * 64,
                                  nullptr, EE);

    // relu stage 0..2 -> fp16 MLPINH slots 0..2 (slot0/1 double as stage-2 gather tables)
    {
        int n4 = 3 * NN * 16;
        relu_to_half<<<(n4 + 255) / 256, 256>>>((const float4*)STAGEp, MLPINHp, n4);
    }

    // stage 2 (fused): adj->S, neigh->stage3 (+degN), diff->stage4 (+degD)
    spmm_stage2_all<<<3 * seg_blocks, 256>>>(adj_src, adj_dst, adj_val, neigh_src, neigh_dst,
                                             neigh_val, diff_src, diff_dst, diff_val, MLPINHp,
                                             MLPINHp + (size_t)NN * 64, Sp,
                                             STAGEp + (size_t)3 * NN * 64,
                                             STAGEp + (size_t)4 * NN * 64, DEGp + NN,
                                             DEGp + 2 * NN, EE, seg_blocks);

    // emb = relu(S @ W_dec + deg_adj ⊗ b_dec)  (spmm linearity), tf32
    mma_gemm<1><<<dim3(4, MROWS), 256>>>(Sp, W_dec, b_dec, DEGp, emb, nullptr, NN, 64, 256);

    // sigmoid averages -> fp16 MLPINH slots 3,4
    {
        int n2 = 2 * NN * 16;
        sigavg_to_half<<<(n2 + 255) / 256, 256>>>((const float4*)(STAGEp + (size_t)3 * NN * 64),
                                                  MLPINHp + (size_t)3 * NN * 64, DEGp + NN,
                                                  DEGp + 2 * NN);
    }

    // fused batched MLP (register-resident hidden, 1 barrier/chunk)
    {
        int M = 5 * NN;
        mlp16<<<(M + 127) / 128, 256, MLP_SMEM>>>(MLPINHp, W1Tp, b1, prelu_a, W3Tp, b3, MLPOUTp,
                                                  M);
    }

    // discriminator heads
    disc_kernel<<<(NN + 3) / 4, 128>>>(MLPOUTp, W_disc, b_disc, ret, ret_a);
}

// round 16
// speedup vs baseline: 1.4545x; 1.0200x over previous
#include <cuda_runtime.h>
#include <cuda_fp16.h>
#include <math.h>

#define NN 50000
#define EE 800000

// ---------------- scratch (static device globals; no runtime alloc) ----------------
__device__ __half g_Xh[(size_t)NN * 64];           // feat@W_enc + b_enc (fp16, gather table)
__device__ float  g_STAGE[(size_t)5 * NN * 64];    // fp32 atomic staging: h,h_g,shuf_h,nsum,dsum
__device__ __half g_MLPINH[(size_t)5 * NN * 64];   // fp16 MLP inputs (slots 0/1 = gather tables)
__device__ float  g_S[(size_t)NN * 64];            // spmm(adj, relu_h)
__device__ float  g_MLPOUT[(size_t)5 * NN * 64];   // z, z_g, shuf_z, g, g_g
__device__ float  g_DEG[3 * NN];                   // [adj | neigh | diff]
__device__ __half g_W1T[512 * 64];                 // W1 transposed [n][k] fp16
__device__ __half g_W3T[64 * 512];                 // W3 transposed [n][k] fp16

// ---------------- mma helpers ----------------
__device__ __forceinline__ unsigned cvt_tf32(float x) {
    unsigned u;
    asm("cvt.rna.tf32.f32 %0, %1;" : "=r"(u) : "f"(x));
    return u;
}
__device__ __forceinline__ void mma8(float* c, const unsigned* a, const unsigned* b) {
    asm("mma.sync.aligned.m16n8k8.row.col.f32.tf32.tf32.f32 "
        "{%0,%1,%2,%3},{%4,%5,%6,%7},{%8,%9},{%0,%1,%2,%3};"
        : "+f"(c[0]), "+f"(c[1]), "+f"(c[2]), "+f"(c[3])
        : "r"(a[0]), "r"(a[1]), "r"(a[2]), "r"(a[3]), "r"(b[0]), "r"(b[1]));
}
__device__ __forceinline__ void mma16(float* c, const unsigned* a, const unsigned* b) {
    asm("mma.sync.aligned.m16n8k16.row.col.f32.f16.f16.f32 "
        "{%0,%1,%2,%3},{%4,%5,%6,%7},{%8,%9},{%0,%1,%2,%3};"
        : "+f"(c[0]), "+f"(c[1]), "+f"(c[2]), "+f"(c[3])
        : "r"(a[0]), "r"(a[1]), "r"(a[2]), "r"(a[3]), "r"(b[0]), "r"(b[1]));
}
__device__ __forceinline__ void ldm_x4(unsigned* r, unsigned saddr) {
    asm volatile("ldmatrix.sync.aligned.m8n8.x4.shared.b16 {%0,%1,%2,%3}, [%4];"
                 : "=r"(r[0]), "=r"(r[1]), "=r"(r[2]), "=r"(r[3])
                 : "r"(saddr));
}

#define CP16(sdst, gsrc) \
    asm volatile("cp.async.ca.shared.global [%0], [%1], 16;" ::"r"(sdst), "l"(gsrc))
#define CP_COMMIT() asm volatile("cp.async.commit_group;")
#define CP_WAIT0() asm volatile("cp.async.wait_group 0;" ::: "memory")

// ---------------- weight pre-transpose (fp32 -> fp16, [k][n] -> [n][k]) --------------
__global__ void transpose_w(const float* __restrict__ W1, const float* __restrict__ W3,
                            __half* __restrict__ W1T, __half* __restrict__ W3T) {
    int b = blockIdx.x, t = threadIdx.x;
    if (b < 8) {
        int n = b * 64 + (t >> 3);
        int k0 = (t & 7) * 8;
#pragma unroll
        for (int i = 0; i < 8; i++)
            W1T[n * 64 + k0 + i] = __float2half_rn(W1[(size_t)(k0 + i) * 512 + n]);
    } else {
        int n = (b - 8) * 8 + (t >> 6);
        int k0 = (t & 63) * 8;
#pragma unroll
        for (int i = 0; i < 8; i++)
            W3T[n * 512 + k0 + i] = __float2half_rn(W3[(size_t)(k0 + i) * 64 + n]);
    }
}

// ---------------- single-TF32 GEMM ----------------
// EPI 1: C = relu(acc + deg[m]*bias[n]) fp32; EPI 2: Ch = half(acc + bias[n]) fp16
template <int EPI>
__global__ __launch_bounds__(256) void mma_gemm(const float* __restrict__ A,
                                                const float* __restrict__ W,
                                                const float* __restrict__ bias,
                                                const float* __restrict__ deg,
                                                float* __restrict__ C, __half* __restrict__ Ch,
                                                int M, int K, int Nc) {
    __shared__ unsigned As[128][36];
    __shared__ unsigned Bs[32][72];

    const int tid = threadIdx.x, lane = tid & 31, wid = tid >> 5;
    const int bm = blockIdx.y * 128, bn0 = blockIdx.x * 64;
    const int m_base = (wid & 3) * 32, n_base = (wid >> 2) * 32;
    const int lr = lane >> 2, lk = lane & 3;

    float acc[2][4][4];
#pragma unroll
    for (int mi = 0; mi < 2; mi++)
#pragma unroll
        for (int ni = 0; ni < 4; ni++)
#pragma unroll
            for (int i = 0; i < 4; i++) acc[mi][ni][i] = 0.f;

    for (int k0 = 0; k0 < K; k0 += 32) {
#pragma unroll
        for (int p = 0; p < 4; p++) {
            int idx = tid + p * 256;
            int row = idx >> 3, q = idx & 7;
            float4 v = make_float4(0.f, 0.f, 0.f, 0.f);
            if (bm + row < M)
                v = *reinterpret_cast<const float4*>(A + (size_t)(bm + row) * K + k0 + q * 4);
            As[row][q * 4 + 0] = cvt_tf32(v.x);
            As[row][q * 4 + 1] = cvt_tf32(v.y);
            As[row][q * 4 + 2] = cvt_tf32(v.z);
            As[row][q * 4 + 3] = cvt_tf32(v.w);
        }
#pragma unroll
        for (int p = 0; p < 2; p++) {
            int idx = tid + p * 256;
            int kr = idx >> 4, q = idx & 15;
            float4 v = *reinterpret_cast<const float4*>(W + (size_t)(k0 + kr) * Nc + bn0 + q * 4);
            Bs[kr][q * 4 + 0] = cvt_tf32(v.x);
            Bs[kr][q * 4 + 1] = cvt_tf32(v.y);
            Bs[kr][q * 4 + 2] = cvt_tf32(v.z);
            Bs[kr][q * 4 + 3] = cvt_tf32(v.w);
        }
        __syncthreads();

#pragma unroll
        for (int kk = 0; kk < 4; kk++) {
            unsigned a[2][4], b[4][2];
#pragma unroll
            for (int mi = 0; mi < 2; mi++) {
                int r0 = m_base + mi * 16 + lr;
                a[mi][0] = As[r0][kk * 8 + lk];
                a[mi][1] = As[r0 + 8][kk * 8 + lk];
                a[mi][2] = As[r0][kk * 8 + lk + 4];
                a[mi][3] = As[r0 + 8][kk * 8 + lk + 4];
            }
#pragma unroll
            for (int ni = 0; ni < 4; ni++) {
                int cn = n_base + ni * 8 + lr;
                b[ni][0] = Bs[kk * 8 + lk][cn];
                b[ni][1] = Bs[kk * 8 + lk + 4][cn];
            }
#pragma unroll
            for (int mi = 0; mi < 2; mi++)
#pragma unroll
                for (int ni = 0; ni < 4; ni++) mma8(acc[mi][ni], a[mi], b[ni]);
        }
        __syncthreads();
    }

#pragma unroll
    for (int mi = 0; mi < 2; mi++)
#pragma unroll
        for (int ni = 0; ni < 4; ni++) {
#pragma unroll
            for (int hi = 0; hi < 2; hi++) {
                int row = m_base + mi * 16 + lr + hi * 8;
                int col = n_base + ni * 8 + 2 * lk;
                int gm = bm + row, gn = bn0 + col;
                if (gm < M) {
                    float v0 = acc[mi][ni][hi * 2 + 0];
                    float v1 = acc[mi][ni][hi * 2 + 1];
                    if (EPI == 1) {
                        float dg = deg[gm];
                        v0 = fmaxf(v0 + dg * bias[gn], 0.f);
                        v1 = fmaxf(v1 + dg * bias[gn + 1], 0.f);
                        C[(size_t)gm * Nc + gn] = v0;
                        C[(size_t)gm * Nc + gn + 1] = v1;
                    } else {
                        v0 += bias[gn];
                        v1 += bias[gn + 1];
                        *reinterpret_cast<__half2*>(Ch + (size_t)gm * Nc + gn) =
                            __floats2half2_rn(v0, v1);
                    }
                }
            }
        }
}

// ---------------- fused MLP v4: reg-resident hidden + B via ldmatrix.x4 --------------
// BM=128, 256 threads (8 warps, each warp: 16 rows x all 64 cols). 1 barrier/chunk.
__global__ __launch_bounds__(256, 2) void mlp16(const __half* __restrict__ A,
                                                const __half* __restrict__ W1T,
                                                const float* __restrict__ b1,
                                                const float* __restrict__ aptr,
                                                const __half* __restrict__ W3T,
                                                const float* __restrict__ b3,
                                                float* __restrict__ C, int M) {
    extern __shared__ __half hsm[];
    __half(*As)[72] = (__half(*)[72])hsm;                      // 128 x 72
    const unsigned W1_OFF = 128 * 72;                          // halves
    const unsigned W3_OFF = W1_OFF + 2 * 64 * 72;

    const int tid = threadIdx.x, lane = tid & 31, wid = tid >> 5;
    const int bm = blockIdx.x * 128;
    const int m_base = wid * 16;
    const int g = lane >> 2, t = lane & 3;
    const float alpha = aptr[0];
    const unsigned sb = (unsigned)__cvta_generic_to_shared(hsm);

    // A-frag ldmatrix lane addressing
    const unsigned lrow = (unsigned)(lane & 15);
    const unsigned lcol8 = (unsigned)((lane >> 4) << 3);
    const unsigned aAddr0 = sb + ((m_base + lrow) * 72 + lcol8) * 2u;
    const unsigned KK_STEP = 16 * 2u;

    // B-frag ldmatrix lane addressing: tiles (rows 16p+rowsel, halves kb*16+colsel)
    const unsigned browsel = (unsigned)((lane & 7) | (((lane >> 4) & 1) << 3));
    const unsigned bcolsel = (unsigned)(((lane >> 3) & 1) << 3);
    const unsigned bW1Addr0 = sb + (W1_OFF + browsel * 72 + bcolsel) * 2u;
    const unsigned bW3Addr0 = sb + (W3_OFF + browsel * 72 + bcolsel) * 2u;
    const unsigned BUF_STEP = 64 * 72 * 2u;   // buffer stride (bytes)
    const unsigned P_STEP = 16 * 72 * 2u;     // +16 n-rows
    const unsigned KB_STEP = 16 * 2u;         // +16 k-halves

    auto issue = [&](int ch, int buf) {
#pragma unroll
        for (int j = 0; j < 2; j++) {
            int idx = tid + j * 256;
            int n = idx >> 3, o = idx & 7;
            const __half* s1 = W1T + ((size_t)(ch * 64 + n)) * 64 + o * 8;
            unsigned d1 = sb + (W1_OFF + (unsigned)buf * 64 * 72 + n * 72 + o * 8) * 2u;
            CP16(d1, s1);
            const __half* s3 = W3T + (size_t)n * 512 + ch * 64 + o * 8;
            unsigned d3 = sb + (W3_OFF + (unsigned)buf * 64 * 72 + n * 72 + o * 8) * 2u;
            CP16(d3, s3);
        }
        CP_COMMIT();
    };
    issue(0, 0);

    // A tile 128x64 fp16: straight uint4 copy
#pragma unroll
    for (int p = 0; p < 4; p++) {
        int idx = tid + p * 256;
        int row = idx >> 3, q = idx & 7;
        uint4 u = make_uint4(0u, 0u, 0u, 0u);
        if (bm + row < M)
            u = *reinterpret_cast<const uint4*>(A + (size_t)(bm + row) * 64 + q * 8);
        *reinterpret_cast<uint4*>(&As[row][q * 8]) = u;
    }

    float out_acc[8][4];
#pragma unroll
    for (int ni = 0; ni < 8; ni++)
#pragma unroll
        for (int i = 0; i < 4; i++) out_acc[ni][i] = 0.f;

    for (int ch = 0; ch < 8; ch++) {
        const int buf = ch & 1;
        CP_WAIT0();
        __syncthreads();  // weights(ch) visible (and As on ch==0)
        if (ch < 7) issue(ch + 1, buf ^ 1);
        const unsigned bufoff = (unsigned)buf * BUF_STEP;

        // ---- stage 1: H[16 x 64] = A @ W1chunk ----
        float h_acc[8][4];
#pragma unroll
        for (int ni = 0; ni < 8; ni++)
#pragma unroll
            for (int i = 0; i < 4; i++) h_acc[ni][i] = 0.f;

#pragma unroll
        for (int kb = 0; kb < 4; kb++) {
            unsigned a[4];
            ldm_x4(a, aAddr0 + kb * KK_STEP);
#pragma unroll
            for (int p = 0; p < 4; p++) {
                unsigned bfr[4];
                ldm_x4(bfr, bW1Addr0 + bufoff + p * P_STEP + kb * KB_STEP);
                mma16(h_acc[2 * p], a, bfr);
                mma16(h_acc[2 * p + 1], a, bfr + 2);
            }
        }

        // ---- bias + prelu in registers, pack as stage-2 A fragments ----
        unsigned hlo[8], hhi[8];
#pragma unroll
        for (int ni = 0; ni < 8; ni++) {
            int hc = ni * 8 + 2 * t;
            float bb0 = b1[ch * 64 + hc], bb1 = b1[ch * 64 + hc + 1];
            float v0 = h_acc[ni][0] + bb0;
            float v1 = h_acc[ni][1] + bb1;
            float v2 = h_acc[ni][2] + bb0;
            float v3 = h_acc[ni][3] + bb1;
            v0 = (v0 >= 0.f) ? v0 : alpha * v0;
            v1 = (v1 >= 0.f) ? v1 : alpha * v1;
            v2 = (v2 >= 0.f) ? v2 : alpha * v2;
            v3 = (v3 >= 0.f) ? v3 : alpha * v3;
            __half2 lo = __floats2half2_rn(v0, v1);
            __half2 hi = __floats2half2_rn(v2, v3);
            hlo[ni] = *reinterpret_cast<unsigned*>(&lo);
            hhi[ni] = *reinterpret_cast<unsigned*>(&hi);
        }

        // ---- stage 2: out += H @ W3chunk ----
#pragma unroll
        for (int kb = 0; kb < 4; kb++) {
            unsigned a[4] = {hlo[2 * kb], hhi[2 * kb], hlo[2 * kb + 1], hhi[2 * kb + 1]};
#pragma unroll
            for (int p = 0; p < 4; p++) {
                unsigned bfr[4];
                ldm_x4(bfr, bW3Addr0 + bufoff + p * P_STEP + kb * KB_STEP);
                mma16(out_acc[2 * p], a, bfr);
                mma16(out_acc[2 * p + 1], a, bfr + 2);
            }
        }
    }

    // epilogue
#pragma unroll
    for (int ni = 0; ni < 8; ni++) {
        int col = ni * 8 + 2 * t;
        int gm0 = bm + m_base + g;
        int gm1 = gm0 + 8;
        if (gm0 < M) {
            float2 v = make_float2(out_acc[ni][0] + b3[col], out_acc[ni][1] + b3[col + 1]);
            *reinterpret_cast<float2*>(C + (size_t)gm0 * 64 + col) = v;
        }
        if (gm1 < M) {
            float2 v = make_float2(out_acc[ni][2] + b3[col], out_acc[ni][3] + b3[col + 1]);
            *reinterpret_cast<float2*>(C + (size_t)gm1 * 64 + col) = v;
        }
    }
}

// ---------------- fp16-gather SpMM primitives ----------------
__device__ __forceinline__ void red4(float* p, float a, float b, float c, float d) {
    asm volatile("red.global.add.v4.f32 [%0], {%1,%2,%3,%4};" ::"l"(p), "f"(a), "f"(b), "f"(c),
                 "f"(d)
                 : "memory");
}
__device__ __forceinline__ void mulred16(const uint4& ra, const uint4& rb, float v, float* p) {
    const __half2* ha = reinterpret_cast<const __half2*>(&ra);
    const __half2* hb = reinterpret_cast<const __half2*>(&rb);
    float f[16];
#pragma unroll
    for (int i = 0; i < 4; i++) {
        float2 x = __half22float2(ha[i]);
        f[2 * i] = v * x.x;
        f[2 * i + 1] = v * x.y;
        float2 y = __half22float2(hb[i]);
        f[8 + 2 * i] = v * y.x;
        f[8 + 2 * i + 1] = v * y.y;
    }
#pragma unroll
    for (int i = 0; i < 4; i++)
        red4(p + 4 * i, f[4 * i], f[4 * i + 1], f[4 * i + 2], f[4 * i + 3]);
}

// spmm body: 2 edges per thread (q and q+E/2), 4 threads/edge (16 cols each).
__device__ __forceinline__ void spmm2_body(unsigned gid, const int* __restrict__ src,
                                           const int* __restrict__ dst,
                                           const float* __restrict__ val,
                                           const __half* __restrict__ X, float* __restrict__ out,
                                           float* __restrict__ deg, int E) {
    unsigned half_e = (unsigned)E >> 1;
    unsigned q = gid >> 2;
    if (q >= half_e) return;
    unsigned c = gid & 3;
    unsigned e1 = q + half_e;
    int s0 = src[q], d0 = dst[q];
    float v0 = val[q];
    int s1 = src[e1], d1 = dst[e1];
    float v1 = val[e1];
    const __half* g0 = X + (size_t)(unsigned)d0 * 64 + c * 16;
    const __half* g1 = X + (size_t)(unsigned)d1 * 64 + c * 16;
    uint4 ra0 = *reinterpret_cast<const uint4*>(g0);
    uint4 rb0 = *reinterpret_cast<const uint4*>(g0 + 8);
    uint4 ra1 = *reinterpret_cast<const uint4*>(g1);
    uint4 rb1 = *reinterpret_cast<const uint4*>(g1 + 8);
    mulred16(ra0, rb0, v0, out + (size_t)s0 * 64 + c * 16);
    mulred16(ra1, rb1, v1, out + (size_t)s1 * 64 + c * 16);
    if (deg != nullptr && c == 0) {
        atomicAdd(&deg[s0], v0);
        atomicAdd(&deg[s1], v1);
    }
}

// dual body (adj + shuffled-adj, 1 edge/thread) used by stage-1 fused kernel
__device__ __forceinline__ void spmm_dual_body(unsigned gid, const int* __restrict__ src,
                                               const int* __restrict__ dst,
                                               const float* __restrict__ val,
                                               const int* __restrict__ perm,
                                               const __half* __restrict__ X,
                                               float* __restrict__ out0,
                                               float* __restrict__ out1,
                                               float* __restrict__ deg, int E) {
    unsigned e = gid >> 2;
    if (e >= (unsigned)E) return;
    unsigned c = gid & 3;
    int s = src[e];
    int d = dst[e];
    float v = val[e];
    int pd = perm[d];
    const __half* g0 = X + (unsigned)d * 64 + c * 16;
    const __half* g1 = X + (unsigned)pd * 64 + c * 16;
    uint4 ra0 = *reinterpret_cast<const uint4*>(g0);
    uint4 rb0 = *reinterpret_cast<const uint4*>(g0 + 8);
    uint4 ra1 = *reinterpret_cast<const uint4*>(g1);
    uint4 rb1 = *reinterpret_cast<const uint4*>(g1 + 8);
    mulred16(ra0, rb0, v, out0 + (size_t)s * 64 + c * 16);
    mulred16(ra1, rb1, v, out1 + (size_t)s * 64 + c * 16);
    if (c == 0) atomicAdd(&deg[s], v);
}

// stage 1 fused: blocks [0,dualBlocks) = adj dual (+degA); rest = gdc (2 edges/thread)
__global__ __launch_bounds__(256) void spmm_stage1_all(
    const int* __restrict__ sA, const int* __restrict__ dA, const float* __restrict__ vA,
    const int* __restrict__ perm, const int* __restrict__ sG, const int* __restrict__ dG,
    const float* __restrict__ vG, const __half* __restrict__ X, float* __restrict__ st0,
    float* __restrict__ st1, float* __restrict__ st2, float* __restrict__ degA, int E,
    int dualBlocks) {
    if ((int)blockIdx.x < dualBlocks) {
        unsigned gid = blockIdx.x * blockDim.x + threadIdx.x;
        spmm_dual_body(gid, sA, dA, vA, perm, X, st0, st2, degA, E);
    } else {
        unsigned gid = (unsigned)(blockIdx.x - dualBlocks) * blockDim.x + threadIdx.x;
        spmm2_body(gid, sG, dG, vG, X, st1, nullptr, E);
    }
}

// stage 2 fused: seg 0 = adj->S, seg 1 = neigh->stage3 (+degN), seg 2 = diff->stage4 (+degD)
__global__ __launch_bounds__(256) void spmm_stage2_all(
    const int* __restrict__ sA, const int* __restrict__ dA, const float* __restrict__ vA,
    const int* __restrict__ sN, const int* __restrict__ dN, const float* __restrict__ vN,
    const int* __restrict__ sD, const int* __restrict__ dD, const float* __restrict__ vD,
    const __half* __restrict__ H0, const __half* __restrict__ H1, float* __restrict__ S,
    float* __restrict__ st3, float* __restrict__ st4, float* __restrict__ degN,
    float* __restrict__ degD, int E, int segBlocks) {
    int seg = blockIdx.x / segBlocks;
    int blk = blockIdx.x - seg * segBlocks;
    unsigned gid = (unsigned)blk * blockDim.x + threadIdx.x;
    if (seg == 0) {
        spmm2_body(gid, sA, dA, vA, H0, S, nullptr, E);
    } else if (seg == 1) {
        spmm2_body(gid, sN, dN, vN, H0, st3, degN, E);
    } else {
        spmm2_body(gid, sD, dD, vD, H1, st4, degD, E);
    }
}

// ---------------- relu(stage slots 0..2) -> fp16 MLPINH slots 0..2 ----------------
__global__ void relu_to_half(const float4* __restrict__ stage, __half* __restrict__ hout,
                             int n4) {
    int i = blockIdx.x * blockDim.x + threadIdx.x;
    if (i < n4) {
        float4 v = stage[i];
        __half2 a = __floats2half2_rn(fmaxf(v.x, 0.f), fmaxf(v.y, 0.f));
        __half2 b = __floats2half2_rn(fmaxf(v.z, 0.f), fmaxf(v.w, 0.f));
        uint2 u;
        u.x = *reinterpret_cast<unsigned*>(&a);
        u.y = *reinterpret_cast<unsigned*>(&b);
        *reinterpret_cast<uint2*>(hout + (size_t)i * 4) = u;
    }
}

// ---------------- sigmoid(stage slots 3,4 / max(deg,1)) -> fp16 MLPINH 3,4 -----------
__global__ void sigavg_to_half(const float4* __restrict__ stage, __half* __restrict__ hout,
                               const float* __restrict__ degN, const float* __restrict__ degD) {
    int i = blockIdx.x * blockDim.x + threadIdx.x;
    const int n4 = NN * 16;
    if (i < 2 * n4) {
        int j = i * 4;
        const float* deg = (i < n4) ? degN : degD;
        int node = ((i < n4) ? j : (j - NN * 64)) >> 6;
        float d = deg[node];
        d = (d > 1.f) ? d : 1.f;
        float4 v = stage[i];
        float s0 = 1.f / (1.f + expf(-v.x / d));
        float s1 = 1.f / (1.f + expf(-v.y / d));
        float s2 = 1.f / (1.f + expf(-v.z / d));
        float s3 = 1.f / (1.f + expf(-v.w / d));
        __half2 a = __floats2half2_rn(s0, s1);
        __half2 b = __floats2half2_rn(s2, s3);
        uint2 u;
        u.x = *reinterpret_cast<unsigned*>(&a);
        u.y = *reinterpret_cast<unsigned*>(&b);
        *reinterpret_cast<uint2*>(hout + (size_t)i * 4) = u;
    }
}

// ---------------- discriminator ----------------
__global__ void disc_kernel(const float* __restrict__ Mo, const float* __restrict__ W,
                            const float* __restrict__ bptr, float* __restrict__ ret,
                            float* __restrict__ ret_a) {
    __shared__ float Ws[64][65];
    int tid = threadIdx.x;
    for (int i = tid; i < 4096; i += 128) Ws[i >> 6][i & 63] = W[i];
    __syncthreads();

    int warp = tid >> 5, lane = tid & 31;
    int node = blockIdx.x * 4 + warp;
    if (node >= NN) return;

    const float* z = Mo + (size_t)0 * NN * 64 + (size_t)node * 64;
    const float* zg = Mo + (size_t)1 * NN * 64 + (size_t)node * 64;
    const float* sz = Mo + (size_t)2 * NN * 64 + (size_t)node * 64;
    const float* gv = Mo + (size_t)3 * NN * 64 + (size_t)node * 64;
    const float* gg = Mo + (size_t)4 * NN * 64 + (size_t)node * 64;

    float r0 = 0.f, r1 = 0.f, a0 = 0.f, a1 = 0.f;
#pragma unroll
    for (int h = 0; h < 2; h++) {
        int d = lane + h * 32;
        float tgg = 0.f, tg = 0.f;
#pragma unroll
        for (int e = 0; e < 64; e++) {
            float w = Ws[d][e];
            tgg += w * gg[e];
            tg += w * gv[e];
        }
        r0 += z[d] * tgg;
        r1 += sz[d] * tgg;
        a0 += zg[d] * tg;
        a1 += sz[d] * tg;
    }
#pragma unroll
    for (int o = 16; o; o >>= 1) {
        r0 += __shfl_xor_sync(0xFFFFFFFFu, r0, o);
        r1 += __shfl_xor_sync(0xFFFFFFFFu, r1, o);
        a0 += __shfl_xor_sync(0xFFFFFFFFu, a0, o);
        a1 += __shfl_xor_sync(0xFFFFFFFFu, a1, o);
    }
    if (lane == 0) {
        float b = bptr[0];
        ret[(size_t)node * 2 + 0] = r0 + b;
        ret[(size_t)node * 2 + 1] = r1 + b;
        ret_a[(size_t)node * 2 + 0] = a0 + b;
        ret_a[(size_t)node * 2 + 1] = a1 + b;
    }
}

// =====================================================================================
extern "C" void kernel_launch(void* const* d_in, const int* in_sizes, int n_in, void* d_out,
                              int out_size) {
    (void)in_sizes; (void)n_in; (void)out_size;

    const float* feat      = (const float*)d_in[0];
    const int*   adj_src   = (const int*)d_in[1];
    const int*   adj_dst   = (const int*)d_in[2];
    const float* adj_val   = (const float*)d_in[3];
    const int*   gdc_src   = (const int*)d_in[4];
    const int*   gdc_dst   = (const int*)d_in[5];
    const float* gdc_val   = (const float*)d_in[6];
    const int*   neigh_src = (const int*)d_in[7];
    const int*   neigh_dst = (const int*)d_in[8];
    const float* neigh_val = (const float*)d_in[9];
    const int*   diff_src  = (const int*)d_in[10];
    const int*   diff_dst  = (const int*)d_in[11];
    const float* diff_val  = (const float*)d_in[12];
    const int*   perm      = (const int*)d_in[13];
    const float* W_enc     = (const float*)d_in[14];
    const float* b_enc     = (const float*)d_in[15];
    const float* W_dec     = (const float*)d_in[16];
    const float* b_dec     = (const float*)d_in[17];
    const float* W1        = (const float*)d_in[18];
    const float* b1        = (const float*)d_in[19];
    const float* prelu_a   = (const float*)d_in[20];
    const float* W3        = (const float*)d_in[21];
    const float* b3        = (const float*)d_in[22];
    const float* W_disc    = (const float*)d_in[23];
    const float* b_disc    = (const float*)d_in[24];

    __half *Xhp, *MLPINHp, *W1Tp, *W3Tp;
    float *STAGEp, *Sp, *MLPOUTp, *DEGp;
    cudaGetSymbolAddress((void**)&Xhp, g_Xh);
    cudaGetSymbolAddress((void**)&MLPINHp, g_MLPINH);
    cudaGetSymbolAddress((void**)&W1Tp, g_W1T);
    cudaGetSymbolAddress((void**)&W3Tp, g_W3T);
    cudaGetSymbolAddress((void**)&STAGEp, g_STAGE);
    cudaGetSymbolAddress((void**)&Sp, g_S);
    cudaGetSymbolAddress((void**)&MLPOUTp, g_MLPOUT);
    cudaGetSymbolAddress((void**)&DEGp, g_DEG);

    float* out = (float*)d_out;
    float* emb = out;                       // [NN,256]
    float* ret = out + (size_t)NN * 256;    // [NN,2]
    float* ret_a = ret + (size_t)NN * 2;    // [NN,2]

    const int MLP_SMEM = (128 * 72 + 4 * 64 * 72) * 2;  // 55296 B
    static bool attr_set = false;
    if (!attr_set) {
        cudaFuncSetAttribute(mlp16, cudaFuncAttributeMaxDynamicSharedMemorySize, MLP_SMEM);
        attr_set = true;
    }

    const int MROWS = (NN + 127) / 128;                          // 391
    const int dual_blocks = (EE * 4 + 255) / 256;                // 12500
    const int seg_blocks = ((EE / 2) * 4 + 255) / 256;           // 6250

    // zero accumulators
    cudaMemsetAsync(STAGEp, 0, (size_t)5 * NN * 64 * sizeof(float));
    cudaMemsetAsync(Sp, 0, (size_t)NN * 64 * sizeof(float));
    cudaMemsetAsync(DEGp, 0, (size_t)3 * NN * sizeof(float));

    // weight pre-transpose (parallel, independent)
    transpose_w<<<16, 512>>>(W1, W3, W1Tp, W3Tp);

    // Xh = half(feat @ W_enc + b_enc)  [NN,64]  (tf32)
    mma_gemm<2><<<dim3(1, MROWS), 256>>>(feat, W_enc, b_enc, nullptr, nullptr, Xhp, NN, 256, 64);

    // stage 1 (fused): adj dual -> stage0/stage2 (+degA); gdc -> stage1
    spmm_stage1_all<<<dual_blocks + seg_blocks, 256>>>(adj_src, adj_dst, adj_val, perm, gdc_src,
                                                       gdc_dst, gdc_val, Xhp,
                                                       STAGEp + (size_t)0 * NN * 64,
                                                       STAGEp + (size_t)1 * NN * 64,
                                                       STAGEp + (size_t)2 * NN * 64, DEGp, EE,
                                                       dual_blocks);

    // relu stage 0..2 -> fp16 MLPINH slots 0..2 (slot0/1 double as stage-2 gather tables)
    {
        int n4 = 3 * NN * 16;
        relu_to_half<<<(n4 + 255) / 256, 256>>>((const float4*)STAGEp, MLPINHp, n4);
    }

    // stage 2 (fused): adj->S, neigh->stage3 (+degN), diff->stage4 (+degD)
    spmm_stage2_all<<<3 * seg_blocks, 256>>>(adj_src, adj_dst, adj_val, neigh_src, neigh_dst,
                                             neigh_val, diff_src, diff_dst, diff_val, MLPINHp,
                                             MLPINHp + (size_t)NN * 64, Sp,
                                             STAGEp + (size_t)3 * NN * 64,
                                             STAGEp + (size_t)4 * NN * 64, DEGp + NN,
                                             DEGp + 2 * NN, EE, seg_blocks);

    // emb = relu(S @ W_dec + deg_adj ⊗ b_dec)  (spmm linearity), tf32
    mma_gemm<1><<<dim3(4, MROWS), 256>>>(Sp, W_dec, b_dec, DEGp, emb, nullptr, NN, 64, 256);

    // sigmoid averages -> fp16 MLPINH slots 3,4
    {
        int n2 = 2 * NN * 16;
        sigavg_to_half<<<(n2 + 255) / 256, 256>>>((const float4*)(STAGEp + (size_t)3 * NN * 64),
                                                  MLPINHp + (size_t)3 * NN * 64, DEGp + NN,
                                                  DEGp + 2 * NN);
    }

    // fused batched MLP (register-resident hidden, ldmatrix A+B)
    {
        int M = 5 * NN;
        mlp16<<<(M + 127) / 128, 256, MLP_SMEM>>>(MLPINHp, W1Tp, b1, prelu_a, W3Tp, b3, MLPOUTp,
                                                  M);
    }

    // discriminator heads
    disc_kernel<<<(NN + 3) / 4, 128>>>(MLPOUTp, W_disc, b_disc, ret, ret_a);
}

// round 17
// speedup vs baseline: 1.4841x; 1.0204x over previous
#include <cuda_runtime.h>
#include <cuda_fp16.h>
#include <math.h>

#define NN 50000
#define EE 800000

// ---------------- scratch (static device globals; no runtime alloc) ----------------
__device__ __half g_Xh[(size_t)NN * 64];           // feat@W_enc + b_enc (fp16, gather table)
// one zeroable block: STAGE (5*NN*64) | S (NN*64) | DEG (3*NN)
__device__ float  g_Z[(size_t)5 * NN * 64 + (size_t)NN * 64 + 3 * NN];
__device__ __half g_MLPINH[(size_t)5 * NN * 64];   // fp16 MLP inputs (slots 0/1 = gather tables)
__device__ float  g_MLPOUT[(size_t)5 * NN * 64];   // z, z_g, shuf_z, g, g_g
__device__ __half g_W1T[512 * 64];                 // W1 transposed [n][k] fp16
__device__ __half g_W3T[64 * 512];                 // W3 transposed [n][k] fp16

// ---------------- mma helpers ----------------
__device__ __forceinline__ unsigned cvt_tf32(float x) {
    unsigned u;
    asm("cvt.rna.tf32.f32 %0, %1;" : "=r"(u) : "f"(x));
    return u;
}
__device__ __forceinline__ void mma8(float* c, const unsigned* a, const unsigned* b) {
    asm("mma.sync.aligned.m16n8k8.row.col.f32.tf32.tf32.f32 "
        "{%0,%1,%2,%3},{%4,%5,%6,%7},{%8,%9},{%0,%1,%2,%3};"
        : "+f"(c[0]), "+f"(c[1]), "+f"(c[2]), "+f"(c[3])
        : "r"(a[0]), "r"(a[1]), "r"(a[2]), "r"(a[3]), "r"(b[0]), "r"(b[1]));
}
__device__ __forceinline__ void mma16(float* c, const unsigned* a, const unsigned* b) {
    asm("mma.sync.aligned.m16n8k16.row.col.f32.f16.f16.f32 "
        "{%0,%1,%2,%3},{%4,%5,%6,%7},{%8,%9},{%0,%1,%2,%3};"
        : "+f"(c[0]), "+f"(c[1]), "+f"(c[2]), "+f"(c[3])
        : "r"(a[0]), "r"(a[1]), "r"(a[2]), "r"(a[3]), "r"(b[0]), "r"(b[1]));
}
__device__ __forceinline__ void ldm_x4(unsigned* r, unsigned saddr) {
    asm volatile("ldmatrix.sync.aligned.m8n8.x4.shared.b16 {%0,%1,%2,%3}, [%4];"
                 : "=r"(r[0]), "=r"(r[1]), "=r"(r[2]), "=r"(r[3])
                 : "r"(saddr));
}

#define CP16(sdst, gsrc) \
    asm volatile("cp.async.ca.shared.global [%0], [%1], 16;" ::"r"(sdst), "l"(gsrc))
#define CP_COMMIT() asm volatile("cp.async.commit_group;")
#define CP_WAIT0() asm volatile("cp.async.wait_group 0;" ::: "memory")

// ---------------- weight pre-transpose (fp32 -> fp16, [k][n] -> [n][k]) --------------
__global__ void transpose_w(const float* __restrict__ W1, const float* __restrict__ W3,
                            __half* __restrict__ W1T, __half* __restrict__ W3T) {
    int b = blockIdx.x, t = threadIdx.x;
    if (b < 8) {
        int n = b * 64 + (t >> 3);
        int k0 = (t & 7) * 8;
#pragma unroll
        for (int i = 0; i < 8; i++)
            W1T[n * 64 + k0 + i] = __float2half_rn(W1[(size_t)(k0 + i) * 512 + n]);
    } else {
        int n = (b - 8) * 8 + (t >> 6);
        int k0 = (t & 63) * 8;
#pragma unroll
        for (int i = 0; i < 8; i++)
            W3T[n * 512 + k0 + i] = __float2half_rn(W3[(size_t)(k0 + i) * 64 + n]);
    }
}

// ---------------- single-TF32 GEMM ----------------
// EPI 1: C = relu(acc + deg[m]*bias[n]) fp32; EPI 2: Ch = half(acc + bias[n]) fp16
template <int EPI>
__global__ __launch_bounds__(256) void mma_gemm(const float* __restrict__ A,
                                                const float* __restrict__ W,
                                                const float* __restrict__ bias,
                                                const float* __restrict__ deg,
                                                float* __restrict__ C, __half* __restrict__ Ch,
                                                int M, int K, int Nc) {
    __shared__ unsigned As[128][36];
    __shared__ unsigned Bs[32][72];

    const int tid = threadIdx.x, lane = tid & 31, wid = tid >> 5;
    const int bm = blockIdx.y * 128, bn0 = blockIdx.x * 64;
    const int m_base = (wid & 3) * 32, n_base = (wid >> 2) * 32;
    const int lr = lane >> 2, lk = lane & 3;

    float acc[2][4][4];
#pragma unroll
    for (int mi = 0; mi < 2; mi++)
#pragma unroll
        for (int ni = 0; ni < 4; ni++)
#pragma unroll
            for (int i = 0; i < 4; i++) acc[mi][ni][i] = 0.f;

    for (int k0 = 0; k0 < K; k0 += 32) {
#pragma unroll
        for (int p = 0; p < 4; p++) {
            int idx = tid + p * 256;
            int row = idx >> 3, q = idx & 7;
            float4 v = make_float4(0.f, 0.f, 0.f, 0.f);
            if (bm + row < M)
                v = *reinterpret_cast<const float4*>(A + (size_t)(bm + row) * K + k0 + q * 4);
            As[row][q * 4 + 0] = cvt_tf32(v.x);
            As[row][q * 4 + 1] = cvt_tf32(v.y);
            As[row][q * 4 + 2] = cvt_tf32(v.z);
            As[row][q * 4 + 3] = cvt_tf32(v.w);
        }
#pragma unroll
        for (int p = 0; p < 2; p++) {
            int idx = tid + p * 256;
            int kr = idx >> 4, q = idx & 15;
            float4 v = *reinterpret_cast<const float4*>(W + (size_t)(k0 + kr) * Nc + bn0 + q * 4);
            Bs[kr][q * 4 + 0] = cvt_tf32(v.x);
            Bs[kr][q * 4 + 1] = cvt_tf32(v.y);
            Bs[kr][q * 4 + 2] = cvt_tf32(v.z);
            Bs[kr][q * 4 + 3] = cvt_tf32(v.w);
        }
        __syncthreads();

#pragma unroll
        for (int kk = 0; kk < 4; kk++) {
            unsigned a[2][4], b[4][2];
#pragma unroll
            for (int mi = 0; mi < 2; mi++) {
                int r0 = m_base + mi * 16 + lr;
                a[mi][0] = As[r0][kk * 8 + lk];
                a[mi][1] = As[r0 + 8][kk * 8 + lk];
                a[mi][2] = As[r0][kk * 8 + lk + 4];
                a[mi][3] = As[r0 + 8][kk * 8 + lk + 4];
            }
#pragma unroll
            for (int ni = 0; ni < 4; ni++) {
                int cn = n_base + ni * 8 + lr;
                b[ni][0] = Bs[kk * 8 + lk][cn];
                b[ni][1] = Bs[kk * 8 + lk + 4][cn];
            }
#pragma unroll
            for (int mi = 0; mi < 2; mi++)
#pragma unroll
                for (int ni = 0; ni < 4; ni++) mma8(acc[mi][ni], a[mi], b[ni]);
        }
        __syncthreads();
    }

#pragma unroll
    for (int mi = 0; mi < 2; mi++)
#pragma unroll
        for (int ni = 0; ni < 4; ni++) {
#pragma unroll
            for (int hi = 0; hi < 2; hi++) {
                int row = m_base + mi * 16 + lr + hi * 8;
                int col = n_base + ni * 8 + 2 * lk;
                int gm = bm + row, gn = bn0 + col;
                if (gm < M) {
                    float v0 = acc[mi][ni][hi * 2 + 0];
                    float v1 = acc[mi][ni][hi * 2 + 1];
                    if (EPI == 1) {
                        float dg = deg[gm];
                        v0 = fmaxf(v0 + dg * bias[gn], 0.f);
                        v1 = fmaxf(v1 + dg * bias[gn + 1], 0.f);
                        C[(size_t)gm * Nc + gn] = v0;
                        C[(size_t)gm * Nc + gn + 1] = v1;
                    } else {
                        v0 += bias[gn];
                        v1 += bias[gn + 1];
                        *reinterpret_cast<__half2*>(Ch + (size_t)gm * Nc + gn) =
                            __floats2half2_rn(v0, v1);
                    }
                }
            }
        }
}

// ---------------- fused MLP v4: reg-resident hidden + B via ldmatrix.x4 --------------
__global__ __launch_bounds__(256, 2) void mlp16(const __half* __restrict__ A,
                                                const __half* __restrict__ W1T,
                                                const float* __restrict__ b1,
                                                const float* __restrict__ aptr,
                                                const __half* __restrict__ W3T,
                                                const float* __restrict__ b3,
                                                float* __restrict__ C, int M) {
    extern __shared__ __half hsm[];
    __half(*As)[72] = (__half(*)[72])hsm;                      // 128 x 72
    const unsigned W1_OFF = 128 * 72;                          // halves
    const unsigned W3_OFF = W1_OFF + 2 * 64 * 72;

    const int tid = threadIdx.x, lane = tid & 31, wid = tid >> 5;
    const int bm = blockIdx.x * 128;
    const int m_base = wid * 16;
    const int g = lane >> 2, t = lane & 3;
    const float alpha = aptr[0];
    const unsigned sb = (unsigned)__cvta_generic_to_shared(hsm);

    const unsigned lrow = (unsigned)(lane & 15);
    const unsigned lcol8 = (unsigned)((lane >> 4) << 3);
    const unsigned aAddr0 = sb + ((m_base + lrow) * 72 + lcol8) * 2u;
    const unsigned KK_STEP = 16 * 2u;

    const unsigned browsel = (unsigned)((lane & 7) | (((lane >> 4) & 1) << 3));
    const unsigned bcolsel = (unsigned)(((lane >> 3) & 1) << 3);
    const unsigned bW1Addr0 = sb + (W1_OFF + browsel * 72 + bcolsel) * 2u;
    const unsigned bW3Addr0 = sb + (W3_OFF + browsel * 72 + bcolsel) * 2u;
    const unsigned BUF_STEP = 64 * 72 * 2u;
    const unsigned P_STEP = 16 * 72 * 2u;
    const unsigned KB_STEP = 16 * 2u;

    auto issue = [&](int ch, int buf) {
#pragma unroll
        for (int j = 0; j < 2; j++) {
            int idx = tid + j * 256;
            int n = idx >> 3, o = idx & 7;
            const __half* s1 = W1T + ((size_t)(ch * 64 + n)) * 64 + o * 8;
            unsigned d1 = sb + (W1_OFF + (unsigned)buf * 64 * 72 + n * 72 + o * 8) * 2u;
            CP16(d1, s1);
            const __half* s3 = W3T + (size_t)n * 512 + ch * 64 + o * 8;
            unsigned d3 = sb + (W3_OFF + (unsigned)buf * 64 * 72 + n * 72 + o * 8) * 2u;
            CP16(d3, s3);
        }
        CP_COMMIT();
    };
    issue(0, 0);

#pragma unroll
    for (int p = 0; p < 4; p++) {
        int idx = tid + p * 256;
        int row = idx >> 3, q = idx & 7;
        uint4 u = make_uint4(0u, 0u, 0u, 0u);
        if (bm + row < M)
            u = *reinterpret_cast<const uint4*>(A + (size_t)(bm + row) * 64 + q * 8);
        *reinterpret_cast<uint4*>(&As[row][q * 8]) = u;
    }

    float out_acc[8][4];
#pragma unroll
    for (int ni = 0; ni < 8; ni++)
#pragma unroll
        for (int i = 0; i < 4; i++) out_acc[ni][i] = 0.f;

    for (int ch = 0; ch < 8; ch++) {
        const int buf = ch & 1;
        CP_WAIT0();
        __syncthreads();
        if (ch < 7) issue(ch + 1, buf ^ 1);
        const unsigned bufoff = (unsigned)buf * BUF_STEP;

        float h_acc[8][4];
#pragma unroll
        for (int ni = 0; ni < 8; ni++)
#pragma unroll
            for (int i = 0; i < 4; i++) h_acc[ni][i] = 0.f;

#pragma unroll
        for (int kb = 0; kb < 4; kb++) {
            unsigned a[4];
            ldm_x4(a, aAddr0 + kb * KK_STEP);
#pragma unroll
            for (int p = 0; p < 4; p++) {
                unsigned bfr[4];
                ldm_x4(bfr, bW1Addr0 + bufoff + p * P_STEP + kb * KB_STEP);
                mma16(h_acc[2 * p], a, bfr);
                mma16(h_acc[2 * p + 1], a, bfr + 2);
            }
        }

        unsigned hlo[8], hhi[8];
#pragma unroll
        for (int ni = 0; ni < 8; ni++) {
            int hc = ni * 8 + 2 * t;
            float bb0 = b1[ch * 64 + hc], bb1 = b1[ch * 64 + hc + 1];
            float v0 = h_acc[ni][0] + bb0;
            float v1 = h_acc[ni][1] + bb1;
            float v2 = h_acc[ni][2] + bb0;
            float v3 = h_acc[ni][3] + bb1;
            v0 = (v0 >= 0.f) ? v0 : alpha * v0;
            v1 = (v1 >= 0.f) ? v1 : alpha * v1;
            v2 = (v2 >= 0.f) ? v2 : alpha * v2;
            v3 = (v3 >= 0.f) ? v3 : alpha * v3;
            __half2 lo = __floats2half2_rn(v0, v1);
            __half2 hi = __floats2half2_rn(v2, v3);
            hlo[ni] = *reinterpret_cast<unsigned*>(&lo);
            hhi[ni] = *reinterpret_cast<unsigned*>(&hi);
        }

#pragma unroll
        for (int kb = 0; kb < 4; kb++) {
            unsigned a[4] = {hlo[2 * kb], hhi[2 * kb], hlo[2 * kb + 1], hhi[2 * kb + 1]};
#pragma unroll
            for (int p = 0; p < 4; p++) {
                unsigned bfr[4];
                ldm_x4(bfr, bW3Addr0 + bufoff + p * P_STEP + kb * KB_STEP);
                mma16(out_acc[2 * p], a, bfr);
                mma16(out_acc[2 * p + 1], a, bfr + 2);
            }
        }
    }

#pragma unroll
    for (int ni = 0; ni < 8; ni++) {
        int col = ni * 8 + 2 * t;
        int gm0 = bm + m_base + g;
        int gm1 = gm0 + 8;
        if (gm0 < M) {
            float2 v = make_float2(out_acc[ni][0] + b3[col], out_acc[ni][1] + b3[col + 1]);
            *reinterpret_cast<float2*>(C + (size_t)gm0 * 64 + col) = v;
        }
        if (gm1 < M) {
            float2 v = make_float2(out_acc[ni][2] + b3[col], out_acc[ni][3] + b3[col + 1]);
            *reinterpret_cast<float2*>(C + (size_t)gm1 * 64 + col) = v;
        }
    }
}

// ---------------- fp16-gather SpMM primitives ----------------
__device__ __forceinline__ void red4(float* p, float a, float b, float c, float d) {
    asm volatile("red.global.add.v4.f32 [%0], {%1,%2,%3,%4};" ::"l"(p), "f"(a), "f"(b), "f"(c),
                 "f"(d)
                 : "memory");
}
__device__ __forceinline__ void mulred16(const uint4& ra, const uint4& rb, float v, float* p) {
    const __half2* ha = reinterpret_cast<const __half2*>(&ra);
    const __half2* hb = reinterpret_cast<const __half2*>(&rb);
    float f[16];
#pragma unroll
    for (int i = 0; i < 4; i++) {
        float2 x = __half22float2(ha[i]);
        f[2 * i] = v * x.x;
        f[2 * i + 1] = v * x.y;
        float2 y = __half22float2(hb[i]);
        f[8 + 2 * i] = v * y.x;
        f[8 + 2 * i + 1] = v * y.y;
    }
#pragma unroll
    for (int i = 0; i < 4; i++)
        red4(p + 4 * i, f[4 * i], f[4 * i + 1], f[4 * i + 2], f[4 * i + 3]);
}

__device__ __forceinline__ void spmm2_body(unsigned gid, const int* __restrict__ src,
                                           const int* __restrict__ dst,
                                           const float* __restrict__ val,
                                           const __half* __restrict__ X, float* __restrict__ out,
                                           float* __restrict__ deg, int E) {
    unsigned half_e = (unsigned)E >> 1;
    unsigned q = gid >> 2;
    if (q >= half_e) return;
    unsigned c = gid & 3;
    unsigned e1 = q + half_e;
    int s0 = src[q], d0 = dst[q];
    float v0 = val[q];
    int s1 = src[e1], d1 = dst[e1];
    float v1 = val[e1];
    const __half* g0 = X + (size_t)(unsigned)d0 * 64 + c * 16;
    const __half* g1 = X + (size_t)(unsigned)d1 * 64 + c * 16;
    uint4 ra0 = *reinterpret_cast<const uint4*>(g0);
    uint4 rb0 = *reinterpret_cast<const uint4*>(g0 + 8);
    uint4 ra1 = *reinterpret_cast<const uint4*>(g1);
    uint4 rb1 = *reinterpret_cast<const uint4*>(g1 + 8);
    mulred16(ra0, rb0, v0, out + (size_t)s0 * 64 + c * 16);
    mulred16(ra1, rb1, v1, out + (size_t)s1 * 64 + c * 16);
    if (deg != nullptr && c == 0) {
        atomicAdd(&deg[s0], v0);
        atomicAdd(&deg[s1], v1);
    }
}

__device__ __forceinline__ void spmm_dual_body(unsigned gid, const int* __restrict__ src,
                                               const int* __restrict__ dst,
                                               const float* __restrict__ val,
                                               const int* __restrict__ perm,
                                               const __half* __restrict__ X,
                                               float* __restrict__ out0,
                                               float* __restrict__ out1,
                                               float* __restrict__ deg, int E) {
    unsigned e = gid >> 2;
    if (e >= (unsigned)E) return;
    unsigned c = gid & 3;
    int s = src[e];
    int d = dst[e];
    float v = val[e];
    int pd = perm[d];
    const __half* g0 = X + (unsigned)d * 64 + c * 16;
    const __half* g1 = X + (unsigned)pd * 64 + c * 16;
    uint4 ra0 = *reinterpret_cast<const uint4*>(g0);
    uint4 rb0 = *reinterpret_cast<const uint4*>(g0 + 8);
    uint4 ra1 = *reinterpret_cast<const uint4*>(g1);
    uint4 rb1 = *reinterpret_cast<const uint4*>(g1 + 8);
    mulred16(ra0, rb0, v, out0 + (size_t)s * 64 + c * 16);
    mulred16(ra1, rb1, v, out1 + (size_t)s * 64 + c * 16);
    if (c == 0) atomicAdd(&deg[s], v);
}

// stage 1 fused: blocks [0,dualBlocks) = adj dual (+degA); rest = gdc (2 edges/thread)
__global__ __launch_bounds__(256) void spmm_stage1_all(
    const int* __restrict__ sA, const int* __restrict__ dA, const float* __restrict__ vA,
    const int* __restrict__ perm, const int* __restrict__ sG, const int* __restrict__ dG,
    const float* __restrict__ vG, const __half* __restrict__ X, float* __restrict__ st0,
    float* __restrict__ st1, float* __restrict__ st2, float* __restrict__ degA, int E,
    int dualBlocks) {
    if ((int)blockIdx.x < dualBlocks) {
        unsigned gid = blockIdx.x * blockDim.x + threadIdx.x;
        spmm_dual_body(gid, sA, dA, vA, perm, X, st0, st2, degA, E);
    } else {
        unsigned gid = (unsigned)(blockIdx.x - dualBlocks) * blockDim.x + threadIdx.x;
        spmm2_body(gid, sG, dG, vG, X, st1, nullptr, E);
    }
}

// stage 2 fused: seg 0 = adj->S, seg 1 = neigh->stage3 (+degN), seg 2 = diff->stage4 (+degD)
__global__ __launch_bounds__(256) void spmm_stage2_all(
    const int* __restrict__ sA, const int* __restrict__ dA, const float* __restrict__ vA,
    const int* __restrict__ sN, const int* __restrict__ dN, const float* __restrict__ vN,
    const int* __restrict__ sD, const int* __restrict__ dD, const float* __restrict__ vD,
    const __half* __restrict__ H0, const __half* __restrict__ H1, float* __restrict__ S,
    float* __restrict__ st3, float* __restrict__ st4, float* __restrict__ degN,
    float* __restrict__ degD, int E, int segBlocks) {
    int seg = blockIdx.x / segBlocks;
    int blk = blockIdx.x - seg * segBlocks;
    unsigned gid = (unsigned)blk * blockDim.x + threadIdx.x;
    if (seg == 0) {
        spmm2_body(gid, sA, dA, vA, H0, S, nullptr, E);
    } else if (seg == 1) {
        spmm2_body(gid, sN, dN, vN, H0, st3, degN, E);
    } else {
        spmm2_body(gid, sD, dD, vD, H1, st4, degD, E);
    }
}

// ---------------- relu(stage slots 0..2) -> fp16 MLPINH slots 0..2 ----------------
__global__ void relu_to_half(const float4* __restrict__ stage, __half* __restrict__ hout,
                             int n4) {
    int i = blockIdx.x * blockDim.x + threadIdx.x;
    if (i < n4) {
        float4 v = stage[i];
        __half2 a = __floats2half2_rn(fmaxf(v.x, 0.f), fmaxf(v.y, 0.f));
        __half2 b = __floats2half2_rn(fmaxf(v.z, 0.f), fmaxf(v.w, 0.f));
        uint2 u;
        u.x = *reinterpret_cast<unsigned*>(&a);
        u.y = *reinterpret_cast<unsigned*>(&b);
        *reinterpret_cast<uint2*>(hout + (size_t)i * 4) = u;
    }
}

// ---------------- sigmoid(stage slots 3,4 / max(deg,1)) -> fp16 MLPINH 3,4 -----------
__global__ void sigavg_to_half(const float4* __restrict__ stage, __half* __restrict__ hout,
                               const float* __restrict__ degN, const float* __restrict__ degD) {
    int i = blockIdx.x * blockDim.x + threadIdx.x;
    const int n4 = NN * 16;
    if (i < 2 * n4) {
        int j = i * 4;
        const float* deg = (i < n4) ? degN : degD;
        int node = ((i < n4) ? j : (j - NN * 64)) >> 6;
        float d = deg[node];
        d = (d > 1.f) ? d : 1.f;
        float4 v = stage[i];
        float s0 = 1.f / (1.f + expf(-v.x / d));
        float s1 = 1.f / (1.f + expf(-v.y / d));
        float s2 = 1.f / (1.f + expf(-v.z / d));
        float s3 = 1.f / (1.f + expf(-v.w / d));
        __half2 a = __floats2half2_rn(s0, s1);
        __half2 b = __floats2half2_rn(s2, s3);
        uint2 u;
        u.x = *reinterpret_cast<unsigned*>(&a);
        u.y = *reinterpret_cast<unsigned*>(&b);
        *reinterpret_cast<uint2*>(hout + (size_t)i * 4) = u;
    }
}

// ---------------- discriminator ----------------
__global__ void disc_kernel(const float* __restrict__ Mo, const float* __restrict__ W,
                            const float* __restrict__ bptr, float* __restrict__ ret,
                            float* __restrict__ ret_a) {
    __shared__ float Ws[64][65];
    int tid = threadIdx.x;
    for (int i = tid; i < 4096; i += 128) Ws[i >> 6][i & 63] = W[i];
    __syncthreads();

    int warp = tid >> 5, lane = tid & 31;
    int node = blockIdx.x * 4 + warp;
    if (node >= NN) return;

    const float* z = Mo + (size_t)0 * NN * 64 + (size_t)node * 64;
    const float* zg = Mo + (size_t)1 * NN * 64 + (size_t)node * 64;
    const float* sz = Mo + (size_t)2 * NN * 64 + (size_t)node * 64;
    const float* gv = Mo + (size_t)3 * NN * 64 + (size_t)node * 64;
    const float* gg = Mo + (size_t)4 * NN * 64 + (size_t)node * 64;

    float r0 = 0.f, r1 = 0.f, a0 = 0.f, a1 = 0.f;
#pragma unroll
    for (int h = 0; h < 2; h++) {
        int d = lane + h * 32;
        float tgg = 0.f, tg = 0.f;
#pragma unroll
        for (int e = 0; e < 64; e++) {
            float w = Ws[d][e];
            tgg += w * gg[e];
            tg += w * gv[e];
        }
        r0 += z[d] * tgg;
        r1 += sz[d] * tgg;
        a0 += zg[d] * tg;
        a1 += sz[d] * tg;
    }
#pragma unroll
    for (int o = 16; o; o >>= 1) {
        r0 += __shfl_xor_sync(0xFFFFFFFFu, r0, o);
        r1 += __shfl_xor_sync(0xFFFFFFFFu, r1, o);
        a0 += __shfl_xor_sync(0xFFFFFFFFu, a0, o);
        a1 += __shfl_xor_sync(0xFFFFFFFFu, a1, o);
    }
    if (lane == 0) {
        float b = bptr[0];
        ret[(size_t)node * 2 + 0] = r0 + b;
        ret[(size_t)node * 2 + 1] = r1 + b;
        ret_a[(size_t)node * 2 + 0] = a0 + b;
        ret_a[(size_t)node * 2 + 1] = a1 + b;
    }
}

// =====================================================================================
extern "C" void kernel_launch(void* const* d_in, const int* in_sizes, int n_in, void* d_out,
                              int out_size) {
    (void)in_sizes; (void)n_in; (void)out_size;

    const float* feat      = (const float*)d_in[0];
    const int*   adj_src   = (const int*)d_in[1];
    const int*   adj_dst   = (const int*)d_in[2];
    const float* adj_val   = (const float*)d_in[3];
    const int*   gdc_src   = (const int*)d_in[4];
    const int*   gdc_dst   = (const int*)d_in[5];
    const float* gdc_val   = (const float*)d_in[6];
    const int*   neigh_src = (const int*)d_in[7];
    const int*   neigh_dst = (const int*)d_in[8];
    const float* neigh_val = (const float*)d_in[9];
    const int*   diff_src  = (const int*)d_in[10];
    const int*   diff_dst  = (const int*)d_in[11];
    const float* diff_val  = (const float*)d_in[12];
    const int*   perm      = (const int*)d_in[13];
    const float* W_enc     = (const float*)d_in[14];
    const float* b_enc     = (const float*)d_in[15];
    const float* W_dec     = (const float*)d_in[16];
    const float* b_dec     = (const float*)d_in[17];
    const float* W1        = (const float*)d_in[18];
    const float* b1        = (const float*)d_in[19];
    const float* prelu_a   = (const float*)d_in[20];
    const float* W3        = (const float*)d_in[21];
    const float* b3        = (const float*)d_in[22];
    const float* W_disc    = (const float*)d_in[23];
    const float* b_disc    = (const float*)d_in[24];

    __half *Xhp, *MLPINHp, *W1Tp, *W3Tp;
    float *Zp, *MLPOUTp;
    cudaGetSymbolAddress((void**)&Xhp, g_Xh);
    cudaGetSymbolAddress((void**)&MLPINHp, g_MLPINH);
    cudaGetSymbolAddress((void**)&W1Tp, g_W1T);
    cudaGetSymbolAddress((void**)&W3Tp, g_W3T);
    cudaGetSymbolAddress((void**)&Zp, g_Z);
    cudaGetSymbolAddress((void**)&MLPOUTp, g_MLPOUT);

    float* STAGEp = Zp;                                   // [5*NN*64]
    float* Sp = Zp + (size_t)5 * NN * 64;                 // [NN*64]
    float* DEGp = Sp + (size_t)NN * 64;                   // [3*NN]

    float* out = (float*)d_out;
    float* emb = out;                       // [NN,256]
    float* ret = out + (size_t)NN * 256;    // [NN,2]
    float* ret_a = ret + (size_t)NN * 2;    // [NN,2]

    const int MLP_SMEM = (128 * 72 + 4 * 64 * 72) * 2;  // 55296 B
    static bool init_done = false;
    static cudaStream_t s1 = nullptr, s2 = nullptr;
    static cudaEvent_t evF = nullptr, ev1 = nullptr, ev2 = nullptr, ev3 = nullptr;
    if (!init_done) {
        cudaFuncSetAttribute(mlp16, cudaFuncAttributeMaxDynamicSharedMemorySize, MLP_SMEM);
        cudaStreamCreateWithFlags(&s1, cudaStreamNonBlocking);
        cudaStreamCreateWithFlags(&s2, cudaStreamNonBlocking);
        cudaEventCreateWithFlags(&evF, cudaEventDisableTiming);
        cudaEventCreateWithFlags(&ev1, cudaEventDisableTiming);
        cudaEventCreateWithFlags(&ev2, cudaEventDisableTiming);
        cudaEventCreateWithFlags(&ev3, cudaEventDisableTiming);
        init_done = true;
    }

    const int MROWS = (NN + 127) / 128;                          // 391
    const int dual_blocks = (EE * 4 + 255) / 256;                // 12500
    const int seg_blocks = ((EE / 2) * 4 + 255) / 256;           // 6250

    // ---- fork: transpose_w on s1 (only mlp16 needs it) ----
    cudaEventRecord(evF, 0);
    cudaStreamWaitEvent(s1, evF, 0);
    transpose_w<<<16, 512, 0, s1>>>(W1, W3, W1Tp, W3Tp);
    cudaEventRecord(ev1, s1);

    // ---- main chain ----
    cudaMemsetAsync(Zp, 0, ((size_t)5 * NN * 64 + (size_t)NN * 64 + 3 * NN) * sizeof(float));

    // Xh = half(feat @ W_enc + b_enc)  [NN,64]  (tf32)
    mma_gemm<2><<<dim3(1, MROWS), 256>>>(feat, W_enc, b_enc, nullptr, nullptr, Xhp, NN, 256, 64);

    // stage 1 (fused): adj dual -> stage0/stage2 (+degA); gdc -> stage1
    spmm_stage1_all<<<dual_blocks + seg_blocks, 256>>>(adj_src, adj_dst, adj_val, perm, gdc_src,
                                                       gdc_dst, gdc_val, Xhp,
                                                       STAGEp + (size_t)0 * NN * 64,
                                                       STAGEp + (size_t)1 * NN * 64,
                                                       STAGEp + (size_t)2 * NN * 64, DEGp, EE,
                                                       dual_blocks);

    // relu stage 0..2 -> fp16 MLPINH slots 0..2
    {
        int n4 = 3 * NN * 16;
        relu_to_half<<<(n4 + 255) / 256, 256>>>((const float4*)STAGEp, MLPINHp, n4);
    }

    // stage 2 (fused): adj->S, neigh->stage3 (+degN), diff->stage4 (+degD)
    spmm_stage2_all<<<3 * seg_blocks, 256>>>(adj_src, adj_dst, adj_val, neigh_src, neigh_dst,
                                             neigh_val, diff_src, diff_dst, diff_val, MLPINHp,
                                             MLPINHp + (size_t)NN * 64, Sp,
                                             STAGEp + (size_t)3 * NN * 64,
                                             STAGEp + (size_t)4 * NN * 64, DEGp + NN,
                                             DEGp + 2 * NN, EE, seg_blocks);

    // ---- fork: emb GEMM on s2 (needs S + degA; independent of sigavg/mlp/disc) ----
    cudaEventRecord(ev2, 0);
    cudaStreamWaitEvent(s2, ev2, 0);
    mma_gemm<1><<<dim3(4, MROWS), 256, 0, s2>>>(Sp, W_dec, b_dec, DEGp, emb, nullptr, NN, 64,
                                                256);
    cudaEventRecord(ev3, s2);

    // ---- main chain continues: sigmoid averages -> fp16 MLPINH slots 3,4 ----
    {
        int n2 = 2 * NN * 16;
        sigavg_to_half<<<(n2 + 255) / 256, 256>>>((const float4*)(STAGEp + (size_t)3 * NN * 64),
                                                  MLPINHp + (size_t)3 * NN * 64, DEGp + NN,
                                                  DEGp + 2 * NN);
    }

    // join transpose_w, then fused MLP
    cudaStreamWaitEvent(0, ev1, 0);
    {
        int M = 5 * NN;
        mlp16<<<(M + 127) / 128, 256, MLP_SMEM>>>(MLPINHp, W1Tp, b1, prelu_a, W3Tp, b3, MLPOUTp,
                                                  M);
    }

    // discriminator heads
    disc_kernel<<<(NN + 3) / 4, 128>>>(MLPOUTp, W_disc, b_disc, ret, ret_a);

    // join emb branch before returning (capture must end with a single joined chain)
    cudaStreamWaitEvent(0, ev3, 0);
}